// round 1
// baseline (speedup 1.0000x reference)
#include <cuda_runtime.h>
#include <math.h>

// Problem dims (fixed)
#define BB   256      // batch
#define NI   16384    // n_items
#define DM   512      // d_model
#define DFF  2048     // ff dim
#define NNZV (NI*33)  // 540672
#define NS1  32       // K-splits for GEMM1 (16384/32 = 512 per split)

// ---------------- scratch (device globals; no allocation allowed) ----------
__device__ float g_x0T[NI*BB];        // x0 transposed [N,B]
__device__ float g_Lx [NI*BB];        // Lx [N,B]
__device__ float g_part[NS1*BB*DM];   // split-K partials (4.19M floats, reused)
__device__ float g_TE [BB*DM];
__device__ float g_h  [BB*DM];
__device__ float g_h1 [BB*DM];
__device__ float g_v  [BB*DM];
__device__ float g_at [BB*DM];
__device__ float g_f1 [BB*DFF];
__device__ float g_f2 [BB*DM];
__device__ float g_h2 [BB*DM];

// ---------------- utility kernels ----------------
__global__ void zero_kernel(float* __restrict__ p, int n) {
    int i = blockIdx.x * blockDim.x + threadIdx.x;
    int stride = gridDim.x * blockDim.x;
    for (; i < n; i += stride) p[i] = 0.f;
}

__global__ void zero1_kernel(float* p) { *p = 0.f; }

// x0 [B,N] -> x0T [N,B]
__global__ void transpose_kernel(const float* __restrict__ x, float* __restrict__ xt) {
    __shared__ float s[32][33];
    int n0 = blockIdx.x * 32, b0 = blockIdx.y * 32;
    int tx = threadIdx.x, ty = threadIdx.y;
#pragma unroll
    for (int i = 0; i < 32; i += 8)
        s[ty + i][tx] = x[(size_t)(b0 + ty + i) * NI + n0 + tx];
    __syncthreads();
#pragma unroll
    for (int i = 0; i < 32; i += 8)
        xt[(size_t)(n0 + ty + i) * BB + b0 + tx] = s[tx][ty + i];
}

// Sparse scatter: Lx[row, :] += val * x0T[col, :]   (one warp per nnz)
__global__ void scatter_kernel(const float* __restrict__ xt,
                               const int* __restrict__ rows,
                               const int* __restrict__ cols,
                               const float* __restrict__ vals,
                               float* __restrict__ Lx) {
    int warp = (blockIdx.x * blockDim.x + threadIdx.x) >> 5;
    if (warp >= NNZV) return;
    int lane = threadIdx.x & 31;
    int r = rows[warp];
    int c = cols[warp];
    float v = vals[warp];
    const float4* src = (const float4*)(xt + (size_t)c * BB);
    float* dst = Lx + (size_t)r * BB;
#pragma unroll
    for (int j = 0; j < 2; j++) {
        int idx = j * 32 + lane;       // float4 index, covers 256 floats
        float4 xv = src[idx];
        atomicAdd(dst + idx * 4 + 0, v * xv.x);
        atomicAdd(dst + idx * 4 + 1, v * xv.y);
        atomicAdd(dst + idx * 4 + 2, v * xv.z);
        atomicAdd(dst + idx * 4 + 3, v * xv.w);
    }
}

// time embedding: te[b,:] = silu(t[b]*W_t1 + b_t1) @ W_t2.T + b_t2
__global__ void te_kernel(const float* __restrict__ t,
                          const float* __restrict__ Wt1, const float* __restrict__ bt1,
                          const float* __restrict__ Wt2, const float* __restrict__ bt2,
                          float* __restrict__ te) {
    __shared__ float u[32];
    int b = blockIdx.x, tid = threadIdx.x;   // 64 threads
    if (tid < 32) {
        float z = t[b] * Wt1[tid] + bt1[tid];
        u[tid] = z / (1.f + expf(-z));       // silu
    }
    __syncthreads();
    for (int d = tid; d < DM; d += 64) {
        float s = bt2[d];
        const float* w = Wt2 + d * 32;
#pragma unroll
        for (int j = 0; j < 32; j++) s += u[j] * w[j];
        te[b * DM + d] = s;
    }
}

// ---------------- GEMM1: h_partial = (x0T - tc[b]*Lx) ^T @ W_in^T ----------
// A stored [K=N, M=B] (batch contiguous). W_in [D, N] row-major (K-major).
// C tile 64(b) x 64(d), BK=16, split-K over blockIdx.z (512 K each).
__global__ void gemm1_kernel(const float* __restrict__ x0T,
                             const float* __restrict__ Lx,
                             const float* __restrict__ t,
                             const float* __restrict__ Win,
                             float* __restrict__ part) {
    __shared__ float As[16][68];
    __shared__ float Ws[16][68];
    __shared__ float tcs[64];
    int b0 = blockIdx.x * 64;
    int d0 = blockIdx.y * 64;
    int s  = blockIdx.z;
    int k0 = s * 512;
    int tid = threadIdx.x;
    if (tid < 64) tcs[tid] = 0.5f * t[b0 + tid];   // t_cont = t * T_MAX
    __syncthreads();

    int ty = tid >> 4, tx = tid & 15;
    int la_k = tid >> 4;            // 0..15
    int la_b = (tid & 15) << 2;     // 0..60
    int lw_n = tid >> 2;            // 0..63
    int lw_k = (tid & 3) << 2;      // 0,4,8,12

    float acc[4][4] = {};
    for (int kt = 0; kt < 512; kt += 16) {
        int k = k0 + kt;
        float4 xv = *(const float4*)(x0T + (size_t)(k + la_k) * BB + b0 + la_b);
        float4 lv = *(const float4*)(Lx  + (size_t)(k + la_k) * BB + b0 + la_b);
        As[la_k][la_b + 0] = xv.x - tcs[la_b + 0] * lv.x;
        As[la_k][la_b + 1] = xv.y - tcs[la_b + 1] * lv.y;
        As[la_k][la_b + 2] = xv.z - tcs[la_b + 2] * lv.z;
        As[la_k][la_b + 3] = xv.w - tcs[la_b + 3] * lv.w;
        float4 wv = *(const float4*)(Win + (size_t)(d0 + lw_n) * NI + k + lw_k);
        Ws[lw_k + 0][lw_n] = wv.x;
        Ws[lw_k + 1][lw_n] = wv.y;
        Ws[lw_k + 2][lw_n] = wv.z;
        Ws[lw_k + 3][lw_n] = wv.w;
        __syncthreads();
#pragma unroll
        for (int kk = 0; kk < 16; kk++) {
            float4 a = *(const float4*)&As[kk][ty * 4];
            float4 w = *(const float4*)&Ws[kk][tx * 4];
            float av[4] = {a.x, a.y, a.z, a.w};
            float wv2[4] = {w.x, w.y, w.z, w.w};
#pragma unroll
            for (int i = 0; i < 4; i++)
#pragma unroll
                for (int j = 0; j < 4; j++) acc[i][j] += av[i] * wv2[j];
        }
        __syncthreads();
    }
    float* cp = part + (size_t)s * (BB * DM);
#pragma unroll
    for (int i = 0; i < 4; i++)
#pragma unroll
        for (int j = 0; j < 4; j++)
            cp[(size_t)(b0 + ty * 4 + i) * DM + d0 + tx * 4 + j] = acc[i][j];
}

// ---------------- generic NT GEMM partial: C = A[M,K] @ W[N2,K]^T ----------
__global__ void gemmNT_kernel(const float* __restrict__ A,
                              const float* __restrict__ W,
                              float* __restrict__ part,
                              int N2, int K, int KS) {
    __shared__ float As[16][68];
    __shared__ float Ws[16][68];
    int m0 = blockIdx.x * 64;
    int n0 = blockIdx.y * 64;
    int s  = blockIdx.z;
    int k0 = s * KS;
    int tid = threadIdx.x;
    int ty = tid >> 4, tx = tid & 15;
    int lm = tid >> 2;              // 0..63
    int lk = (tid & 3) << 2;        // 0,4,8,12

    float acc[4][4] = {};
    for (int kt = 0; kt < KS; kt += 16) {
        float4 av = *(const float4*)(A + (size_t)(m0 + lm) * K + k0 + kt + lk);
        As[lk + 0][lm] = av.x;
        As[lk + 1][lm] = av.y;
        As[lk + 2][lm] = av.z;
        As[lk + 3][lm] = av.w;
        float4 wv = *(const float4*)(W + (size_t)(n0 + lm) * K + k0 + kt + lk);
        Ws[lk + 0][lm] = wv.x;
        Ws[lk + 1][lm] = wv.y;
        Ws[lk + 2][lm] = wv.z;
        Ws[lk + 3][lm] = wv.w;
        __syncthreads();
#pragma unroll
        for (int kk = 0; kk < 16; kk++) {
            float4 a = *(const float4*)&As[kk][ty * 4];
            float4 w = *(const float4*)&Ws[kk][tx * 4];
            float avr[4] = {a.x, a.y, a.z, a.w};
            float wvr[4] = {w.x, w.y, w.z, w.w};
#pragma unroll
            for (int i = 0; i < 4; i++)
#pragma unroll
                for (int j = 0; j < 4; j++) acc[i][j] += avr[i] * wvr[j];
        }
        __syncthreads();
    }
    float* cp = part + (size_t)s * ((size_t)BB * N2);
#pragma unroll
    for (int i = 0; i < 4; i++)
#pragma unroll
        for (int j = 0; j < 4; j++)
            cp[(size_t)(m0 + ty * 4 + i) * N2 + n0 + tx * 4 + j] = acc[i][j];
}

// reduce split-K partials + bias (+extra) (+gelu)
__global__ void reduce_kernel(const float* __restrict__ part, int ns, int total,
                              int N2, const float* __restrict__ bias,
                              const float* __restrict__ extra, int act,
                              float* __restrict__ out) {
    int i = blockIdx.x * blockDim.x + threadIdx.x;
    if (i >= total) return;
    float s = 0.f;
    for (int j = 0; j < ns; j++) s += part[(size_t)j * total + i];
    s += bias[i % N2];
    if (extra) s += extra[i];
    if (act == 1) s = 0.5f * s * (1.f + erff(s * 0.70710678118654752f));  // exact gelu
    out[i] = s;
}

// layernorm over D of (x+res)
__global__ void ln_kernel(const float* __restrict__ x, const float* __restrict__ res,
                          const float* __restrict__ g, const float* __restrict__ be,
                          float* __restrict__ out) {
    __shared__ float sbuf[8];
    int b = blockIdx.x, tid = threadIdx.x;     // 256 threads
    const float* xr = x + (size_t)b * DM;
    const float* rr = res + (size_t)b * DM;
    float y0 = xr[tid] + rr[tid];
    float y1 = xr[tid + 256] + rr[tid + 256];
    float s = y0 + y1;
#pragma unroll
    for (int o = 16; o > 0; o >>= 1) s += __shfl_xor_sync(0xffffffffu, s, o);
    if ((tid & 31) == 0) sbuf[tid >> 5] = s;
    __syncthreads();
    if (tid == 0) {
        float tot = 0.f;
        for (int i = 0; i < 8; i++) tot += sbuf[i];
        sbuf[0] = tot;
    }
    __syncthreads();
    float mu = sbuf[0] * (1.f / DM);
    __syncthreads();
    float d0 = y0 - mu, d1 = y1 - mu;
    float q = d0 * d0 + d1 * d1;
#pragma unroll
    for (int o = 16; o > 0; o >>= 1) q += __shfl_xor_sync(0xffffffffu, q, o);
    if ((tid & 31) == 0) sbuf[tid >> 5] = q;
    __syncthreads();
    if (tid == 0) {
        float tot = 0.f;
        for (int i = 0; i < 8; i++) tot += sbuf[i];
        sbuf[0] = tot;
    }
    __syncthreads();
    float inv = rsqrtf(sbuf[0] * (1.f / DM) + 1e-5f);
    out[(size_t)b * DM + tid]       = d0 * inv * g[tid] + be[tid];
    out[(size_t)b * DM + tid + 256] = d1 * inv * g[tid + 256] + be[tid + 256];
}

// final GEMM (h2 @ W_out^T + b_out) fused with MSE-vs-x0 reduction
__global__ void gemm_out_loss_kernel(const float* __restrict__ h2,
                                     const float* __restrict__ Wout,
                                     const float* __restrict__ bout,
                                     const float* __restrict__ x0,
                                     float* __restrict__ out) {
    __shared__ float As[16][68];
    __shared__ float Ws[16][68];
    __shared__ float sbuf[8];
    int m0 = blockIdx.x * 64;      // batch tile
    int n0 = blockIdx.y * 64;      // item tile
    int tid = threadIdx.x;
    int ty = tid >> 4, tx = tid & 15;
    int lm = tid >> 2;
    int lk = (tid & 3) << 2;

    float acc[4][4] = {};
    for (int kt = 0; kt < DM; kt += 16) {
        float4 av = *(const float4*)(h2 + (size_t)(m0 + lm) * DM + kt + lk);
        As[lk + 0][lm] = av.x;
        As[lk + 1][lm] = av.y;
        As[lk + 2][lm] = av.z;
        As[lk + 3][lm] = av.w;
        float4 wv = *(const float4*)(Wout + (size_t)(n0 + lm) * DM + kt + lk);
        Ws[lk + 0][lm] = wv.x;
        Ws[lk + 1][lm] = wv.y;
        Ws[lk + 2][lm] = wv.z;
        Ws[lk + 3][lm] = wv.w;
        __syncthreads();
#pragma unroll
        for (int kk = 0; kk < 16; kk++) {
            float4 a = *(const float4*)&As[kk][ty * 4];
            float4 w = *(const float4*)&Ws[kk][tx * 4];
            float avr[4] = {a.x, a.y, a.z, a.w};
            float wvr[4] = {w.x, w.y, w.z, w.w};
#pragma unroll
            for (int i = 0; i < 4; i++)
#pragma unroll
                for (int j = 0; j < 4; j++) acc[i][j] += avr[i] * wvr[j];
        }
        __syncthreads();
    }
    float local = 0.f;
#pragma unroll
    for (int i = 0; i < 4; i++) {
        int bi = m0 + ty * 4 + i;
#pragma unroll
        for (int j = 0; j < 4; j++) {
            int nj = n0 + tx * 4 + j;
            float c = acc[i][j] + bout[nj];
            float d = c - x0[(size_t)bi * NI + nj];
            local += d * d;
        }
    }
#pragma unroll
    for (int o = 16; o > 0; o >>= 1) local += __shfl_xor_sync(0xffffffffu, local, o);
    if ((tid & 31) == 0) sbuf[tid >> 5] = local;
    __syncthreads();
    if (tid == 0) {
        float tot = 0.f;
        for (int i = 0; i < 8; i++) tot += sbuf[i];
        atomicAdd(out, tot * (1.f / ((float)BB * (float)NI)));
    }
}

// ---------------- launch ----------------
extern "C" void kernel_launch(void* const* d_in, const int* in_sizes, int n_in,
                              void* d_out, int out_size) {
    const float* x0    = (const float*)d_in[0];
    const float* t     = (const float*)d_in[1];
    const float* Lvals = (const float*)d_in[2];
    const float* W_in  = (const float*)d_in[3];
    const float* b_in  = (const float*)d_in[4];
    const float* W_out = (const float*)d_in[5];
    const float* b_out = (const float*)d_in[6];
    const float* W_qkv = (const float*)d_in[7];
    const float* b_qkv = (const float*)d_in[8];
    const float* W_o   = (const float*)d_in[9];
    const float* b_o   = (const float*)d_in[10];
    const float* g1    = (const float*)d_in[11];
    const float* be1   = (const float*)d_in[12];
    const float* g2    = (const float*)d_in[13];
    const float* be2   = (const float*)d_in[14];
    const float* W_f1  = (const float*)d_in[15];
    const float* b_f1  = (const float*)d_in[16];
    const float* W_f2  = (const float*)d_in[17];
    const float* b_f2  = (const float*)d_in[18];
    const float* W_t1  = (const float*)d_in[19];
    const float* b_t1  = (const float*)d_in[20];
    const float* W_t2  = (const float*)d_in[21];
    const float* b_t2  = (const float*)d_in[22];
    const int*   Lrows = (const int*)d_in[23];
    const int*   Lcols = (const int*)d_in[24];
    float* out = (float*)d_out;

    float *p_x0T, *p_Lx, *p_part, *p_TE, *p_h, *p_h1, *p_v, *p_at, *p_f1, *p_f2, *p_h2;
    cudaGetSymbolAddress((void**)&p_x0T, g_x0T);
    cudaGetSymbolAddress((void**)&p_Lx,  g_Lx);
    cudaGetSymbolAddress((void**)&p_part,g_part);
    cudaGetSymbolAddress((void**)&p_TE,  g_TE);
    cudaGetSymbolAddress((void**)&p_h,   g_h);
    cudaGetSymbolAddress((void**)&p_h1,  g_h1);
    cudaGetSymbolAddress((void**)&p_v,   g_v);
    cudaGetSymbolAddress((void**)&p_at,  g_at);
    cudaGetSymbolAddress((void**)&p_f1,  g_f1);
    cudaGetSymbolAddress((void**)&p_f2,  g_f2);
    cudaGetSymbolAddress((void**)&p_h2,  g_h2);

    zero_kernel<<<4096, 256>>>(p_Lx, NI * BB);
    zero1_kernel<<<1, 1>>>(out);
    transpose_kernel<<<dim3(NI / 32, BB / 32), dim3(32, 8)>>>(x0, p_x0T);
    scatter_kernel<<<NNZV / 8, 256>>>(p_x0T, Lrows, Lcols, Lvals, p_Lx);
    te_kernel<<<BB, 64>>>(t, W_t1, b_t1, W_t2, b_t2, p_TE);

    // h = x_t @ W_in^T + b_in + te
    gemm1_kernel<<<dim3(4, 8, NS1), 256>>>(p_x0T, p_Lx, t, W_in, p_part);
    reduce_kernel<<<(BB * DM) / 256, 256>>>(p_part, NS1, BB * DM, DM, b_in, p_TE, 0, p_h);

    // v = h @ Wv^T + bv   (only V third of qkv is used)
    gemmNT_kernel<<<dim3(4, 8, 2), 256>>>(p_h, W_qkv + 2 * DM * DM, p_part, DM, DM, 256);
    reduce_kernel<<<(BB * DM) / 256, 256>>>(p_part, 2, BB * DM, DM, b_qkv + 2 * DM, nullptr, 0, p_v);

    // attn = v @ W_o^T + b_o
    gemmNT_kernel<<<dim3(4, 8, 2), 256>>>(p_v, W_o, p_part, DM, DM, 256);
    reduce_kernel<<<(BB * DM) / 256, 256>>>(p_part, 2, BB * DM, DM, b_o, nullptr, 0, p_at);

    // h1 = LN(h + attn)
    ln_kernel<<<BB, 256>>>(p_h, p_at, g1, be1, p_h1);

    // f1 = gelu(h1 @ W_f1^T + b_f1)
    gemmNT_kernel<<<dim3(4, DFF / 64, 2), 256>>>(p_h1, W_f1, p_part, DFF, DM, 256);
    reduce_kernel<<<(BB * DFF) / 256, 256>>>(p_part, 2, BB * DFF, DFF, b_f1, nullptr, 1, p_f1);

    // f2 = f1 @ W_f2^T + b_f2
    gemmNT_kernel<<<dim3(4, 8, 8), 256>>>(p_f1, W_f2, p_part, DM, DFF, 256);
    reduce_kernel<<<(BB * DM) / 256, 256>>>(p_part, 8, BB * DM, DM, b_f2, nullptr, 0, p_f2);

    // h2 = LN(h1 + f2)
    ln_kernel<<<BB, 256>>>(p_h1, p_f2, g2, be2, p_h2);

    // loss = mean((h2 @ W_out^T + b_out - x0)^2)
    gemm_out_loss_kernel<<<dim3(4, NI / 64), 256>>>(p_h2, W_out, b_out, x0, out);
}

// round 2
// speedup vs baseline: 1.4565x; 1.4565x over previous
#include <cuda_runtime.h>
#include <math.h>

// Problem dims (fixed)
#define BB   256      // batch
#define NI   16384    // n_items
#define DM   512      // d_model
#define DFF  2048     // ff dim
#define NNZV (NI*33)  // 540672
#define NS1  32       // K-splits for GEMM1 (16384/32 = 512 per split)

// ---------------- scratch (device globals; no allocation allowed) ----------
__device__ float g_x0T[NI*BB];        // x0 transposed [N,B]
__device__ float g_xt [NI*BB];        // x_t = x0 - tc*Lx, stored [N,B]
__device__ float g_part[NS1*BB*DM];   // split-K partials (reused)
__device__ float g_TE [BB*DM];
__device__ float g_h  [BB*DM];
__device__ float g_h1 [BB*DM];
__device__ float g_v  [BB*DM];
__device__ float g_at [BB*DM];
__device__ float g_f1 [BB*DFF];
__device__ float g_f2 [BB*DM];
__device__ float g_h2 [BB*DM];
// CSR build scratch
__device__ int   g_cnt[NI];
__device__ int   g_off[NI + 1];
__device__ int   g_wp [NI];
__device__ int   g_ccol[NNZV];
__device__ float g_cval[NNZV];

// ---------------- utility kernels ----------------
__global__ void zeroi_kernel(int* __restrict__ p, int n) {
    int i = blockIdx.x * blockDim.x + threadIdx.x;
    if (i < n) p[i] = 0;
}

__global__ void zero1_kernel(float* p) { *p = 0.f; }

// x0 [B,N] -> x0T [N,B]
__global__ void transpose_kernel(const float* __restrict__ x, float* __restrict__ xt) {
    __shared__ float s[32][33];
    int n0 = blockIdx.x * 32, b0 = blockIdx.y * 32;
    int tx = threadIdx.x, ty = threadIdx.y;
#pragma unroll
    for (int i = 0; i < 32; i += 8)
        s[ty + i][tx] = x[(size_t)(b0 + ty + i) * NI + n0 + tx];
    __syncthreads();
#pragma unroll
    for (int i = 0; i < 32; i += 8)
        xt[(size_t)(n0 + ty + i) * BB + b0 + tx] = s[tx][ty + i];
}

// ---------------- CSR build ----------------
__global__ void hist_kernel(const int* __restrict__ rows, int* __restrict__ cnt) {
    int i = blockIdx.x * blockDim.x + threadIdx.x;
    if (i < NNZV) atomicAdd(&cnt[rows[i]], 1);
}

// exclusive prefix sum over NI=16384 bins; 1 block, 512 threads, 32 bins each
__global__ void scan_kernel(const int* __restrict__ cnt, int* __restrict__ off) {
    __shared__ int ws[512];
    int tid = threadIdx.x;
    int base = tid * 32;
    int local[32];
    int s = 0;
#pragma unroll
    for (int i = 0; i < 32; i++) { local[i] = s; s += cnt[base + i]; }
    ws[tid] = s;
    __syncthreads();
    for (int ofs = 1; ofs < 512; ofs <<= 1) {
        int v = ws[tid];
        int add = (tid >= ofs) ? ws[tid - ofs] : 0;
        __syncthreads();
        ws[tid] = v + add;
        __syncthreads();
    }
    int excl = (tid > 0) ? ws[tid - 1] : 0;
#pragma unroll
    for (int i = 0; i < 32; i++) off[base + i] = excl + local[i];
    if (tid == 511) off[NI] = ws[511];
}

__global__ void copyi_kernel(const int* __restrict__ src, int* __restrict__ dst, int n) {
    int i = blockIdx.x * blockDim.x + threadIdx.x;
    if (i < n) dst[i] = src[i];
}

__global__ void fill_kernel(const int* __restrict__ rows, const int* __restrict__ cols,
                            const float* __restrict__ vals,
                            int* __restrict__ wp,
                            int* __restrict__ ccol, float* __restrict__ cval) {
    int i = blockIdx.x * blockDim.x + threadIdx.x;
    if (i >= NNZV) return;
    int r = rows[i];
    int p = atomicAdd(&wp[r], 1);
    ccol[p] = cols[i];
    cval[p] = vals[i];
}

// ---------------- gather: xt[r,:] = x0T[r,:] - tc[:] * sum_j val*x0T[col_j,:] ----
__global__ void gather_kernel(const float* __restrict__ x0T,
                              const int* __restrict__ off,
                              const int* __restrict__ ccol,
                              const float* __restrict__ cval,
                              const float* __restrict__ t,
                              float* __restrict__ xt) {
    int r = blockIdx.x;
    int tid = threadIdx.x;            // = batch index b (256 threads)
    int s = off[r], e = off[r + 1];
    float acc = 0.f;
    int j = s;
    for (; j + 1 < e; j += 2) {
        int   c0 = __ldg(&ccol[j]);
        float v0 = __ldg(&cval[j]);
        int   c1 = __ldg(&ccol[j + 1]);
        float v1 = __ldg(&cval[j + 1]);
        acc += v0 * __ldg(&x0T[(size_t)c0 * BB + tid]);
        acc += v1 * __ldg(&x0T[(size_t)c1 * BB + tid]);
    }
    if (j < e) {
        int   c0 = __ldg(&ccol[j]);
        float v0 = __ldg(&cval[j]);
        acc += v0 * __ldg(&x0T[(size_t)c0 * BB + tid]);
    }
    float tc = 0.5f * t[tid];         // t_cont = t * T_MAX
    xt[(size_t)r * BB + tid] = x0T[(size_t)r * BB + tid] - tc * acc;
}

// time embedding: te[b,:] = silu(t[b]*W_t1 + b_t1) @ W_t2.T + b_t2
__global__ void te_kernel(const float* __restrict__ t,
                          const float* __restrict__ Wt1, const float* __restrict__ bt1,
                          const float* __restrict__ Wt2, const float* __restrict__ bt2,
                          float* __restrict__ te) {
    __shared__ float u[32];
    int b = blockIdx.x, tid = threadIdx.x;   // 64 threads
    if (tid < 32) {
        float z = t[b] * 0.5f / 0.5f;        // t_norm = t (tc/T_MAX)
        z = t[b] * Wt1[tid] + bt1[tid];
        u[tid] = z / (1.f + expf(-z));       // silu
    }
    __syncthreads();
    for (int d = tid; d < DM; d += 64) {
        float s = bt2[d];
        const float* w = Wt2 + d * 32;
#pragma unroll
        for (int j = 0; j < 32; j++) s += u[j] * w[j];
        te[b * DM + d] = s;
    }
}

// ---------------- GEMM1: h_partial = xt^T @ W_in^T ----------
// xt stored [K=N, M=B] (batch contiguous). W_in [D, N] row-major (K-major).
// C tile 64(b) x 64(d), BK=16, split-K over blockIdx.z (512 K each).
__global__ void gemm1_kernel(const float* __restrict__ xt,
                             const float* __restrict__ Win,
                             float* __restrict__ part) {
    __shared__ float As[16][68];
    __shared__ float Ws[16][68];
    int b0 = blockIdx.x * 64;
    int d0 = blockIdx.y * 64;
    int s  = blockIdx.z;
    int k0 = s * 512;
    int tid = threadIdx.x;

    int ty = tid >> 4, tx = tid & 15;
    int la_k = tid >> 4;            // 0..15
    int la_b = (tid & 15) << 2;     // 0..60
    int lw_n = tid >> 2;            // 0..63
    int lw_k = (tid & 3) << 2;      // 0,4,8,12

    float acc[4][4] = {};
    for (int kt = 0; kt < 512; kt += 16) {
        int k = k0 + kt;
        float4 xv = *(const float4*)(xt + (size_t)(k + la_k) * BB + b0 + la_b);
        As[la_k][la_b + 0] = xv.x;
        As[la_k][la_b + 1] = xv.y;
        As[la_k][la_b + 2] = xv.z;
        As[la_k][la_b + 3] = xv.w;
        float4 wv = *(const float4*)(Win + (size_t)(d0 + lw_n) * NI + k + lw_k);
        Ws[lw_k + 0][lw_n] = wv.x;
        Ws[lw_k + 1][lw_n] = wv.y;
        Ws[lw_k + 2][lw_n] = wv.z;
        Ws[lw_k + 3][lw_n] = wv.w;
        __syncthreads();
#pragma unroll
        for (int kk = 0; kk < 16; kk++) {
            float4 a = *(const float4*)&As[kk][ty * 4];
            float4 w = *(const float4*)&Ws[kk][tx * 4];
            float av[4] = {a.x, a.y, a.z, a.w};
            float wv2[4] = {w.x, w.y, w.z, w.w};
#pragma unroll
            for (int i = 0; i < 4; i++)
#pragma unroll
                for (int j = 0; j < 4; j++) acc[i][j] += av[i] * wv2[j];
        }
        __syncthreads();
    }
    float* cp = part + (size_t)s * (BB * DM);
#pragma unroll
    for (int i = 0; i < 4; i++)
#pragma unroll
        for (int j = 0; j < 4; j++)
            cp[(size_t)(b0 + ty * 4 + i) * DM + d0 + tx * 4 + j] = acc[i][j];
}

// ---------------- generic NT GEMM partial: C = A[M,K] @ W[N2,K]^T ----------
__global__ void gemmNT_kernel(const float* __restrict__ A,
                              const float* __restrict__ W,
                              float* __restrict__ part,
                              int N2, int K, int KS) {
    __shared__ float As[16][68];
    __shared__ float Ws[16][68];
    int m0 = blockIdx.x * 64;
    int n0 = blockIdx.y * 64;
    int s  = blockIdx.z;
    int k0 = s * KS;
    int tid = threadIdx.x;
    int ty = tid >> 4, tx = tid & 15;
    int lm = tid >> 2;              // 0..63
    int lk = (tid & 3) << 2;        // 0,4,8,12

    float acc[4][4] = {};
    for (int kt = 0; kt < KS; kt += 16) {
        float4 av = *(const float4*)(A + (size_t)(m0 + lm) * K + k0 + kt + lk);
        As[lk + 0][lm] = av.x;
        As[lk + 1][lm] = av.y;
        As[lk + 2][lm] = av.z;
        As[lk + 3][lm] = av.w;
        float4 wv = *(const float4*)(W + (size_t)(n0 + lm) * K + k0 + kt + lk);
        Ws[lk + 0][lm] = wv.x;
        Ws[lk + 1][lm] = wv.y;
        Ws[lk + 2][lm] = wv.z;
        Ws[lk + 3][lm] = wv.w;
        __syncthreads();
#pragma unroll
        for (int kk = 0; kk < 16; kk++) {
            float4 a = *(const float4*)&As[kk][ty * 4];
            float4 w = *(const float4*)&Ws[kk][tx * 4];
            float avr[4] = {a.x, a.y, a.z, a.w};
            float wvr[4] = {w.x, w.y, w.z, w.w};
#pragma unroll
            for (int i = 0; i < 4; i++)
#pragma unroll
                for (int j = 0; j < 4; j++) acc[i][j] += avr[i] * wvr[j];
        }
        __syncthreads();
    }
    float* cp = part + (size_t)s * ((size_t)BB * N2);
#pragma unroll
    for (int i = 0; i < 4; i++)
#pragma unroll
        for (int j = 0; j < 4; j++)
            cp[(size_t)(m0 + ty * 4 + i) * N2 + n0 + tx * 4 + j] = acc[i][j];
}

// reduce split-K partials + bias (+extra) (+gelu)
__global__ void reduce_kernel(const float* __restrict__ part, int ns, int total,
                              int N2, const float* __restrict__ bias,
                              const float* __restrict__ extra, int act,
                              float* __restrict__ out) {
    int i = blockIdx.x * blockDim.x + threadIdx.x;
    if (i >= total) return;
    float s = 0.f;
    for (int j = 0; j < ns; j++) s += part[(size_t)j * total + i];
    s += bias[i % N2];
    if (extra) s += extra[i];
    if (act == 1) s = 0.5f * s * (1.f + erff(s * 0.70710678118654752f));  // exact gelu
    out[i] = s;
}

// layernorm over D of (x+res)
__global__ void ln_kernel(const float* __restrict__ x, const float* __restrict__ res,
                          const float* __restrict__ g, const float* __restrict__ be,
                          float* __restrict__ out) {
    __shared__ float sbuf[8];
    int b = blockIdx.x, tid = threadIdx.x;     // 256 threads
    const float* xr = x + (size_t)b * DM;
    const float* rr = res + (size_t)b * DM;
    float y0 = xr[tid] + rr[tid];
    float y1 = xr[tid + 256] + rr[tid + 256];
    float s = y0 + y1;
#pragma unroll
    for (int o = 16; o > 0; o >>= 1) s += __shfl_xor_sync(0xffffffffu, s, o);
    if ((tid & 31) == 0) sbuf[tid >> 5] = s;
    __syncthreads();
    if (tid == 0) {
        float tot = 0.f;
        for (int i = 0; i < 8; i++) tot += sbuf[i];
        sbuf[0] = tot;
    }
    __syncthreads();
    float mu = sbuf[0] * (1.f / DM);
    __syncthreads();
    float d0 = y0 - mu, d1 = y1 - mu;
    float q = d0 * d0 + d1 * d1;
#pragma unroll
    for (int o = 16; o > 0; o >>= 1) q += __shfl_xor_sync(0xffffffffu, q, o);
    if ((tid & 31) == 0) sbuf[tid >> 5] = q;
    __syncthreads();
    if (tid == 0) {
        float tot = 0.f;
        for (int i = 0; i < 8; i++) tot += sbuf[i];
        sbuf[0] = tot;
    }
    __syncthreads();
    float inv = rsqrtf(sbuf[0] * (1.f / DM) + 1e-5f);
    out[(size_t)b * DM + tid]       = d0 * inv * g[tid] + be[tid];
    out[(size_t)b * DM + tid + 256] = d1 * inv * g[tid + 256] + be[tid + 256];
}

// final GEMM (h2 @ W_out^T + b_out) fused with MSE-vs-x0 reduction
__global__ void gemm_out_loss_kernel(const float* __restrict__ h2,
                                     const float* __restrict__ Wout,
                                     const float* __restrict__ bout,
                                     const float* __restrict__ x0,
                                     float* __restrict__ out) {
    __shared__ float As[16][68];
    __shared__ float Ws[16][68];
    __shared__ float sbuf[8];
    int m0 = blockIdx.x * 64;      // batch tile
    int n0 = blockIdx.y * 64;      // item tile
    int tid = threadIdx.x;
    int ty = tid >> 4, tx = tid & 15;
    int lm = tid >> 2;
    int lk = (tid & 3) << 2;

    float acc[4][4] = {};
    for (int kt = 0; kt < DM; kt += 16) {
        float4 av = *(const float4*)(h2 + (size_t)(m0 + lm) * DM + kt + lk);
        As[lk + 0][lm] = av.x;
        As[lk + 1][lm] = av.y;
        As[lk + 2][lm] = av.z;
        As[lk + 3][lm] = av.w;
        float4 wv = *(const float4*)(Wout + (size_t)(n0 + lm) * DM + kt + lk);
        Ws[lk + 0][lm] = wv.x;
        Ws[lk + 1][lm] = wv.y;
        Ws[lk + 2][lm] = wv.z;
        Ws[lk + 3][lm] = wv.w;
        __syncthreads();
#pragma unroll
        for (int kk = 0; kk < 16; kk++) {
            float4 a = *(const float4*)&As[kk][ty * 4];
            float4 w = *(const float4*)&Ws[kk][tx * 4];
            float avr[4] = {a.x, a.y, a.z, a.w};
            float wvr[4] = {w.x, w.y, w.z, w.w};
#pragma unroll
            for (int i = 0; i < 4; i++)
#pragma unroll
                for (int j = 0; j < 4; j++) acc[i][j] += avr[i] * wvr[j];
        }
        __syncthreads();
    }
    float local = 0.f;
#pragma unroll
    for (int i = 0; i < 4; i++) {
        int bi = m0 + ty * 4 + i;
#pragma unroll
        for (int j = 0; j < 4; j++) {
            int nj = n0 + tx * 4 + j;
            float c = acc[i][j] + bout[nj];
            float d = c - x0[(size_t)bi * NI + nj];
            local += d * d;
        }
    }
#pragma unroll
    for (int o = 16; o > 0; o >>= 1) local += __shfl_xor_sync(0xffffffffu, local, o);
    if ((tid & 31) == 0) sbuf[tid >> 5] = local;
    __syncthreads();
    if (tid == 0) {
        float tot = 0.f;
        for (int i = 0; i < 8; i++) tot += sbuf[i];
        atomicAdd(out, tot * (1.f / ((float)BB * (float)NI)));
    }
}

// ---------------- launch ----------------
extern "C" void kernel_launch(void* const* d_in, const int* in_sizes, int n_in,
                              void* d_out, int out_size) {
    const float* x0    = (const float*)d_in[0];
    const float* t     = (const float*)d_in[1];
    const float* Lvals = (const float*)d_in[2];
    const float* W_in  = (const float*)d_in[3];
    const float* b_in  = (const float*)d_in[4];
    const float* W_out = (const float*)d_in[5];
    const float* b_out = (const float*)d_in[6];
    const float* W_qkv = (const float*)d_in[7];
    const float* b_qkv = (const float*)d_in[8];
    const float* W_o   = (const float*)d_in[9];
    const float* b_o   = (const float*)d_in[10];
    const float* g1    = (const float*)d_in[11];
    const float* be1   = (const float*)d_in[12];
    const float* g2    = (const float*)d_in[13];
    const float* be2   = (const float*)d_in[14];
    const float* W_f1  = (const float*)d_in[15];
    const float* b_f1  = (const float*)d_in[16];
    const float* W_f2  = (const float*)d_in[17];
    const float* b_f2  = (const float*)d_in[18];
    const float* W_t1  = (const float*)d_in[19];
    const float* b_t1  = (const float*)d_in[20];
    const float* W_t2  = (const float*)d_in[21];
    const float* b_t2  = (const float*)d_in[22];
    const int*   Lrows = (const int*)d_in[23];
    const int*   Lcols = (const int*)d_in[24];
    float* out = (float*)d_out;

    float *p_x0T, *p_xt, *p_part, *p_TE, *p_h, *p_h1, *p_v, *p_at, *p_f1, *p_f2, *p_h2;
    float *p_cval;
    int *p_cnt, *p_off, *p_wp, *p_ccol;
    cudaGetSymbolAddress((void**)&p_x0T, g_x0T);
    cudaGetSymbolAddress((void**)&p_xt,  g_xt);
    cudaGetSymbolAddress((void**)&p_part,g_part);
    cudaGetSymbolAddress((void**)&p_TE,  g_TE);
    cudaGetSymbolAddress((void**)&p_h,   g_h);
    cudaGetSymbolAddress((void**)&p_h1,  g_h1);
    cudaGetSymbolAddress((void**)&p_v,   g_v);
    cudaGetSymbolAddress((void**)&p_at,  g_at);
    cudaGetSymbolAddress((void**)&p_f1,  g_f1);
    cudaGetSymbolAddress((void**)&p_f2,  g_f2);
    cudaGetSymbolAddress((void**)&p_h2,  g_h2);
    cudaGetSymbolAddress((void**)&p_cnt, g_cnt);
    cudaGetSymbolAddress((void**)&p_off, g_off);
    cudaGetSymbolAddress((void**)&p_wp,  g_wp);
    cudaGetSymbolAddress((void**)&p_ccol,g_ccol);
    cudaGetSymbolAddress((void**)&p_cval,g_cval);

    zero1_kernel<<<1, 1>>>(out);

    // CSR build (counting sort by row)
    zeroi_kernel<<<(NI + 255) / 256, 256>>>(p_cnt, NI);
    hist_kernel<<<(NNZV + 255) / 256, 256>>>(Lrows, p_cnt);
    scan_kernel<<<1, 512>>>(p_cnt, p_off);
    copyi_kernel<<<(NI + 255) / 256, 256>>>(p_off, p_wp, NI);
    fill_kernel<<<(NNZV + 255) / 256, 256>>>(Lrows, Lcols, Lvals, p_wp, p_ccol, p_cval);

    transpose_kernel<<<dim3(NI / 32, BB / 32), dim3(32, 8)>>>(x0, p_x0T);
    te_kernel<<<BB, 64>>>(t, W_t1, b_t1, W_t2, b_t2, p_TE);

    // xt = x0T - tc*Lx, gathered per row (no atomics)
    gather_kernel<<<NI, 256>>>(p_x0T, p_off, p_ccol, p_cval, t, p_xt);

    // h = x_t @ W_in^T + b_in + te
    gemm1_kernel<<<dim3(4, 8, NS1), 256>>>(p_xt, W_in, p_part);
    reduce_kernel<<<(BB * DM) / 256, 256>>>(p_part, NS1, BB * DM, DM, b_in, p_TE, 0, p_h);

    // v = h @ Wv^T + bv   (only V third of qkv is used)
    gemmNT_kernel<<<dim3(4, 8, 2), 256>>>(p_h, W_qkv + 2 * DM * DM, p_part, DM, DM, 256);
    reduce_kernel<<<(BB * DM) / 256, 256>>>(p_part, 2, BB * DM, DM, b_qkv + 2 * DM, nullptr, 0, p_v);

    // attn = v @ W_o^T + b_o
    gemmNT_kernel<<<dim3(4, 8, 2), 256>>>(p_v, W_o, p_part, DM, DM, 256);
    reduce_kernel<<<(BB * DM) / 256, 256>>>(p_part, 2, BB * DM, DM, b_o, nullptr, 0, p_at);

    // h1 = LN(h + attn)
    ln_kernel<<<BB, 256>>>(p_h, p_at, g1, be1, p_h1);

    // f1 = gelu(h1 @ W_f1^T + b_f1)
    gemmNT_kernel<<<dim3(4, DFF / 64, 2), 256>>>(p_h1, W_f1, p_part, DFF, DM, 256);
    reduce_kernel<<<(BB * DFF) / 256, 256>>>(p_part, 2, BB * DFF, DFF, b_f1, nullptr, 1, p_f1);

    // f2 = f1 @ W_f2^T + b_f2
    gemmNT_kernel<<<dim3(4, 8, 8), 256>>>(p_f1, W_f2, p_part, DM, DFF, 256);
    reduce_kernel<<<(BB * DM) / 256, 256>>>(p_part, 8, BB * DM, DM, b_f2, nullptr, 0, p_f2);

    // h2 = LN(h1 + f2)
    ln_kernel<<<BB, 256>>>(p_h1, p_f2, g2, be2, p_h2);

    // loss = mean((h2 @ W_out^T + b_out - x0)^2)
    gemm_out_loss_kernel<<<dim3(4, NI / 64), 256>>>(p_h2, W_out, b_out, x0, out);
}

// round 4
// speedup vs baseline: 1.4680x; 1.0079x over previous
#include <cuda_runtime.h>
#include <math.h>
#include <stdint.h>

// Problem dims (fixed)
#define BB   256      // batch
#define NI   16384    // n_items
#define DM   512      // d_model
#define DFF  2048     // ff dim
#define NNZV (NI*33)  // 540672
#define NSMAX 32      // max K-splits (part buffer sizing)
#define NSP1 16       // K-splits for GEMM1

// ---------------- scratch (device globals; no allocation allowed) ----------
__device__ float g_x0T[NI*BB];        // x0 transposed [N,B]
__device__ float g_xt [NI*BB];        // x_t = x0 - tc*Lx, stored [N,B]
__device__ float g_part[NSMAX*BB*DM]; // split-K partials (reused)
__device__ float g_TE [BB*DM];
__device__ float g_h  [BB*DM];
__device__ float g_h1 [BB*DM];
__device__ float g_v  [BB*DM];
__device__ float g_at [BB*DM];
__device__ float g_f1 [BB*DFF];
__device__ float g_f2 [BB*DM];
__device__ float g_h2 [BB*DM];
// CSR build scratch
__device__ int   g_cnt[NI];
__device__ int   g_off[NI + 1];
__device__ int   g_wp [NI];
__device__ int   g_ccol[NNZV];
__device__ float g_cval[NNZV];
__device__ int   g_bsum[64];
__device__ int   g_bexcl[64];

// ---------------- helpers ----------------
__device__ __forceinline__ float tf32r(float x) {
    uint32_t r;
    asm("cvt.rna.tf32.f32 %0, %1;" : "=r"(r) : "f"(x));
    return __uint_as_float(r);
}

#define MMA_TF32(c, a, b) \
    asm volatile("mma.sync.aligned.m16n8k8.row.col.f32.tf32.tf32.f32 " \
                 "{%0,%1,%2,%3}, {%4,%5,%6,%7}, {%8,%9}, {%0,%1,%2,%3};" \
                 : "+f"((c)[0]), "+f"((c)[1]), "+f"((c)[2]), "+f"((c)[3]) \
                 : "r"((a)[0]), "r"((a)[1]), "r"((a)[2]), "r"((a)[3]), \
                   "r"((b)[0]), "r"((b)[1]))

// ---------------- utility kernels ----------------
__global__ void zeroi_kernel(int* __restrict__ p, int n) {
    int i = blockIdx.x * blockDim.x + threadIdx.x;
    if (i < n) p[i] = 0;
}

// x0 [B,N] -> x0T [N,B]
__global__ void transpose_kernel(const float* __restrict__ x, float* __restrict__ xt) {
    __shared__ float s[32][33];
    int n0 = blockIdx.x * 32, b0 = blockIdx.y * 32;
    int tx = threadIdx.x, ty = threadIdx.y;
#pragma unroll
    for (int i = 0; i < 32; i += 8)
        s[ty + i][tx] = x[(size_t)(b0 + ty + i) * NI + n0 + tx];
    __syncthreads();
#pragma unroll
    for (int i = 0; i < 32; i += 8)
        xt[(size_t)(n0 + ty + i) * BB + b0 + tx] = s[tx][ty + i];
}

// ---------------- CSR build ----------------
__global__ void hist_kernel(const int* __restrict__ rows, int* __restrict__ cnt) {
    int i = blockIdx.x * blockDim.x + threadIdx.x;
    if (i < NNZV) atomicAdd(&cnt[rows[i]], 1);
}

// stage 1: per-block (256 bins) exclusive scan, write block totals
__global__ void scan1_kernel(const int* __restrict__ cnt, int* __restrict__ off,
                             int* __restrict__ bsum) {
    __shared__ int ws[8];
    int tid = threadIdx.x;
    int i = blockIdx.x * 256 + tid;
    int c = cnt[i];
    int lane = tid & 31, w = tid >> 5;
    int inc = c;
#pragma unroll
    for (int o = 1; o < 32; o <<= 1) {
        int v = __shfl_up_sync(0xffffffffu, inc, o);
        if (lane >= o) inc += v;
    }
    if (lane == 31) ws[w] = inc;
    __syncthreads();
    if (tid < 8) {
        int v = ws[tid];
#pragma unroll
        for (int o = 1; o < 8; o <<= 1) {
            int u = __shfl_up_sync(0xffu, v, o);
            if (tid >= o) v += u;
        }
        ws[tid] = v;
    }
    __syncthreads();
    int base = (w > 0) ? ws[w - 1] : 0;
    off[i] = base + inc - c;
    if (tid == 255) bsum[blockIdx.x] = ws[7];
}

// stage 2: scan the 64 block totals; also write grand total + zero loss out
__global__ void scan2_kernel(const int* __restrict__ bsum, int* __restrict__ bexcl,
                             int* __restrict__ off, float* __restrict__ loss) {
    __shared__ int ws[2];
    int tid = threadIdx.x;  // 64
    int v = bsum[tid];
    int lane = tid & 31, w = tid >> 5;
    int inc = v;
#pragma unroll
    for (int o = 1; o < 32; o <<= 1) {
        int u = __shfl_up_sync(0xffffffffu, inc, o);
        if (lane >= o) inc += u;
    }
    if (lane == 31) ws[w] = inc;
    __syncthreads();
    int base = (w == 1) ? ws[0] : 0;
    bexcl[tid] = base + inc - v;
    if (tid == 63) off[NI] = base + inc;
    if (tid == 0) *loss = 0.f;
}

// stage 3: add block offsets; copy to write-pointer array
__global__ void scan3_kernel(int* __restrict__ off, const int* __restrict__ bexcl,
                             int* __restrict__ wp) {
    int i = blockIdx.x * 256 + threadIdx.x;
    int v = off[i] + bexcl[blockIdx.x];
    off[i] = v;
    wp[i] = v;
}

__global__ void fill_kernel(const int* __restrict__ rows, const int* __restrict__ cols,
                            const float* __restrict__ vals,
                            int* __restrict__ wp,
                            int* __restrict__ ccol, float* __restrict__ cval) {
    int i = blockIdx.x * blockDim.x + threadIdx.x;
    if (i >= NNZV) return;
    int r = rows[i];
    int p = atomicAdd(&wp[r], 1);
    ccol[p] = cols[i];
    cval[p] = vals[i];
}

// ---------------- gather: xt[r,:] = x0T[r,:] - tc[:] * sum_j val*x0T[col_j,:] ----
__global__ void gather_kernel(const float* __restrict__ x0T,
                              const int* __restrict__ off,
                              const int* __restrict__ ccol,
                              const float* __restrict__ cval,
                              const float* __restrict__ t,
                              float* __restrict__ xt) {
    int r = blockIdx.x;
    int tid = threadIdx.x;            // = batch index b (256 threads)
    int s = off[r], e = off[r + 1];
    float acc = 0.f;
    int j = s;
    for (; j + 1 < e; j += 2) {
        int   c0 = __ldg(&ccol[j]);
        float v0 = __ldg(&cval[j]);
        int   c1 = __ldg(&ccol[j + 1]);
        float v1 = __ldg(&cval[j + 1]);
        acc += v0 * __ldg(&x0T[(size_t)c0 * BB + tid]);
        acc += v1 * __ldg(&x0T[(size_t)c1 * BB + tid]);
    }
    if (j < e) {
        int   c0 = __ldg(&ccol[j]);
        float v0 = __ldg(&cval[j]);
        acc += v0 * __ldg(&x0T[(size_t)c0 * BB + tid]);
    }
    float tc = 0.5f * t[tid];         // t_cont = t * T_MAX
    xt[(size_t)r * BB + tid] = x0T[(size_t)r * BB + tid] - tc * acc;
}

// time embedding: te[b,:] = silu(t[b]*W_t1 + b_t1) @ W_t2.T + b_t2
__global__ void te_kernel(const float* __restrict__ t,
                          const float* __restrict__ Wt1, const float* __restrict__ bt1,
                          const float* __restrict__ Wt2, const float* __restrict__ bt2,
                          float* __restrict__ te) {
    __shared__ float u[32];
    int b = blockIdx.x, tid = threadIdx.x;   // 64 threads
    if (tid < 32) {
        float z = t[b] * Wt1[tid] + bt1[tid];
        u[tid] = z / (1.f + expf(-z));       // silu
    }
    __syncthreads();
    for (int d = tid; d < DM; d += 64) {
        float s = bt2[d];
        const float* w = Wt2 + d * 32;
#pragma unroll
        for (int j = 0; j < 32; j++) s += u[j] * w[j];
        te[b * DM + d] = s;
    }
}

// ---------------- TF32 tensor-core GEMM partial: C = A @ W^T -----------------
// AKM=1: A stored [K, M] (k-major rows, m contiguous), lda = M-stride (BB)
// AKM=0: A stored [M, K] row-major, lda = K
// W stored [N2, K] row-major. C partial [BB, N2] per split.
// CTA: 128 threads, 4 warps in 2x2; CTA tile 64(m) x 64(n), BK=16.
template<int AKM>
__global__ void gemm_tf32_kernel(const float* __restrict__ A,
                                 const float* __restrict__ W,
                                 float* __restrict__ part,
                                 int N2, int K, int lda, int Kper) {
    __shared__ float As[64][20];
    __shared__ float Ws[64][20];
    int m0 = blockIdx.x * 64;
    int n0 = blockIdx.y * 64;
    int k0 = blockIdx.z * Kper;
    int tid = threadIdx.x;
    int w = tid >> 5, lane = tid & 31;
    int wm = (w >> 1) * 32, wn = (w & 1) * 32;
    int g = lane >> 2, tg = lane & 3;

    float acc[2][4][4];
#pragma unroll
    for (int i = 0; i < 2; i++)
#pragma unroll
        for (int j = 0; j < 4; j++)
#pragma unroll
            for (int q = 0; q < 4; q++) acc[i][j][q] = 0.f;

    for (int kt = k0; kt < k0 + Kper; kt += 16) {
        // ---- load A tile -> As[m][k] (tf32-rounded) ----
        if (AKM) {
            int kk = tid >> 3;           // 0..15
            int mb = tid & 7;            // base row, stride 8
            const float* src = A + (size_t)(kt + kk) * lda + m0;
#pragma unroll
            for (int j = 0; j < 8; j++)
                As[mb + 8 * j][kk] = tf32r(src[mb + 8 * j]);
        } else {
            int mm = tid >> 1;           // 0..63
            int kk = (tid & 1) * 8;
            const float* src = A + (size_t)(m0 + mm) * lda + kt + kk;
#pragma unroll
            for (int j = 0; j < 8; j++)
                As[mm][kk + j] = tf32r(src[j]);
        }
        // ---- load W tile -> Ws[n][k] ----
        {
            int nn = tid >> 1;           // 0..63
            int kk = (tid & 1) * 8;
            const float* src = W + (size_t)(n0 + nn) * K + kt + kk;
#pragma unroll
            for (int j = 0; j < 8; j++)
                Ws[nn][kk + j] = tf32r(src[j]);
        }
        __syncthreads();
#pragma unroll
        for (int ks = 0; ks < 16; ks += 8) {
            uint32_t af[2][4], bf[4][2];
#pragma unroll
            for (int mi = 0; mi < 2; mi++) {
                int r0 = wm + mi * 16 + g;
                af[mi][0] = __float_as_uint(As[r0    ][ks + tg]);
                af[mi][1] = __float_as_uint(As[r0 + 8][ks + tg]);
                af[mi][2] = __float_as_uint(As[r0    ][ks + tg + 4]);
                af[mi][3] = __float_as_uint(As[r0 + 8][ks + tg + 4]);
            }
#pragma unroll
            for (int ni = 0; ni < 4; ni++) {
                int rn = wn + ni * 8 + g;
                bf[ni][0] = __float_as_uint(Ws[rn][ks + tg]);
                bf[ni][1] = __float_as_uint(Ws[rn][ks + tg + 4]);
            }
#pragma unroll
            for (int mi = 0; mi < 2; mi++)
#pragma unroll
                for (int ni = 0; ni < 4; ni++)
                    MMA_TF32(acc[mi][ni], af[mi], bf[ni]);
        }
        __syncthreads();
    }
    float* cp = part + (size_t)blockIdx.z * ((size_t)BB * N2);
#pragma unroll
    for (int mi = 0; mi < 2; mi++) {
        int r0 = m0 + wm + mi * 16 + g;
#pragma unroll
        for (int ni = 0; ni < 4; ni++) {
            int col = n0 + wn + ni * 8 + 2 * tg;
            float2 s0 = make_float2(acc[mi][ni][0], acc[mi][ni][1]);
            float2 s1 = make_float2(acc[mi][ni][2], acc[mi][ni][3]);
            *(float2*)&cp[(size_t)r0 * N2 + col]       = s0;
            *(float2*)&cp[(size_t)(r0 + 8) * N2 + col] = s1;
        }
    }
}

// reduce split-K partials + bias (+extra) (+gelu)
__global__ void reduce_kernel(const float* __restrict__ part, int ns, int total,
                              int N2, const float* __restrict__ bias,
                              const float* __restrict__ extra, int act,
                              float* __restrict__ out) {
    int i = blockIdx.x * blockDim.x + threadIdx.x;
    if (i >= total) return;
    float s = 0.f;
    for (int j = 0; j < ns; j++) s += part[(size_t)j * total + i];
    s += bias[i % N2];
    if (extra) s += extra[i];
    if (act == 1) s = 0.5f * s * (1.f + erff(s * 0.70710678118654752f));  // exact gelu
    out[i] = s;
}

// layernorm over D of (x+res)
__global__ void ln_kernel(const float* __restrict__ x, const float* __restrict__ res,
                          const float* __restrict__ g, const float* __restrict__ be,
                          float* __restrict__ out) {
    __shared__ float sbuf[8];
    int b = blockIdx.x, tid = threadIdx.x;     // 256 threads
    const float* xr = x + (size_t)b * DM;
    const float* rr = res + (size_t)b * DM;
    float y0 = xr[tid] + rr[tid];
    float y1 = xr[tid + 256] + rr[tid + 256];
    float s = y0 + y1;
#pragma unroll
    for (int o = 16; o > 0; o >>= 1) s += __shfl_xor_sync(0xffffffffu, s, o);
    if ((tid & 31) == 0) sbuf[tid >> 5] = s;
    __syncthreads();
    if (tid == 0) {
        float tot = 0.f;
        for (int i = 0; i < 8; i++) tot += sbuf[i];
        sbuf[0] = tot;
    }
    __syncthreads();
    float mu = sbuf[0] * (1.f / DM);
    __syncthreads();
    float d0 = y0 - mu, d1 = y1 - mu;
    float q = d0 * d0 + d1 * d1;
#pragma unroll
    for (int o = 16; o > 0; o >>= 1) q += __shfl_xor_sync(0xffffffffu, q, o);
    if ((tid & 31) == 0) sbuf[tid >> 5] = q;
    __syncthreads();
    if (tid == 0) {
        float tot = 0.f;
        for (int i = 0; i < 8; i++) tot += sbuf[i];
        sbuf[0] = tot;
    }
    __syncthreads();
    float inv = rsqrtf(sbuf[0] * (1.f / DM) + 1e-5f);
    out[(size_t)b * DM + tid]       = d0 * inv * g[tid] + be[tid];
    out[(size_t)b * DM + tid + 256] = d1 * inv * g[tid + 256] + be[tid + 256];
}

// final GEMM (h2 @ W_out^T + b_out) fused with MSE-vs-x0 reduction (TF32 mma)
__global__ void gemm_loss_tf32_kernel(const float* __restrict__ A,   // h2 [BB, DM]
                                      const float* __restrict__ W,   // W_out [NI, DM]
                                      const float* __restrict__ bout,
                                      const float* __restrict__ x0,
                                      float* __restrict__ out) {
    __shared__ float As[64][20];
    __shared__ float Ws[64][20];
    __shared__ float sbuf[4];
    int m0 = blockIdx.x * 64;      // batch tile
    int n0 = blockIdx.y * 64;      // item tile
    int tid = threadIdx.x;
    int w = tid >> 5, lane = tid & 31;
    int wm = (w >> 1) * 32, wn = (w & 1) * 32;
    int g = lane >> 2, tg = lane & 3;

    float acc[2][4][4];
#pragma unroll
    for (int i = 0; i < 2; i++)
#pragma unroll
        for (int j = 0; j < 4; j++)
#pragma unroll
            for (int q = 0; q < 4; q++) acc[i][j][q] = 0.f;

    for (int kt = 0; kt < DM; kt += 16) {
        {
            int mm = tid >> 1;
            int kk = (tid & 1) * 8;
            const float* src = A + (size_t)(m0 + mm) * DM + kt + kk;
#pragma unroll
            for (int j = 0; j < 8; j++)
                As[mm][kk + j] = tf32r(src[j]);
        }
        {
            int nn = tid >> 1;
            int kk = (tid & 1) * 8;
            const float* src = W + (size_t)(n0 + nn) * DM + kt + kk;
#pragma unroll
            for (int j = 0; j < 8; j++)
                Ws[nn][kk + j] = tf32r(src[j]);
        }
        __syncthreads();
#pragma unroll
        for (int ks = 0; ks < 16; ks += 8) {
            uint32_t af[2][4], bf[4][2];
#pragma unroll
            for (int mi = 0; mi < 2; mi++) {
                int r0 = wm + mi * 16 + g;
                af[mi][0] = __float_as_uint(As[r0    ][ks + tg]);
                af[mi][1] = __float_as_uint(As[r0 + 8][ks + tg]);
                af[mi][2] = __float_as_uint(As[r0    ][ks + tg + 4]);
                af[mi][3] = __float_as_uint(As[r0 + 8][ks + tg + 4]);
            }
#pragma unroll
            for (int ni = 0; ni < 4; ni++) {
                int rn = wn + ni * 8 + g;
                bf[ni][0] = __float_as_uint(Ws[rn][ks + tg]);
                bf[ni][1] = __float_as_uint(Ws[rn][ks + tg + 4]);
            }
#pragma unroll
            for (int mi = 0; mi < 2; mi++)
#pragma unroll
                for (int ni = 0; ni < 4; ni++)
                    MMA_TF32(acc[mi][ni], af[mi], bf[ni]);
        }
        __syncthreads();
    }
    // loss epilogue
    float local = 0.f;
#pragma unroll
    for (int ni = 0; ni < 4; ni++) {
        int col = n0 + wn + ni * 8 + 2 * tg;
        float bo0 = bout[col], bo1 = bout[col + 1];
#pragma unroll
        for (int mi = 0; mi < 2; mi++) {
            int r0 = m0 + wm + mi * 16 + g;
            float d00 = acc[mi][ni][0] + bo0 - x0[(size_t)r0 * NI + col];
            float d01 = acc[mi][ni][1] + bo1 - x0[(size_t)r0 * NI + col + 1];
            float d10 = acc[mi][ni][2] + bo0 - x0[(size_t)(r0 + 8) * NI + col];
            float d11 = acc[mi][ni][3] + bo1 - x0[(size_t)(r0 + 8) * NI + col + 1];
            local += d00 * d00 + d01 * d01 + d10 * d10 + d11 * d11;
        }
    }
#pragma unroll
    for (int o = 16; o > 0; o >>= 1) local += __shfl_xor_sync(0xffffffffu, local, o);
    if (lane == 0) sbuf[w] = local;
    __syncthreads();
    if (tid == 0) {
        float tot = sbuf[0] + sbuf[1] + sbuf[2] + sbuf[3];
        atomicAdd(out, tot * (1.f / ((float)BB * (float)NI)));
    }
}

// ---------------- launch ----------------
extern "C" void kernel_launch(void* const* d_in, const int* in_sizes, int n_in,
                              void* d_out, int out_size) {
    const float* x0    = (const float*)d_in[0];
    const float* t     = (const float*)d_in[1];
    const float* Lvals = (const float*)d_in[2];
    const float* W_in  = (const float*)d_in[3];
    const float* b_in  = (const float*)d_in[4];
    const float* W_out = (const float*)d_in[5];
    const float* b_out = (const float*)d_in[6];
    const float* W_qkv = (const float*)d_in[7];
    const float* b_qkv = (const float*)d_in[8];
    const float* W_o   = (const float*)d_in[9];
    const float* b_o   = (const float*)d_in[10];
    const float* g1    = (const float*)d_in[11];
    const float* be1   = (const float*)d_in[12];
    const float* g2    = (const float*)d_in[13];
    const float* be2   = (const float*)d_in[14];
    const float* W_f1  = (const float*)d_in[15];
    const float* b_f1  = (const float*)d_in[16];
    const float* W_f2  = (const float*)d_in[17];
    const float* b_f2  = (const float*)d_in[18];
    const float* W_t1  = (const float*)d_in[19];
    const float* b_t1  = (const float*)d_in[20];
    const float* W_t2  = (const float*)d_in[21];
    const float* b_t2  = (const float*)d_in[22];
    const int*   Lrows = (const int*)d_in[23];
    const int*   Lcols = (const int*)d_in[24];
    float* out = (float*)d_out;

    float *p_x0T, *p_xt, *p_part, *p_TE, *p_h, *p_h1, *p_v, *p_at, *p_f1, *p_f2, *p_h2;
    float *p_cval;
    int *p_cnt, *p_off, *p_wp, *p_ccol, *p_bsum, *p_bexcl;
    cudaGetSymbolAddress((void**)&p_x0T, g_x0T);
    cudaGetSymbolAddress((void**)&p_xt,  g_xt);
    cudaGetSymbolAddress((void**)&p_part,g_part);
    cudaGetSymbolAddress((void**)&p_TE,  g_TE);
    cudaGetSymbolAddress((void**)&p_h,   g_h);
    cudaGetSymbolAddress((void**)&p_h1,  g_h1);
    cudaGetSymbolAddress((void**)&p_v,   g_v);
    cudaGetSymbolAddress((void**)&p_at,  g_at);
    cudaGetSymbolAddress((void**)&p_f1,  g_f1);
    cudaGetSymbolAddress((void**)&p_f2,  g_f2);
    cudaGetSymbolAddress((void**)&p_h2,  g_h2);
    cudaGetSymbolAddress((void**)&p_cnt, g_cnt);
    cudaGetSymbolAddress((void**)&p_off, g_off);
    cudaGetSymbolAddress((void**)&p_wp,  g_wp);
    cudaGetSymbolAddress((void**)&p_ccol,g_ccol);
    cudaGetSymbolAddress((void**)&p_cval,g_cval);
    cudaGetSymbolAddress((void**)&p_bsum, g_bsum);
    cudaGetSymbolAddress((void**)&p_bexcl,g_bexcl);

    // CSR build (counting sort by row) + hierarchical scan
    zeroi_kernel<<<(NI + 255) / 256, 256>>>(p_cnt, NI);
    hist_kernel<<<(NNZV + 255) / 256, 256>>>(Lrows, p_cnt);
    scan1_kernel<<<64, 256>>>(p_cnt, p_off, p_bsum);
    scan2_kernel<<<1, 64>>>(p_bsum, p_bexcl, p_off, out);
    scan3_kernel<<<64, 256>>>(p_off, p_bexcl, p_wp);
    fill_kernel<<<(NNZV + 255) / 256, 256>>>(Lrows, Lcols, Lvals, p_wp, p_ccol, p_cval);

    transpose_kernel<<<dim3(NI / 32, BB / 32), dim3(32, 8)>>>(x0, p_x0T);
    te_kernel<<<BB, 64>>>(t, W_t1, b_t1, W_t2, b_t2, p_TE);

    // xt = x0T - tc*Lx, gathered per row (no atomics)
    gather_kernel<<<NI, 256>>>(p_x0T, p_off, p_ccol, p_cval, t, p_xt);

    // h = x_t @ W_in^T + b_in + te   (A is [K=NI, M=BB], k-major)
    gemm_tf32_kernel<1><<<dim3(4, 8, NSP1), 128>>>(p_xt, W_in, p_part, DM, NI, BB, NI / NSP1);
    reduce_kernel<<<(BB * DM) / 256, 256>>>(p_part, NSP1, BB * DM, DM, b_in, p_TE, 0, p_h);

    // v = h @ Wv^T + bv   (only V third of qkv is used)
    gemm_tf32_kernel<0><<<dim3(4, 8, 4), 128>>>(p_h, W_qkv + 2 * DM * DM, p_part, DM, DM, DM, 128);
    reduce_kernel<<<(BB * DM) / 256, 256>>>(p_part, 4, BB * DM, DM, b_qkv + 2 * DM, nullptr, 0, p_v);

    // attn = v @ W_o^T + b_o
    gemm_tf32_kernel<0><<<dim3(4, 8, 4), 128>>>(p_v, W_o, p_part, DM, DM, DM, 128);
    reduce_kernel<<<(BB * DM) / 256, 256>>>(p_part, 4, BB * DM, DM, b_o, nullptr, 0, p_at);

    // h1 = LN(h + attn)
    ln_kernel<<<BB, 256>>>(p_h, p_at, g1, be1, p_h1);

    // f1 = gelu(h1 @ W_f1^T + b_f1)
    gemm_tf32_kernel<0><<<dim3(4, DFF / 64, 2), 128>>>(p_h1, W_f1, p_part, DFF, DM, DM, 256);
    reduce_kernel<<<(BB * DFF) / 256, 256>>>(p_part, 2, BB * DFF, DFF, b_f1, nullptr, 1, p_f1);

    // f2 = f1 @ W_f2^T + b_f2
    gemm_tf32_kernel<0><<<dim3(4, 8, 8), 128>>>(p_f1, W_f2, p_part, DM, DFF, DFF, 256);
    reduce_kernel<<<(BB * DM) / 256, 256>>>(p_part, 8, BB * DM, DM, b_f2, nullptr, 0, p_f2);

    // h2 = LN(h1 + f2)
    ln_kernel<<<BB, 256>>>(p_h1, p_f2, g2, be2, p_h2);

    // loss = mean((h2 @ W_out^T + b_out - x0)^2)
    gemm_loss_tf32_kernel<<<dim3(4, NI / 64), 128>>>(p_h2, W_out, b_out, x0, out);
}

// round 5
// speedup vs baseline: 1.5777x; 1.0747x over previous
#include <cuda_runtime.h>
#include <math.h>
#include <stdint.h>

// Problem dims (fixed)
#define BB   256      // batch
#define NI   16384    // n_items
#define DM   512      // d_model
#define DFF  2048     // ff dim
#define NNZV (NI*33)  // 540672
#define NSMAX 32      // max K-splits (part buffer sizing)
#define NSP1 16       // K-splits for GEMM1

// ---------------- scratch (device globals; no allocation allowed) ----------
__device__ float g_x0T[NI*BB];        // x0 transposed [N,B]
__device__ float g_xt [NI*BB];        // x_t = x0 - tc*Lx, stored [N,B]
__device__ float g_part[NSMAX*BB*DM]; // split-K partials (reused)
__device__ float g_TE [BB*DM];
__device__ float g_h  [BB*DM];
__device__ float g_h1 [BB*DM];
__device__ float g_v  [BB*DM];
__device__ float g_at [BB*DM];
__device__ float g_f1 [BB*DFF];
__device__ float g_f2 [BB*DM];
__device__ float g_h2 [BB*DM];
// CSR build scratch
__device__ int   g_cnt[NI];
__device__ int   g_off[NI + 1];
__device__ int   g_wp [NI];
__device__ int   g_ccol[NNZV];
__device__ float g_cval[NNZV];
__device__ int   g_bsum[64];
__device__ int   g_bexcl[64];

// ---------------- helpers ----------------
__device__ __forceinline__ float tf32r(float x) {
    uint32_t r;
    asm("cvt.rna.tf32.f32 %0, %1;" : "=r"(r) : "f"(x));
    return __uint_as_float(r);
}

#define MMA_TF32(c, a, b) \
    asm volatile("mma.sync.aligned.m16n8k8.row.col.f32.tf32.tf32.f32 " \
                 "{%0,%1,%2,%3}, {%4,%5,%6,%7}, {%8,%9}, {%0,%1,%2,%3};" \
                 : "+f"((c)[0]), "+f"((c)[1]), "+f"((c)[2]), "+f"((c)[3]) \
                 : "r"((a)[0]), "r"((a)[1]), "r"((a)[2]), "r"((a)[3]), \
                   "r"((b)[0]), "r"((b)[1]))

// ---------------- utility kernels ----------------
__global__ void zeroi_kernel(int* __restrict__ p, int n) {
    int i = blockIdx.x * blockDim.x + threadIdx.x;
    if (i < n) p[i] = 0;
}

// x0 [B,N] -> x0T [N,B]
__global__ void transpose_kernel(const float* __restrict__ x, float* __restrict__ xt) {
    __shared__ float s[32][33];
    int n0 = blockIdx.x * 32, b0 = blockIdx.y * 32;
    int tx = threadIdx.x, ty = threadIdx.y;
#pragma unroll
    for (int i = 0; i < 32; i += 8)
        s[ty + i][tx] = x[(size_t)(b0 + ty + i) * NI + n0 + tx];
    __syncthreads();
#pragma unroll
    for (int i = 0; i < 32; i += 8)
        xt[(size_t)(n0 + ty + i) * BB + b0 + tx] = s[tx][ty + i];
}

// ---------------- CSR build ----------------
__global__ void hist_kernel(const int* __restrict__ rows, int* __restrict__ cnt) {
    int i = blockIdx.x * blockDim.x + threadIdx.x;
    if (i < NNZV) atomicAdd(&cnt[rows[i]], 1);
}

__global__ void scan1_kernel(const int* __restrict__ cnt, int* __restrict__ off,
                             int* __restrict__ bsum) {
    __shared__ int ws[8];
    int tid = threadIdx.x;
    int i = blockIdx.x * 256 + tid;
    int c = cnt[i];
    int lane = tid & 31, w = tid >> 5;
    int inc = c;
#pragma unroll
    for (int o = 1; o < 32; o <<= 1) {
        int v = __shfl_up_sync(0xffffffffu, inc, o);
        if (lane >= o) inc += v;
    }
    if (lane == 31) ws[w] = inc;
    __syncthreads();
    if (tid < 8) {
        int v = ws[tid];
#pragma unroll
        for (int o = 1; o < 8; o <<= 1) {
            int u = __shfl_up_sync(0xffu, v, o);
            if (tid >= o) v += u;
        }
        ws[tid] = v;
    }
    __syncthreads();
    int base = (w > 0) ? ws[w - 1] : 0;
    off[i] = base + inc - c;
    if (tid == 255) bsum[blockIdx.x] = ws[7];
}

__global__ void scan2_kernel(const int* __restrict__ bsum, int* __restrict__ bexcl,
                             int* __restrict__ off, float* __restrict__ loss) {
    __shared__ int ws[2];
    int tid = threadIdx.x;  // 64
    int v = bsum[tid];
    int lane = tid & 31, w = tid >> 5;
    int inc = v;
#pragma unroll
    for (int o = 1; o < 32; o <<= 1) {
        int u = __shfl_up_sync(0xffffffffu, inc, o);
        if (lane >= o) inc += u;
    }
    if (lane == 31) ws[w] = inc;
    __syncthreads();
    int base = (w == 1) ? ws[0] : 0;
    bexcl[tid] = base + inc - v;
    if (tid == 63) off[NI] = base + inc;
    if (tid == 0) *loss = 0.f;
}

__global__ void scan3_kernel(int* __restrict__ off, const int* __restrict__ bexcl,
                             int* __restrict__ wp) {
    int i = blockIdx.x * 256 + threadIdx.x;
    int v = off[i] + bexcl[blockIdx.x];
    off[i] = v;
    wp[i] = v;
}

__global__ void fill_kernel(const int* __restrict__ rows, const int* __restrict__ cols,
                            const float* __restrict__ vals,
                            int* __restrict__ wp,
                            int* __restrict__ ccol, float* __restrict__ cval) {
    int i = blockIdx.x * blockDim.x + threadIdx.x;
    if (i >= NNZV) return;
    int r = rows[i];
    int p = atomicAdd(&wp[r], 1);
    ccol[p] = cols[i];
    cval[p] = vals[i];
}

// ---------------- gather: xt[r,:] = x0T[r,:] - tc[:] * sum_j val*x0T[col_j,:] ----
__global__ void gather_kernel(const float* __restrict__ x0T,
                              const int* __restrict__ off,
                              const int* __restrict__ ccol,
                              const float* __restrict__ cval,
                              const float* __restrict__ t,
                              float* __restrict__ xt) {
    int r = blockIdx.x;
    int tid = threadIdx.x;            // = batch index b (256 threads)
    int s = off[r], e = off[r + 1];
    float acc = 0.f;
    int j = s;
    for (; j + 1 < e; j += 2) {
        int   c0 = __ldg(&ccol[j]);
        float v0 = __ldg(&cval[j]);
        int   c1 = __ldg(&ccol[j + 1]);
        float v1 = __ldg(&cval[j + 1]);
        acc += v0 * __ldg(&x0T[(size_t)c0 * BB + tid]);
        acc += v1 * __ldg(&x0T[(size_t)c1 * BB + tid]);
    }
    if (j < e) {
        int   c0 = __ldg(&ccol[j]);
        float v0 = __ldg(&cval[j]);
        acc += v0 * __ldg(&x0T[(size_t)c0 * BB + tid]);
    }
    float tc = 0.5f * t[tid];         // t_cont = t * T_MAX
    xt[(size_t)r * BB + tid] = x0T[(size_t)r * BB + tid] - tc * acc;
}

// time embedding: te[b,:] = silu(t[b]*W_t1 + b_t1) @ W_t2.T + b_t2
__global__ void te_kernel(const float* __restrict__ t,
                          const float* __restrict__ Wt1, const float* __restrict__ bt1,
                          const float* __restrict__ Wt2, const float* __restrict__ bt2,
                          float* __restrict__ te) {
    __shared__ float u[32];
    int b = blockIdx.x, tid = threadIdx.x;   // 64 threads
    if (tid < 32) {
        float z = t[b] * Wt1[tid] + bt1[tid];
        u[tid] = z / (1.f + expf(-z));       // silu
    }
    __syncthreads();
    for (int d = tid; d < DM; d += 64) {
        float s = bt2[d];
        const float* w = Wt2 + d * 32;
#pragma unroll
        for (int j = 0; j < 32; j++) s += u[j] * w[j];
        te[b * DM + d] = s;
    }
}

// =================== BIG TF32 GEMM: 128x128 tile, double-buffered ===========
// AKM=1: A stored [K, M] (k-major, m contiguous), lda = m-stride
// AKM=0: A stored [M, K] row-major, lda = K
// W stored [N2, K] row-major. Writes partial C [BB, N2] per z-split.
// 256 threads = 8 warps (2m x 4n); per warp 64x32; BK=16.
template<int AKM>
__device__ __forceinline__ void big_ldg(const float* __restrict__ A,
                                        const float* __restrict__ W,
                                        int m0, int n0, int kt, int lda, int K,
                                        int tid, float4* ra, float4* rw) {
#pragma unroll
    for (int r = 0; r < 2; r++) {
        int idx = tid + 256 * r;
        if (AKM) {
            int kk = idx >> 5, mq = (idx & 31) << 2;
            ra[r] = *(const float4*)(A + (size_t)(kt + kk) * lda + m0 + mq);
        } else {
            int mm = idx >> 2, kq = (idx & 3) << 2;
            ra[r] = *(const float4*)(A + (size_t)(m0 + mm) * lda + kt + kq);
        }
    }
    int nn = tid >> 1, kq = (tid & 1) * 8;
#pragma unroll
    for (int r = 0; r < 2; r++)
        rw[r] = *(const float4*)(W + (size_t)(n0 + nn) * K + kt + kq + 4 * r);
}

template<int AKM>
__device__ __forceinline__ void big_sts(float As[16][136], float Ws[16][136],
                                        int tid, const float4* ra, const float4* rw) {
#pragma unroll
    for (int r = 0; r < 2; r++) {
        int idx = tid + 256 * r;
        if (AKM) {
            int kk = idx >> 5, mq = (idx & 31) << 2;
            As[kk][mq + 0] = tf32r(ra[r].x);
            As[kk][mq + 1] = tf32r(ra[r].y);
            As[kk][mq + 2] = tf32r(ra[r].z);
            As[kk][mq + 3] = tf32r(ra[r].w);
        } else {
            int mm = idx >> 2, kq = (idx & 3) << 2;
            As[kq + 0][mm] = tf32r(ra[r].x);
            As[kq + 1][mm] = tf32r(ra[r].y);
            As[kq + 2][mm] = tf32r(ra[r].z);
            As[kq + 3][mm] = tf32r(ra[r].w);
        }
    }
    int nn = tid >> 1, kq = (tid & 1) * 8;
#pragma unroll
    for (int r = 0; r < 2; r++) {
        Ws[kq + 4 * r + 0][nn] = tf32r(rw[r].x);
        Ws[kq + 4 * r + 1][nn] = tf32r(rw[r].y);
        Ws[kq + 4 * r + 2][nn] = tf32r(rw[r].z);
        Ws[kq + 4 * r + 3][nn] = tf32r(rw[r].w);
    }
}

__device__ __forceinline__ void big_mma(const float As[16][136], const float Ws[16][136],
                                        int wm, int wn, int g, int tg,
                                        float acc[4][4][4]) {
#pragma unroll
    for (int ks = 0; ks < 16; ks += 8) {
        uint32_t af[4][4], bf[4][2];
#pragma unroll
        for (int mi = 0; mi < 4; mi++) {
            int r0 = wm + mi * 16 + g;
            af[mi][0] = __float_as_uint(As[ks + tg    ][r0]);
            af[mi][1] = __float_as_uint(As[ks + tg    ][r0 + 8]);
            af[mi][2] = __float_as_uint(As[ks + tg + 4][r0]);
            af[mi][3] = __float_as_uint(As[ks + tg + 4][r0 + 8]);
        }
#pragma unroll
        for (int ni = 0; ni < 4; ni++) {
            int rn = wn + ni * 8 + g;
            bf[ni][0] = __float_as_uint(Ws[ks + tg    ][rn]);
            bf[ni][1] = __float_as_uint(Ws[ks + tg + 4][rn]);
        }
#pragma unroll
        for (int mi = 0; mi < 4; mi++)
#pragma unroll
            for (int ni = 0; ni < 4; ni++)
                MMA_TF32(acc[mi][ni], af[mi], bf[ni]);
    }
}

template<int AKM>
__global__ __launch_bounds__(256) void gemm_big_kernel(const float* __restrict__ A,
                                                       const float* __restrict__ W,
                                                       float* __restrict__ part,
                                                       int N2, int K, int lda, int Kper) {
    __shared__ float As[2][16][136];
    __shared__ float Ws[2][16][136];
    int m0 = blockIdx.x * 128;
    int n0 = blockIdx.y * 128;
    int k0 = blockIdx.z * Kper, kend = k0 + Kper;
    int tid = threadIdx.x;
    int w = tid >> 5, lane = tid & 31;
    int wm = (w >> 2) * 64, wn = (w & 3) * 32;
    int g = lane >> 2, tg = lane & 3;

    float acc[4][4][4];
#pragma unroll
    for (int i = 0; i < 4; i++)
#pragma unroll
        for (int j = 0; j < 4; j++)
#pragma unroll
            for (int q = 0; q < 4; q++) acc[i][j][q] = 0.f;

    float4 ra[2], rw[2];
    big_ldg<AKM>(A, W, m0, n0, k0, lda, K, tid, ra, rw);
    big_sts<AKM>(As[0], Ws[0], tid, ra, rw);
    __syncthreads();

    int buf = 0;
    for (int kt = k0; kt < kend; kt += 16) {
        bool has_next = (kt + 16 < kend);
        if (has_next) big_ldg<AKM>(A, W, m0, n0, kt + 16, lda, K, tid, ra, rw);
        big_mma(As[buf], Ws[buf], wm, wn, g, tg, acc);
        if (has_next) big_sts<AKM>(As[buf ^ 1], Ws[buf ^ 1], tid, ra, rw);
        __syncthreads();
        buf ^= 1;
    }

    float* cp = part + (size_t)blockIdx.z * ((size_t)BB * N2);
#pragma unroll
    for (int mi = 0; mi < 4; mi++) {
        int r0 = m0 + wm + mi * 16 + g;
#pragma unroll
        for (int ni = 0; ni < 4; ni++) {
            int col = n0 + wn + ni * 8 + 2 * tg;
            *(float2*)&cp[(size_t)r0 * N2 + col] =
                make_float2(acc[mi][ni][0], acc[mi][ni][1]);
            *(float2*)&cp[(size_t)(r0 + 8) * N2 + col] =
                make_float2(acc[mi][ni][2], acc[mi][ni][3]);
        }
    }
}

// big-tile variant fused with bias + MSE-vs-x0 reduction (K = DM, no split)
__global__ __launch_bounds__(256) void gemm_loss_big_kernel(const float* __restrict__ A,
                                                            const float* __restrict__ W,
                                                            const float* __restrict__ bout,
                                                            const float* __restrict__ x0,
                                                            float* __restrict__ out) {
    __shared__ float As[2][16][136];
    __shared__ float Ws[2][16][136];
    __shared__ float sbuf[8];
    int m0 = blockIdx.x * 128;
    int n0 = blockIdx.y * 128;
    int tid = threadIdx.x;
    int w = tid >> 5, lane = tid & 31;
    int wm = (w >> 2) * 64, wn = (w & 3) * 32;
    int g = lane >> 2, tg = lane & 3;

    float acc[4][4][4];
#pragma unroll
    for (int i = 0; i < 4; i++)
#pragma unroll
        for (int j = 0; j < 4; j++)
#pragma unroll
            for (int q = 0; q < 4; q++) acc[i][j][q] = 0.f;

    float4 ra[2], rw[2];
    big_ldg<0>(A, W, m0, n0, 0, DM, DM, tid, ra, rw);
    big_sts<0>(As[0], Ws[0], tid, ra, rw);
    __syncthreads();

    int buf = 0;
    for (int kt = 0; kt < DM; kt += 16) {
        bool has_next = (kt + 16 < DM);
        if (has_next) big_ldg<0>(A, W, m0, n0, kt + 16, DM, DM, tid, ra, rw);
        big_mma(As[buf], Ws[buf], wm, wn, g, tg, acc);
        if (has_next) big_sts<0>(As[buf ^ 1], Ws[buf ^ 1], tid, ra, rw);
        __syncthreads();
        buf ^= 1;
    }

    float local = 0.f;
#pragma unroll
    for (int ni = 0; ni < 4; ni++) {
        int col = n0 + wn + ni * 8 + 2 * tg;
        float bo0 = bout[col], bo1 = bout[col + 1];
#pragma unroll
        for (int mi = 0; mi < 4; mi++) {
            int r0 = m0 + wm + mi * 16 + g;
            float d00 = acc[mi][ni][0] + bo0 - x0[(size_t)r0 * NI + col];
            float d01 = acc[mi][ni][1] + bo1 - x0[(size_t)r0 * NI + col + 1];
            float d10 = acc[mi][ni][2] + bo0 - x0[(size_t)(r0 + 8) * NI + col];
            float d11 = acc[mi][ni][3] + bo1 - x0[(size_t)(r0 + 8) * NI + col + 1];
            local += d00 * d00 + d01 * d01 + d10 * d10 + d11 * d11;
        }
    }
#pragma unroll
    for (int o = 16; o > 0; o >>= 1) local += __shfl_xor_sync(0xffffffffu, local, o);
    if (lane == 0) sbuf[w] = local;
    __syncthreads();
    if (tid == 0) {
        float tot = 0.f;
#pragma unroll
        for (int i = 0; i < 8; i++) tot += sbuf[i];
        atomicAdd(out, tot * (1.f / ((float)BB * (float)NI)));
    }
}

// ---------------- small TF32 GEMM (middle section, 64x64) -------------------
template<int AKM>
__global__ void gemm_tf32_kernel(const float* __restrict__ A,
                                 const float* __restrict__ W,
                                 float* __restrict__ part,
                                 int N2, int K, int lda, int Kper) {
    __shared__ float As[64][20];
    __shared__ float Ws[64][20];
    int m0 = blockIdx.x * 64;
    int n0 = blockIdx.y * 64;
    int k0 = blockIdx.z * Kper;
    int tid = threadIdx.x;
    int w = tid >> 5, lane = tid & 31;
    int wm = (w >> 1) * 32, wn = (w & 1) * 32;
    int g = lane >> 2, tg = lane & 3;

    float acc[2][4][4];
#pragma unroll
    for (int i = 0; i < 2; i++)
#pragma unroll
        for (int j = 0; j < 4; j++)
#pragma unroll
            for (int q = 0; q < 4; q++) acc[i][j][q] = 0.f;

    for (int kt = k0; kt < k0 + Kper; kt += 16) {
        if (AKM) {
            int kk = tid >> 3;
            int mb = tid & 7;
            const float* src = A + (size_t)(kt + kk) * lda + m0;
#pragma unroll
            for (int j = 0; j < 8; j++)
                As[mb + 8 * j][kk] = tf32r(src[mb + 8 * j]);
        } else {
            int mm = tid >> 1;
            int kk = (tid & 1) * 8;
            const float* src = A + (size_t)(m0 + mm) * lda + kt + kk;
#pragma unroll
            for (int j = 0; j < 8; j++)
                As[mm][kk + j] = tf32r(src[j]);
        }
        {
            int nn = tid >> 1;
            int kk = (tid & 1) * 8;
            const float* src = W + (size_t)(n0 + nn) * K + kt + kk;
#pragma unroll
            for (int j = 0; j < 8; j++)
                Ws[nn][kk + j] = tf32r(src[j]);
        }
        __syncthreads();
#pragma unroll
        for (int ks = 0; ks < 16; ks += 8) {
            uint32_t af[2][4], bf[4][2];
#pragma unroll
            for (int mi = 0; mi < 2; mi++) {
                int r0 = wm + mi * 16 + g;
                af[mi][0] = __float_as_uint(As[r0    ][ks + tg]);
                af[mi][1] = __float_as_uint(As[r0 + 8][ks + tg]);
                af[mi][2] = __float_as_uint(As[r0    ][ks + tg + 4]);
                af[mi][3] = __float_as_uint(As[r0 + 8][ks + tg + 4]);
            }
#pragma unroll
            for (int ni = 0; ni < 4; ni++) {
                int rn = wn + ni * 8 + g;
                bf[ni][0] = __float_as_uint(Ws[rn][ks + tg]);
                bf[ni][1] = __float_as_uint(Ws[rn][ks + tg + 4]);
            }
#pragma unroll
            for (int mi = 0; mi < 2; mi++)
#pragma unroll
                for (int ni = 0; ni < 4; ni++)
                    MMA_TF32(acc[mi][ni], af[mi], bf[ni]);
        }
        __syncthreads();
    }
    float* cp = part + (size_t)blockIdx.z * ((size_t)BB * N2);
#pragma unroll
    for (int mi = 0; mi < 2; mi++) {
        int r0 = m0 + wm + mi * 16 + g;
#pragma unroll
        for (int ni = 0; ni < 4; ni++) {
            int col = n0 + wn + ni * 8 + 2 * tg;
            *(float2*)&cp[(size_t)r0 * N2 + col] =
                make_float2(acc[mi][ni][0], acc[mi][ni][1]);
            *(float2*)&cp[(size_t)(r0 + 8) * N2 + col] =
                make_float2(acc[mi][ni][2], acc[mi][ni][3]);
        }
    }
}

// reduce split-K partials + bias (+extra) (+gelu)
__global__ void reduce_kernel(const float* __restrict__ part, int ns, int total,
                              int N2, const float* __restrict__ bias,
                              const float* __restrict__ extra, int act,
                              float* __restrict__ out) {
    int i = blockIdx.x * blockDim.x + threadIdx.x;
    if (i >= total) return;
    float s = 0.f;
    for (int j = 0; j < ns; j++) s += part[(size_t)j * total + i];
    s += bias[i % N2];
    if (extra) s += extra[i];
    if (act == 1) s = 0.5f * s * (1.f + erff(s * 0.70710678118654752f));  // exact gelu
    out[i] = s;
}

// layernorm over D of (x+res)
__global__ void ln_kernel(const float* __restrict__ x, const float* __restrict__ res,
                          const float* __restrict__ g, const float* __restrict__ be,
                          float* __restrict__ out) {
    __shared__ float sbuf[8];
    int b = blockIdx.x, tid = threadIdx.x;     // 256 threads
    const float* xr = x + (size_t)b * DM;
    const float* rr = res + (size_t)b * DM;
    float y0 = xr[tid] + rr[tid];
    float y1 = xr[tid + 256] + rr[tid + 256];
    float s = y0 + y1;
#pragma unroll
    for (int o = 16; o > 0; o >>= 1) s += __shfl_xor_sync(0xffffffffu, s, o);
    if ((tid & 31) == 0) sbuf[tid >> 5] = s;
    __syncthreads();
    if (tid == 0) {
        float tot = 0.f;
        for (int i = 0; i < 8; i++) tot += sbuf[i];
        sbuf[0] = tot;
    }
    __syncthreads();
    float mu = sbuf[0] * (1.f / DM);
    __syncthreads();
    float d0 = y0 - mu, d1 = y1 - mu;
    float q = d0 * d0 + d1 * d1;
#pragma unroll
    for (int o = 16; o > 0; o >>= 1) q += __shfl_xor_sync(0xffffffffu, q, o);
    if ((tid & 31) == 0) sbuf[tid >> 5] = q;
    __syncthreads();
    if (tid == 0) {
        float tot = 0.f;
        for (int i = 0; i < 8; i++) tot += sbuf[i];
        sbuf[0] = tot;
    }
    __syncthreads();
    float inv = rsqrtf(sbuf[0] * (1.f / DM) + 1e-5f);
    out[(size_t)b * DM + tid]       = d0 * inv * g[tid] + be[tid];
    out[(size_t)b * DM + tid + 256] = d1 * inv * g[tid + 256] + be[tid + 256];
}

// ---------------- launch ----------------
extern "C" void kernel_launch(void* const* d_in, const int* in_sizes, int n_in,
                              void* d_out, int out_size) {
    const float* x0    = (const float*)d_in[0];
    const float* t     = (const float*)d_in[1];
    const float* Lvals = (const float*)d_in[2];
    const float* W_in  = (const float*)d_in[3];
    const float* b_in  = (const float*)d_in[4];
    const float* W_out = (const float*)d_in[5];
    const float* b_out = (const float*)d_in[6];
    const float* W_qkv = (const float*)d_in[7];
    const float* b_qkv = (const float*)d_in[8];
    const float* W_o   = (const float*)d_in[9];
    const float* b_o   = (const float*)d_in[10];
    const float* g1    = (const float*)d_in[11];
    const float* be1   = (const float*)d_in[12];
    const float* g2    = (const float*)d_in[13];
    const float* be2   = (const float*)d_in[14];
    const float* W_f1  = (const float*)d_in[15];
    const float* b_f1  = (const float*)d_in[16];
    const float* W_f2  = (const float*)d_in[17];
    const float* b_f2  = (const float*)d_in[18];
    const float* W_t1  = (const float*)d_in[19];
    const float* b_t1  = (const float*)d_in[20];
    const float* W_t2  = (const float*)d_in[21];
    const float* b_t2  = (const float*)d_in[22];
    const int*   Lrows = (const int*)d_in[23];
    const int*   Lcols = (const int*)d_in[24];
    float* out = (float*)d_out;

    float *p_x0T, *p_xt, *p_part, *p_TE, *p_h, *p_h1, *p_v, *p_at, *p_f1, *p_f2, *p_h2;
    float *p_cval;
    int *p_cnt, *p_off, *p_wp, *p_ccol, *p_bsum, *p_bexcl;
    cudaGetSymbolAddress((void**)&p_x0T, g_x0T);
    cudaGetSymbolAddress((void**)&p_xt,  g_xt);
    cudaGetSymbolAddress((void**)&p_part,g_part);
    cudaGetSymbolAddress((void**)&p_TE,  g_TE);
    cudaGetSymbolAddress((void**)&p_h,   g_h);
    cudaGetSymbolAddress((void**)&p_h1,  g_h1);
    cudaGetSymbolAddress((void**)&p_v,   g_v);
    cudaGetSymbolAddress((void**)&p_at,  g_at);
    cudaGetSymbolAddress((void**)&p_f1,  g_f1);
    cudaGetSymbolAddress((void**)&p_f2,  g_f2);
    cudaGetSymbolAddress((void**)&p_h2,  g_h2);
    cudaGetSymbolAddress((void**)&p_cnt, g_cnt);
    cudaGetSymbolAddress((void**)&p_off, g_off);
    cudaGetSymbolAddress((void**)&p_wp,  g_wp);
    cudaGetSymbolAddress((void**)&p_ccol,g_ccol);
    cudaGetSymbolAddress((void**)&p_cval,g_cval);
    cudaGetSymbolAddress((void**)&p_bsum, g_bsum);
    cudaGetSymbolAddress((void**)&p_bexcl,g_bexcl);

    // CSR build (counting sort by row) + hierarchical scan
    zeroi_kernel<<<(NI + 255) / 256, 256>>>(p_cnt, NI);
    hist_kernel<<<(NNZV + 255) / 256, 256>>>(Lrows, p_cnt);
    scan1_kernel<<<64, 256>>>(p_cnt, p_off, p_bsum);
    scan2_kernel<<<1, 64>>>(p_bsum, p_bexcl, p_off, out);
    scan3_kernel<<<64, 256>>>(p_off, p_bexcl, p_wp);
    fill_kernel<<<(NNZV + 255) / 256, 256>>>(Lrows, Lcols, Lvals, p_wp, p_ccol, p_cval);

    transpose_kernel<<<dim3(NI / 32, BB / 32), dim3(32, 8)>>>(x0, p_x0T);
    te_kernel<<<BB, 64>>>(t, W_t1, b_t1, W_t2, b_t2, p_TE);

    // xt = x0T - tc*Lx, gathered per row (no atomics)
    gather_kernel<<<NI, 256>>>(p_x0T, p_off, p_ccol, p_cval, t, p_xt);

    // h = x_t @ W_in^T + b_in + te   (A is [K=NI, M=BB], k-major; 128x128 tiles)
    gemm_big_kernel<1><<<dim3(2, 4, NSP1), 256>>>(p_xt, W_in, p_part, DM, NI, BB, NI / NSP1);
    reduce_kernel<<<(BB * DM) / 256, 256>>>(p_part, NSP1, BB * DM, DM, b_in, p_TE, 0, p_h);

    // v = h @ Wv^T + bv   (only V third of qkv is used)
    gemm_tf32_kernel<0><<<dim3(4, 8, 4), 128>>>(p_h, W_qkv + 2 * DM * DM, p_part, DM, DM, DM, 128);
    reduce_kernel<<<(BB * DM) / 256, 256>>>(p_part, 4, BB * DM, DM, b_qkv + 2 * DM, nullptr, 0, p_v);

    // attn = v @ W_o^T + b_o
    gemm_tf32_kernel<0><<<dim3(4, 8, 4), 128>>>(p_v, W_o, p_part, DM, DM, DM, 128);
    reduce_kernel<<<(BB * DM) / 256, 256>>>(p_part, 4, BB * DM, DM, b_o, nullptr, 0, p_at);

    // h1 = LN(h + attn)
    ln_kernel<<<BB, 256>>>(p_h, p_at, g1, be1, p_h1);

    // f1 = gelu(h1 @ W_f1^T + b_f1)
    gemm_tf32_kernel<0><<<dim3(4, DFF / 64, 2), 128>>>(p_h1, W_f1, p_part, DFF, DM, DM, 256);
    reduce_kernel<<<(BB * DFF) / 256, 256>>>(p_part, 2, BB * DFF, DFF, b_f1, nullptr, 1, p_f1);

    // f2 = f1 @ W_f2^T + b_f2
    gemm_tf32_kernel<0><<<dim3(4, 8, 8), 128>>>(p_f1, W_f2, p_part, DM, DFF, DFF, 256);
    reduce_kernel<<<(BB * DM) / 256, 256>>>(p_part, 8, BB * DM, DM, b_f2, nullptr, 0, p_f2);

    // h2 = LN(h1 + f2)
    ln_kernel<<<BB, 256>>>(p_h1, p_f2, g2, be2, p_h2);

    // loss = mean((h2 @ W_out^T + b_out - x0)^2)  (128x128 tiles)
    gemm_loss_big_kernel<<<dim3(2, NI / 128), 256>>>(p_h2, W_out, b_out, x0, out);
}

// round 6
// speedup vs baseline: 2.0352x; 1.2900x over previous
#include <cuda_runtime.h>
#include <cuda_bf16.h>
#include <math.h>
#include <stdint.h>

// Problem dims (fixed)
#define BB   256      // batch
#define NI   16384    // n_items
#define DM   512      // d_model
#define DFF  2048     // ff dim
#define NNZV (NI*33)  // 540672
#define NSMAX 32      // max K-splits (part buffer sizing)
#define NSP1 16       // K-splits for GEMM1

// ---------------- scratch (device globals; no allocation allowed) ----------
__device__ float g_x0T[NI*BB];               // x0 transposed [N,B] fp32
__device__ __nv_bfloat16 g_x0Th[NI*BB];      // x0 transposed [N,B] bf16
__device__ float g_xt [NI*BB];               // x_t [N,B]
__device__ float g_part[NSMAX*BB*DM];        // split-K partials (reused)
__device__ float g_h  [BB*DM];
__device__ float g_h1 [BB*DM];
__device__ float g_v  [BB*DM];
__device__ float g_at [BB*DM];
__device__ float g_f1 [BB*DFF];
__device__ float g_f2 [BB*DM];
__device__ float g_h2 [BB*DM];
// CSR build scratch
__device__ int   g_cnt[NI];       // zero-initialized; scan1 re-zeros each replay
__device__ int   g_off[NI + 1];
__device__ int   g_wp [NI];
__device__ int   g_ccol[NNZV];
__device__ float g_cval[NNZV];
__device__ int   g_bsum[64];

// ---------------- helpers ----------------
__device__ __forceinline__ float tf32r(float x) {
    uint32_t r;
    asm("cvt.rna.tf32.f32 %0, %1;" : "=r"(r) : "f"(x));
    return __uint_as_float(r);
}

#define MMA_TF32(c, a, b) \
    asm volatile("mma.sync.aligned.m16n8k8.row.col.f32.tf32.tf32.f32 " \
                 "{%0,%1,%2,%3}, {%4,%5,%6,%7}, {%8,%9}, {%0,%1,%2,%3};" \
                 : "+f"((c)[0]), "+f"((c)[1]), "+f"((c)[2]), "+f"((c)[3]) \
                 : "r"((a)[0]), "r"((a)[1]), "r"((a)[2]), "r"((a)[3]), \
                   "r"((b)[0]), "r"((b)[1]))

__device__ __forceinline__ float gelu_exact(float s) {
    return 0.5f * s * (1.f + erff(s * 0.70710678118654752f));
}

// ---------------- CSR build ----------------
__global__ void hist_kernel(const int* __restrict__ rows, int* __restrict__ cnt) {
    int i = blockIdx.x * blockDim.x + threadIdx.x;
    if (i < NNZV) atomicAdd(&cnt[rows[i]], 1);
}

// per-block (256 bins) exclusive scan, write block totals; resets cnt to 0
__global__ void scan1_kernel(int* __restrict__ cnt, int* __restrict__ off,
                             int* __restrict__ bsum) {
    __shared__ int ws[8];
    int tid = threadIdx.x;
    int i = blockIdx.x * 256 + tid;
    int c = cnt[i];
    cnt[i] = 0;                       // reset for next replay (saves a kernel)
    int lane = tid & 31, w = tid >> 5;
    int inc = c;
#pragma unroll
    for (int o = 1; o < 32; o <<= 1) {
        int v = __shfl_up_sync(0xffffffffu, inc, o);
        if (lane >= o) inc += v;
    }
    if (lane == 31) ws[w] = inc;
    __syncthreads();
    if (tid < 8) {
        int v = ws[tid];
#pragma unroll
        for (int o = 1; o < 8; o <<= 1) {
            int u = __shfl_up_sync(0xffu, v, o);
            if (tid >= o) v += u;
        }
        ws[tid] = v;
    }
    __syncthreads();
    int base = (w > 0) ? ws[w - 1] : 0;
    off[i] = base + inc - c;
    if (tid == 255) bsum[blockIdx.x] = ws[7];
}

// merged scan2+scan3: scan 64 block sums, apply to off, copy to wp, zero loss
__global__ void scan23_kernel(const int* __restrict__ bsum,
                              int* __restrict__ off, int* __restrict__ wp,
                              float* __restrict__ loss) {
    __shared__ int sb[64];
    __shared__ int ws[2];
    int tid = threadIdx.x;   // 1024
    int lane = tid & 31;
    int v = 0, inc = 0;
    if (tid < 64) {
        v = bsum[tid];
        inc = v;
#pragma unroll
        for (int o = 1; o < 32; o <<= 1) {
            int u = __shfl_up_sync(0xffffffffu, inc, o);
            if (lane >= o) inc += u;
        }
        if (lane == 31) ws[tid >> 5] = inc;
    }
    __syncthreads();
    if (tid < 64) {
        int base = (tid >= 32) ? ws[0] : 0;
        sb[tid] = base + inc - v;
    }
    if (tid == 0) *loss = 0.f;
    __syncthreads();
    if (tid == 0) off[NI] = ws[0] + ws[1];
#pragma unroll
    for (int it = 0; it < 16; it++) {
        int i = it * 1024 + tid;
        int val = off[i] + sb[i >> 8];
        off[i] = val;
        wp[i] = val;
    }
}

__global__ void fill_kernel(const int* __restrict__ rows, const int* __restrict__ cols,
                            const float* __restrict__ vals,
                            int* __restrict__ wp,
                            int* __restrict__ ccol, float* __restrict__ cval) {
    int i = blockIdx.x * blockDim.x + threadIdx.x;
    if (i >= NNZV) return;
    int r = rows[i];
    int p = atomicAdd(&wp[r], 1);
    ccol[p] = cols[i];
    cval[p] = vals[i];
}

// ---------------- transpose: x0 [B,N] -> x0T [N,B] fp32 + bf16 ----------
__global__ void transpose_kernel(const float* __restrict__ x,
                                 float* __restrict__ xt,
                                 __nv_bfloat16* __restrict__ xh) {
    __shared__ float s[32][33];
    int n0 = blockIdx.x * 32, b0 = blockIdx.y * 32;
    int tx = threadIdx.x, ty = threadIdx.y;
#pragma unroll
    for (int i = 0; i < 32; i += 8)
        s[ty + i][tx] = x[(size_t)(b0 + ty + i) * NI + n0 + tx];
    __syncthreads();
#pragma unroll
    for (int i = 0; i < 32; i += 8) {
        float val = s[tx][ty + i];
        size_t idx = (size_t)(n0 + ty + i) * BB + b0 + tx;
        xt[idx] = val;
        xh[idx] = __float2bfloat16(val);
    }
}

// ---------------- gather: xt[r,:] = x0T[r,:] - tc[:] * sum_j val*x0Th[col_j,:] --
// 128 threads per row; each thread owns 2 batch lanes (bf16x2 loads).
__global__ void gather_kernel(const float* __restrict__ x0T,
                              const __nv_bfloat16* __restrict__ x0Th,
                              const int* __restrict__ off,
                              const int* __restrict__ ccol,
                              const float* __restrict__ cval,
                              const float* __restrict__ t,
                              float* __restrict__ xt) {
    int r = blockIdx.x;
    int tid = threadIdx.x;        // 0..127
    int b2 = tid * 2;
    int s = off[r], e = off[r + 1];
    float acc0 = 0.f, acc1 = 0.f;
    int j = s;
    for (; j + 3 < e; j += 4) {
        int   c0 = __ldg(&ccol[j]),     c1 = __ldg(&ccol[j + 1]);
        int   c2 = __ldg(&ccol[j + 2]), c3 = __ldg(&ccol[j + 3]);
        float v0 = __ldg(&cval[j]),     v1 = __ldg(&cval[j + 1]);
        float v2 = __ldg(&cval[j + 2]), v3 = __ldg(&cval[j + 3]);
        __nv_bfloat162 h0 = *(const __nv_bfloat162*)(x0Th + (size_t)c0 * BB + b2);
        __nv_bfloat162 h1 = *(const __nv_bfloat162*)(x0Th + (size_t)c1 * BB + b2);
        __nv_bfloat162 h2 = *(const __nv_bfloat162*)(x0Th + (size_t)c2 * BB + b2);
        __nv_bfloat162 h3 = *(const __nv_bfloat162*)(x0Th + (size_t)c3 * BB + b2);
        float2 f0 = __bfloat1622float2(h0);
        float2 f1 = __bfloat1622float2(h1);
        float2 f2 = __bfloat1622float2(h2);
        float2 f3 = __bfloat1622float2(h3);
        acc0 += v0 * f0.x + v1 * f1.x + v2 * f2.x + v3 * f3.x;
        acc1 += v0 * f0.y + v1 * f1.y + v2 * f2.y + v3 * f3.y;
    }
    for (; j < e; j++) {
        int   c0 = __ldg(&ccol[j]);
        float v0 = __ldg(&cval[j]);
        __nv_bfloat162 h0 = *(const __nv_bfloat162*)(x0Th + (size_t)c0 * BB + b2);
        float2 f0 = __bfloat1622float2(h0);
        acc0 += v0 * f0.x;
        acc1 += v0 * f0.y;
    }
    float tc0 = 0.5f * t[b2];
    float tc1 = 0.5f * t[b2 + 1];
    float2 xv = *(const float2*)(x0T + (size_t)r * BB + b2);
    float2 o;
    o.x = xv.x - tc0 * acc0;
    o.y = xv.y - tc1 * acc1;
    *(float2*)(xt + (size_t)r * BB + b2) = o;
}

// =================== BIG TF32 GEMM: 128x128 tile, double-buffered ===========
template<int AKM>
__device__ __forceinline__ void big_ldg(const float* __restrict__ A,
                                        const float* __restrict__ W,
                                        int m0, int n0, int kt, int lda, int K,
                                        int tid, float4* ra, float4* rw) {
#pragma unroll
    for (int r = 0; r < 2; r++) {
        int idx = tid + 256 * r;
        if (AKM) {
            int kk = idx >> 5, mq = (idx & 31) << 2;
            ra[r] = *(const float4*)(A + (size_t)(kt + kk) * lda + m0 + mq);
        } else {
            int mm = idx >> 2, kq = (idx & 3) << 2;
            ra[r] = *(const float4*)(A + (size_t)(m0 + mm) * lda + kt + kq);
        }
    }
    int nn = tid >> 1, kq = (tid & 1) * 8;
#pragma unroll
    for (int r = 0; r < 2; r++)
        rw[r] = *(const float4*)(W + (size_t)(n0 + nn) * K + kt + kq + 4 * r);
}

template<int AKM>
__device__ __forceinline__ void big_sts(float As[16][136], float Ws[16][136],
                                        int tid, const float4* ra, const float4* rw) {
#pragma unroll
    for (int r = 0; r < 2; r++) {
        int idx = tid + 256 * r;
        if (AKM) {
            int kk = idx >> 5, mq = (idx & 31) << 2;
            As[kk][mq + 0] = tf32r(ra[r].x);
            As[kk][mq + 1] = tf32r(ra[r].y);
            As[kk][mq + 2] = tf32r(ra[r].z);
            As[kk][mq + 3] = tf32r(ra[r].w);
        } else {
            int mm = idx >> 2, kq = (idx & 3) << 2;
            As[kq + 0][mm] = tf32r(ra[r].x);
            As[kq + 1][mm] = tf32r(ra[r].y);
            As[kq + 2][mm] = tf32r(ra[r].z);
            As[kq + 3][mm] = tf32r(ra[r].w);
        }
    }
    int nn = tid >> 1, kq = (tid & 1) * 8;
#pragma unroll
    for (int r = 0; r < 2; r++) {
        Ws[kq + 4 * r + 0][nn] = tf32r(rw[r].x);
        Ws[kq + 4 * r + 1][nn] = tf32r(rw[r].y);
        Ws[kq + 4 * r + 2][nn] = tf32r(rw[r].z);
        Ws[kq + 4 * r + 3][nn] = tf32r(rw[r].w);
    }
}

__device__ __forceinline__ void big_mma(const float As[16][136], const float Ws[16][136],
                                        int wm, int wn, int g, int tg,
                                        float acc[4][4][4]) {
#pragma unroll
    for (int ks = 0; ks < 16; ks += 8) {
        uint32_t af[4][4], bf[4][2];
#pragma unroll
        for (int mi = 0; mi < 4; mi++) {
            int r0 = wm + mi * 16 + g;
            af[mi][0] = __float_as_uint(As[ks + tg    ][r0]);
            af[mi][1] = __float_as_uint(As[ks + tg    ][r0 + 8]);
            af[mi][2] = __float_as_uint(As[ks + tg + 4][r0]);
            af[mi][3] = __float_as_uint(As[ks + tg + 4][r0 + 8]);
        }
#pragma unroll
        for (int ni = 0; ni < 4; ni++) {
            int rn = wn + ni * 8 + g;
            bf[ni][0] = __float_as_uint(Ws[ks + tg    ][rn]);
            bf[ni][1] = __float_as_uint(Ws[ks + tg + 4][rn]);
        }
#pragma unroll
        for (int mi = 0; mi < 4; mi++)
#pragma unroll
            for (int ni = 0; ni < 4; ni++)
                MMA_TF32(acc[mi][ni], af[mi], bf[ni]);
    }
}

template<int AKM>
__global__ __launch_bounds__(256) void gemm_big_kernel(const float* __restrict__ A,
                                                       const float* __restrict__ W,
                                                       float* __restrict__ part,
                                                       int N2, int K, int lda, int Kper) {
    __shared__ float As[2][16][136];
    __shared__ float Ws[2][16][136];
    int m0 = blockIdx.x * 128;
    int n0 = blockIdx.y * 128;
    int k0 = blockIdx.z * Kper, kend = k0 + Kper;
    int tid = threadIdx.x;
    int w = tid >> 5, lane = tid & 31;
    int wm = (w >> 2) * 64, wn = (w & 3) * 32;
    int g = lane >> 2, tg = lane & 3;

    float acc[4][4][4];
#pragma unroll
    for (int i = 0; i < 4; i++)
#pragma unroll
        for (int j = 0; j < 4; j++)
#pragma unroll
            for (int q = 0; q < 4; q++) acc[i][j][q] = 0.f;

    float4 ra[2], rw[2];
    big_ldg<AKM>(A, W, m0, n0, k0, lda, K, tid, ra, rw);
    big_sts<AKM>(As[0], Ws[0], tid, ra, rw);
    __syncthreads();

    int buf = 0;
    for (int kt = k0; kt < kend; kt += 16) {
        bool has_next = (kt + 16 < kend);
        if (has_next) big_ldg<AKM>(A, W, m0, n0, kt + 16, lda, K, tid, ra, rw);
        big_mma(As[buf], Ws[buf], wm, wn, g, tg, acc);
        if (has_next) big_sts<AKM>(As[buf ^ 1], Ws[buf ^ 1], tid, ra, rw);
        __syncthreads();
        buf ^= 1;
    }

    float* cp = part + (size_t)blockIdx.z * ((size_t)BB * N2);
#pragma unroll
    for (int mi = 0; mi < 4; mi++) {
        int r0 = m0 + wm + mi * 16 + g;
#pragma unroll
        for (int ni = 0; ni < 4; ni++) {
            int col = n0 + wn + ni * 8 + 2 * tg;
            *(float2*)&cp[(size_t)r0 * N2 + col] =
                make_float2(acc[mi][ni][0], acc[mi][ni][1]);
            *(float2*)&cp[(size_t)(r0 + 8) * N2 + col] =
                make_float2(acc[mi][ni][2], acc[mi][ni][3]);
        }
    }
}

// big-tile variant fused with bias + MSE-vs-x0 reduction (K = DM, no split)
__global__ __launch_bounds__(256) void gemm_loss_big_kernel(const float* __restrict__ A,
                                                            const float* __restrict__ W,
                                                            const float* __restrict__ bout,
                                                            const float* __restrict__ x0,
                                                            float* __restrict__ out) {
    __shared__ float As[2][16][136];
    __shared__ float Ws[2][16][136];
    __shared__ float sbuf[8];
    int m0 = blockIdx.x * 128;
    int n0 = blockIdx.y * 128;
    int tid = threadIdx.x;
    int w = tid >> 5, lane = tid & 31;
    int wm = (w >> 2) * 64, wn = (w & 3) * 32;
    int g = lane >> 2, tg = lane & 3;

    float acc[4][4][4];
#pragma unroll
    for (int i = 0; i < 4; i++)
#pragma unroll
        for (int j = 0; j < 4; j++)
#pragma unroll
            for (int q = 0; q < 4; q++) acc[i][j][q] = 0.f;

    float4 ra[2], rw[2];
    big_ldg<0>(A, W, m0, n0, 0, DM, DM, tid, ra, rw);
    big_sts<0>(As[0], Ws[0], tid, ra, rw);
    __syncthreads();

    int buf = 0;
    for (int kt = 0; kt < DM; kt += 16) {
        bool has_next = (kt + 16 < DM);
        if (has_next) big_ldg<0>(A, W, m0, n0, kt + 16, DM, DM, tid, ra, rw);
        big_mma(As[buf], Ws[buf], wm, wn, g, tg, acc);
        if (has_next) big_sts<0>(As[buf ^ 1], Ws[buf ^ 1], tid, ra, rw);
        __syncthreads();
        buf ^= 1;
    }

    float local = 0.f;
#pragma unroll
    for (int ni = 0; ni < 4; ni++) {
        int col = n0 + wn + ni * 8 + 2 * tg;
        float bo0 = bout[col], bo1 = bout[col + 1];
#pragma unroll
        for (int mi = 0; mi < 4; mi++) {
            int r0 = m0 + wm + mi * 16 + g;
            float d00 = acc[mi][ni][0] + bo0 - x0[(size_t)r0 * NI + col];
            float d01 = acc[mi][ni][1] + bo1 - x0[(size_t)r0 * NI + col + 1];
            float d10 = acc[mi][ni][2] + bo0 - x0[(size_t)(r0 + 8) * NI + col];
            float d11 = acc[mi][ni][3] + bo1 - x0[(size_t)(r0 + 8) * NI + col + 1];
            local += d00 * d00 + d01 * d01 + d10 * d10 + d11 * d11;
        }
    }
#pragma unroll
    for (int o = 16; o > 0; o >>= 1) local += __shfl_xor_sync(0xffffffffu, local, o);
    if (lane == 0) sbuf[w] = local;
    __syncthreads();
    if (tid == 0) {
        float tot = 0.f;
#pragma unroll
        for (int i = 0; i < 8; i++) tot += sbuf[i];
        atomicAdd(out, tot * (1.f / ((float)BB * (float)NI)));
    }
}

// -------- small TF32 GEMM, no split-K, fused bias(+gelu) epilogue ----------
// C[m,n] = act(A[M,K] @ W[N2,K]^T + bias[n]); 64x64 tile, 128 threads.
template<int ACT>
__global__ void gemm_small_kernel(const float* __restrict__ A,
                                  const float* __restrict__ W,
                                  const float* __restrict__ bias,
                                  float* __restrict__ out,
                                  int N2, int K) {
    __shared__ float As[64][20];
    __shared__ float Ws[64][20];
    int m0 = blockIdx.x * 64;
    int n0 = blockIdx.y * 64;
    int tid = threadIdx.x;
    int w = tid >> 5, lane = tid & 31;
    int wm = (w >> 1) * 32, wn = (w & 1) * 32;
    int g = lane >> 2, tg = lane & 3;

    float acc[2][4][4];
#pragma unroll
    for (int i = 0; i < 2; i++)
#pragma unroll
        for (int j = 0; j < 4; j++)
#pragma unroll
            for (int q = 0; q < 4; q++) acc[i][j][q] = 0.f;

    for (int kt = 0; kt < K; kt += 16) {
        {
            int mm = tid >> 1;
            int kk = (tid & 1) * 8;
            const float* src = A + (size_t)(m0 + mm) * K + kt + kk;
#pragma unroll
            for (int j = 0; j < 8; j++)
                As[mm][kk + j] = tf32r(src[j]);
        }
        {
            int nn = tid >> 1;
            int kk = (tid & 1) * 8;
            const float* src = W + (size_t)(n0 + nn) * K + kt + kk;
#pragma unroll
            for (int j = 0; j < 8; j++)
                Ws[nn][kk + j] = tf32r(src[j]);
        }
        __syncthreads();
#pragma unroll
        for (int ks = 0; ks < 16; ks += 8) {
            uint32_t af[2][4], bf[4][2];
#pragma unroll
            for (int mi = 0; mi < 2; mi++) {
                int r0 = wm + mi * 16 + g;
                af[mi][0] = __float_as_uint(As[r0    ][ks + tg]);
                af[mi][1] = __float_as_uint(As[r0 + 8][ks + tg]);
                af[mi][2] = __float_as_uint(As[r0    ][ks + tg + 4]);
                af[mi][3] = __float_as_uint(As[r0 + 8][ks + tg + 4]);
            }
#pragma unroll
            for (int ni = 0; ni < 4; ni++) {
                int rn = wn + ni * 8 + g;
                bf[ni][0] = __float_as_uint(Ws[rn][ks + tg]);
                bf[ni][1] = __float_as_uint(Ws[rn][ks + tg + 4]);
            }
#pragma unroll
            for (int mi = 0; mi < 2; mi++)
#pragma unroll
                for (int ni = 0; ni < 4; ni++)
                    MMA_TF32(acc[mi][ni], af[mi], bf[ni]);
        }
        __syncthreads();
    }
#pragma unroll
    for (int mi = 0; mi < 2; mi++) {
        int r0 = m0 + wm + mi * 16 + g;
#pragma unroll
        for (int ni = 0; ni < 4; ni++) {
            int col = n0 + wn + ni * 8 + 2 * tg;
            float b0v = bias[col], b1v = bias[col + 1];
            float v00 = acc[mi][ni][0] + b0v;
            float v01 = acc[mi][ni][1] + b1v;
            float v10 = acc[mi][ni][2] + b0v;
            float v11 = acc[mi][ni][3] + b1v;
            if (ACT == 1) {
                v00 = gelu_exact(v00); v01 = gelu_exact(v01);
                v10 = gelu_exact(v10); v11 = gelu_exact(v11);
            }
            *(float2*)&out[(size_t)r0 * N2 + col]       = make_float2(v00, v01);
            *(float2*)&out[(size_t)(r0 + 8) * N2 + col] = make_float2(v10, v11);
        }
    }
}

// small TF32 GEMM producing split-K partials (used for f2, K=2048)
__global__ void gemm_split_kernel(const float* __restrict__ A,
                                  const float* __restrict__ W,
                                  float* __restrict__ part,
                                  int N2, int K, int Kper) {
    __shared__ float As[64][20];
    __shared__ float Ws[64][20];
    int m0 = blockIdx.x * 64;
    int n0 = blockIdx.y * 64;
    int k0 = blockIdx.z * Kper;
    int tid = threadIdx.x;
    int w = tid >> 5, lane = tid & 31;
    int wm = (w >> 1) * 32, wn = (w & 1) * 32;
    int g = lane >> 2, tg = lane & 3;

    float acc[2][4][4];
#pragma unroll
    for (int i = 0; i < 2; i++)
#pragma unroll
        for (int j = 0; j < 4; j++)
#pragma unroll
            for (int q = 0; q < 4; q++) acc[i][j][q] = 0.f;

    for (int kt = k0; kt < k0 + Kper; kt += 16) {
        {
            int mm = tid >> 1;
            int kk = (tid & 1) * 8;
            const float* src = A + (size_t)(m0 + mm) * K + kt + kk;
#pragma unroll
            for (int j = 0; j < 8; j++)
                As[mm][kk + j] = tf32r(src[j]);
        }
        {
            int nn = tid >> 1;
            int kk = (tid & 1) * 8;
            const float* src = W + (size_t)(n0 + nn) * K + kt + kk;
#pragma unroll
            for (int j = 0; j < 8; j++)
                Ws[nn][kk + j] = tf32r(src[j]);
        }
        __syncthreads();
#pragma unroll
        for (int ks = 0; ks < 16; ks += 8) {
            uint32_t af[2][4], bf[4][2];
#pragma unroll
            for (int mi = 0; mi < 2; mi++) {
                int r0 = wm + mi * 16 + g;
                af[mi][0] = __float_as_uint(As[r0    ][ks + tg]);
                af[mi][1] = __float_as_uint(As[r0 + 8][ks + tg]);
                af[mi][2] = __float_as_uint(As[r0    ][ks + tg + 4]);
                af[mi][3] = __float_as_uint(As[r0 + 8][ks + tg + 4]);
            }
#pragma unroll
            for (int ni = 0; ni < 4; ni++) {
                int rn = wn + ni * 8 + g;
                bf[ni][0] = __float_as_uint(Ws[rn][ks + tg]);
                bf[ni][1] = __float_as_uint(Ws[rn][ks + tg + 4]);
            }
#pragma unroll
            for (int mi = 0; mi < 2; mi++)
#pragma unroll
                for (int ni = 0; ni < 4; ni++)
                    MMA_TF32(acc[mi][ni], af[mi], bf[ni]);
        }
        __syncthreads();
    }
    float* cp = part + (size_t)blockIdx.z * ((size_t)BB * N2);
#pragma unroll
    for (int mi = 0; mi < 2; mi++) {
        int r0 = m0 + wm + mi * 16 + g;
#pragma unroll
        for (int ni = 0; ni < 4; ni++) {
            int col = n0 + wn + ni * 8 + 2 * tg;
            *(float2*)&cp[(size_t)r0 * N2 + col] =
                make_float2(acc[mi][ni][0], acc[mi][ni][1]);
            *(float2*)&cp[(size_t)(r0 + 8) * N2 + col] =
                make_float2(acc[mi][ni][2], acc[mi][ni][3]);
        }
    }
}

// reduce split-K partials for gemm1 + bias + fused time embedding
__global__ void reduce1_te_kernel(const float* __restrict__ part, int ns,
                                  const float* __restrict__ bias,
                                  const float* __restrict__ t,
                                  const float* __restrict__ Wt1, const float* __restrict__ bt1,
                                  const float* __restrict__ Wt2, const float* __restrict__ bt2,
                                  float* __restrict__ out) {
    __shared__ float u[32];
    int i = blockIdx.x * 256 + threadIdx.x;
    int b = i >> 9;       // / DM
    int d = i & 511;
    if (threadIdx.x < 32) {
        float z = t[b] * Wt1[threadIdx.x] + bt1[threadIdx.x];
        u[threadIdx.x] = z / (1.f + expf(-z));     // silu
    }
    __syncthreads();
    float s = 0.f;
    for (int j = 0; j < ns; j++) s += part[(size_t)j * (BB * DM) + i];
    s += bias[d];
    float te = bt2[d];
    const float* wr = Wt2 + d * 32;
#pragma unroll
    for (int j = 0; j < 32; j++) te += u[j] * wr[j];
    out[i] = s + te;
}

// generic reduce (f2): partials + bias
__global__ void reduce_kernel(const float* __restrict__ part, int ns, int total,
                              int N2, const float* __restrict__ bias,
                              float* __restrict__ out) {
    int i = blockIdx.x * blockDim.x + threadIdx.x;
    if (i >= total) return;
    float s = 0.f;
    for (int j = 0; j < ns; j++) s += part[(size_t)j * total + i];
    s += bias[i % N2];
    out[i] = s;
}

// layernorm over D of (x+res)
__global__ void ln_kernel(const float* __restrict__ x, const float* __restrict__ res,
                          const float* __restrict__ g, const float* __restrict__ be,
                          float* __restrict__ out) {
    __shared__ float sbuf[8];
    int b = blockIdx.x, tid = threadIdx.x;     // 256 threads
    const float* xr = x + (size_t)b * DM;
    const float* rr = res + (size_t)b * DM;
    float y0 = xr[tid] + rr[tid];
    float y1 = xr[tid + 256] + rr[tid + 256];
    float s = y0 + y1;
#pragma unroll
    for (int o = 16; o > 0; o >>= 1) s += __shfl_xor_sync(0xffffffffu, s, o);
    if ((tid & 31) == 0) sbuf[tid >> 5] = s;
    __syncthreads();
    if (tid == 0) {
        float tot = 0.f;
        for (int i = 0; i < 8; i++) tot += sbuf[i];
        sbuf[0] = tot;
    }
    __syncthreads();
    float mu = sbuf[0] * (1.f / DM);
    __syncthreads();
    float d0 = y0 - mu, d1 = y1 - mu;
    float q = d0 * d0 + d1 * d1;
#pragma unroll
    for (int o = 16; o > 0; o >>= 1) q += __shfl_xor_sync(0xffffffffu, q, o);
    if ((tid & 31) == 0) sbuf[tid >> 5] = q;
    __syncthreads();
    if (tid == 0) {
        float tot = 0.f;
        for (int i = 0; i < 8; i++) tot += sbuf[i];
        sbuf[0] = tot;
    }
    __syncthreads();
    float inv = rsqrtf(sbuf[0] * (1.f / DM) + 1e-5f);
    out[(size_t)b * DM + tid]       = d0 * inv * g[tid] + be[tid];
    out[(size_t)b * DM + tid + 256] = d1 * inv * g[tid + 256] + be[tid + 256];
}

// ---------------- launch ----------------
extern "C" void kernel_launch(void* const* d_in, const int* in_sizes, int n_in,
                              void* d_out, int out_size) {
    const float* x0    = (const float*)d_in[0];
    const float* t     = (const float*)d_in[1];
    const float* Lvals = (const float*)d_in[2];
    const float* W_in  = (const float*)d_in[3];
    const float* b_in  = (const float*)d_in[4];
    const float* W_out = (const float*)d_in[5];
    const float* b_out = (const float*)d_in[6];
    const float* W_qkv = (const float*)d_in[7];
    const float* b_qkv = (const float*)d_in[8];
    const float* W_o   = (const float*)d_in[9];
    const float* b_o   = (const float*)d_in[10];
    const float* g1    = (const float*)d_in[11];
    const float* be1   = (const float*)d_in[12];
    const float* g2    = (const float*)d_in[13];
    const float* be2   = (const float*)d_in[14];
    const float* W_f1  = (const float*)d_in[15];
    const float* b_f1  = (const float*)d_in[16];
    const float* W_f2  = (const float*)d_in[17];
    const float* b_f2  = (const float*)d_in[18];
    const float* W_t1  = (const float*)d_in[19];
    const float* b_t1  = (const float*)d_in[20];
    const float* W_t2  = (const float*)d_in[21];
    const float* b_t2  = (const float*)d_in[22];
    const int*   Lrows = (const int*)d_in[23];
    const int*   Lcols = (const int*)d_in[24];
    float* out = (float*)d_out;

    float *p_x0T, *p_xt, *p_part, *p_h, *p_h1, *p_v, *p_at, *p_f1, *p_f2, *p_h2;
    float *p_cval;
    __nv_bfloat16* p_x0Th;
    int *p_cnt, *p_off, *p_wp, *p_ccol, *p_bsum;
    cudaGetSymbolAddress((void**)&p_x0T,  g_x0T);
    cudaGetSymbolAddress((void**)&p_x0Th, g_x0Th);
    cudaGetSymbolAddress((void**)&p_xt,   g_xt);
    cudaGetSymbolAddress((void**)&p_part, g_part);
    cudaGetSymbolAddress((void**)&p_h,    g_h);
    cudaGetSymbolAddress((void**)&p_h1,   g_h1);
    cudaGetSymbolAddress((void**)&p_v,    g_v);
    cudaGetSymbolAddress((void**)&p_at,   g_at);
    cudaGetSymbolAddress((void**)&p_f1,   g_f1);
    cudaGetSymbolAddress((void**)&p_f2,   g_f2);
    cudaGetSymbolAddress((void**)&p_h2,   g_h2);
    cudaGetSymbolAddress((void**)&p_cnt,  g_cnt);
    cudaGetSymbolAddress((void**)&p_off,  g_off);
    cudaGetSymbolAddress((void**)&p_wp,   g_wp);
    cudaGetSymbolAddress((void**)&p_ccol, g_ccol);
    cudaGetSymbolAddress((void**)&p_cval, g_cval);
    cudaGetSymbolAddress((void**)&p_bsum, g_bsum);

    // CSR build: hist -> scan1 (self-resets cnt) -> scan23 (also zeroes loss) -> fill
    hist_kernel<<<(NNZV + 255) / 256, 256>>>(Lrows, p_cnt);
    scan1_kernel<<<64, 256>>>(p_cnt, p_off, p_bsum);
    scan23_kernel<<<1, 1024>>>(p_bsum, p_off, p_wp, out);
    fill_kernel<<<(NNZV + 255) / 256, 256>>>(Lrows, Lcols, Lvals, p_wp, p_ccol, p_cval);

    // transpose (fp32 + bf16)
    transpose_kernel<<<dim3(NI / 32, BB / 32), dim3(32, 8)>>>(x0, p_x0T, p_x0Th);

    // xt = x0T - tc*Lx (bf16 gathered Laplacian, fp32 diagonal)
    gather_kernel<<<NI, 128>>>(p_x0T, p_x0Th, p_off, p_ccol, p_cval, t, p_xt);

    // h = x_t @ W_in^T + b_in + te  (te fused into reduce)
    gemm_big_kernel<1><<<dim3(2, 4, NSP1), 256>>>(p_xt, W_in, p_part, DM, NI, BB, NI / NSP1);
    reduce1_te_kernel<<<(BB * DM) / 256, 256>>>(p_part, NSP1, b_in, t,
                                                W_t1, b_t1, W_t2, b_t2, p_h);

    // v = h @ Wv^T + bv
    gemm_small_kernel<0><<<dim3(4, 8), 128>>>(p_h, W_qkv + 2 * DM * DM,
                                              b_qkv + 2 * DM, p_v, DM, DM);
    // attn = v @ W_o^T + b_o
    gemm_small_kernel<0><<<dim3(4, 8), 128>>>(p_v, W_o, b_o, p_at, DM, DM);

    // h1 = LN(h + attn)
    ln_kernel<<<BB, 256>>>(p_h, p_at, g1, be1, p_h1);

    // f1 = gelu(h1 @ W_f1^T + b_f1)
    gemm_small_kernel<1><<<dim3(4, DFF / 64), 128>>>(p_h1, W_f1, b_f1, p_f1, DFF, DM);

    // f2 = f1 @ W_f2^T + b_f2  (K=2048: split-4 + reduce)
    gemm_split_kernel<<<dim3(4, 8, 4), 128>>>(p_f1, W_f2, p_part, DM, DFF, DFF / 4);
    reduce_kernel<<<(BB * DM) / 256, 256>>>(p_part, 4, BB * DM, DM, b_f2, p_f2);

    // h2 = LN(h1 + f2)
    ln_kernel<<<BB, 256>>>(p_h1, p_f2, g2, be2, p_h2);

    // loss = mean((h2 @ W_out^T + b_out - x0)^2)
    gemm_loss_big_kernel<<<dim3(2, NI / 128), 256>>>(p_h2, W_out, b_out, x0, out);
}

// round 9
// speedup vs baseline: 2.2385x; 1.0999x over previous
#include <cuda_runtime.h>
#include <cuda_bf16.h>
#include <math.h>
#include <stdint.h>

// Problem dims (fixed)
#define BB   256      // batch
#define NI   16384    // n_items
#define DM   512      // d_model
#define DFF  2048     // ff dim
#define NNZV (NI*33)  // 540672
#define NSMAX 32      // max K-splits (part buffer sizing)
#define NSP1 16       // K-splits for GEMM1

// ---------------- scratch (device globals; no allocation allowed) ----------
__device__ float g_x0T[NI*BB];               // x0 transposed [N,B] fp32
__device__ __nv_bfloat16 g_x0Th[NI*BB];      // x0 transposed [N,B] bf16
__device__ __nv_bfloat16 g_xth[NI*BB];       // x_t [N,B] bf16 (k-major for GEMM1)
__device__ __nv_bfloat16 g_Winh[DM*NI];      // W_in bf16
__device__ __nv_bfloat16 g_Wouth[NI*DM];     // W_out bf16
__device__ float g_part[NSMAX*BB*DM];        // split-K partials (reused)
__device__ float g_h  [BB*DM];
__device__ float g_h1 [BB*DM];
__device__ float g_v  [BB*DM];
__device__ float g_at [BB*DM];
__device__ float g_f1 [BB*DFF];
__device__ float g_f2 [BB*DM];
__device__ __nv_bfloat16 g_h2h[BB*DM];       // h2 bf16 (only loss GEMM reads it)
// CSR build scratch
__device__ int   g_cnt[NI];       // zero-initialized; scan1 re-zeros each replay
__device__ int   g_off[NI + 1];
__device__ int   g_wp [NI];
__device__ int   g_ccol[NNZV];
__device__ float g_cval[NNZV];
__device__ int   g_bsum[64];

// ---------------- helpers ----------------
__device__ __forceinline__ float tf32r(float x) {
    uint32_t r;
    asm("cvt.rna.tf32.f32 %0, %1;" : "=r"(r) : "f"(x));
    return __uint_as_float(r);
}

__device__ __forceinline__ uint32_t bf2u(__nv_bfloat162 h) {
    uint32_t u;
    memcpy(&u, &h, 4);
    return u;
}

#define MMA_TF32(c, a, b) \
    asm volatile("mma.sync.aligned.m16n8k8.row.col.f32.tf32.tf32.f32 " \
                 "{%0,%1,%2,%3}, {%4,%5,%6,%7}, {%8,%9}, {%0,%1,%2,%3};" \
                 : "+f"((c)[0]), "+f"((c)[1]), "+f"((c)[2]), "+f"((c)[3]) \
                 : "r"((a)[0]), "r"((a)[1]), "r"((a)[2]), "r"((a)[3]), \
                   "r"((b)[0]), "r"((b)[1]))

#define MMA_BF16(c, a, b) \
    asm volatile("mma.sync.aligned.m16n8k16.row.col.f32.bf16.bf16.f32 " \
                 "{%0,%1,%2,%3}, {%4,%5,%6,%7}, {%8,%9}, {%0,%1,%2,%3};" \
                 : "+f"((c)[0]), "+f"((c)[1]), "+f"((c)[2]), "+f"((c)[3]) \
                 : "r"((a)[0]), "r"((a)[1]), "r"((a)[2]), "r"((a)[3]), \
                   "r"((b)[0]), "r"((b)[1]))

#define LDMATRIX_X4_TRANS(r0, r1, r2, r3, addr) \
    asm volatile("ldmatrix.sync.aligned.m8n8.x4.trans.shared.b16 {%0,%1,%2,%3}, [%4];" \
                 : "=r"(r0), "=r"(r1), "=r"(r2), "=r"(r3) : "r"(addr))

__device__ __forceinline__ float gelu_exact(float s) {
    return 0.5f * s * (1.f + erff(s * 0.70710678118654752f));
}

// ---------------- CSR build ----------------
__global__ void hist_kernel(const int* __restrict__ rows, int* __restrict__ cnt) {
    int i = blockIdx.x * blockDim.x + threadIdx.x;
    if (i < NNZV) atomicAdd(&cnt[rows[i]], 1);
}

// per-block (256 bins) exclusive scan, write block totals; resets cnt to 0
__global__ void scan1_kernel(int* __restrict__ cnt, int* __restrict__ off,
                             int* __restrict__ bsum) {
    __shared__ int ws[8];
    int tid = threadIdx.x;
    int i = blockIdx.x * 256 + tid;
    int c = cnt[i];
    cnt[i] = 0;                       // reset for next replay
    int lane = tid & 31, w = tid >> 5;
    int inc = c;
#pragma unroll
    for (int o = 1; o < 32; o <<= 1) {
        int v = __shfl_up_sync(0xffffffffu, inc, o);
        if (lane >= o) inc += v;
    }
    if (lane == 31) ws[w] = inc;
    __syncthreads();
    if (tid < 8) {
        int v = ws[tid];
#pragma unroll
        for (int o = 1; o < 8; o <<= 1) {
            int u = __shfl_up_sync(0xffu, v, o);
            if (tid >= o) v += u;
        }
        ws[tid] = v;
    }
    __syncthreads();
    int base = (w > 0) ? ws[w - 1] : 0;
    off[i] = base + inc - c;
    if (tid == 255) bsum[blockIdx.x] = ws[7];
}

// merged scan2+scan3: scan 64 block sums, apply to off, copy to wp, zero loss
__global__ void scan23_kernel(const int* __restrict__ bsum,
                              int* __restrict__ off, int* __restrict__ wp,
                              float* __restrict__ loss) {
    __shared__ int sb[64];
    __shared__ int ws[2];
    int tid = threadIdx.x;   // 1024
    int lane = tid & 31;
    int v = 0, inc = 0;
    if (tid < 64) {
        v = bsum[tid];
        inc = v;
#pragma unroll
        for (int o = 1; o < 32; o <<= 1) {
            int u = __shfl_up_sync(0xffffffffu, inc, o);
            if (lane >= o) inc += u;
        }
        if (lane == 31) ws[tid >> 5] = inc;
    }
    __syncthreads();
    if (tid < 64) {
        int base = (tid >= 32) ? ws[0] : 0;
        sb[tid] = base + inc - v;
    }
    if (tid == 0) *loss = 0.f;
    __syncthreads();
    if (tid == 0) off[NI] = ws[0] + ws[1];
#pragma unroll
    for (int it = 0; it < 16; it++) {
        int i = it * 1024 + tid;
        int val = off[i] + sb[i >> 8];
        off[i] = val;
        wp[i] = val;
    }
}

__global__ void fill_kernel(const int* __restrict__ rows, const int* __restrict__ cols,
                            const float* __restrict__ vals,
                            int* __restrict__ wp,
                            int* __restrict__ ccol, float* __restrict__ cval) {
    int i = blockIdx.x * blockDim.x + threadIdx.x;
    if (i >= NNZV) return;
    int r = rows[i];
    int p = atomicAdd(&wp[r], 1);
    ccol[p] = cols[i];
    cval[p] = vals[i];
}

// ---------------- transpose: x0 [B,N] -> x0T [N,B] fp32 + bf16 ----------
__global__ void transpose_kernel(const float* __restrict__ x,
                                 float* __restrict__ xt,
                                 __nv_bfloat16* __restrict__ xh) {
    __shared__ float s[32][33];
    int n0 = blockIdx.x * 32, b0 = blockIdx.y * 32;
    int tx = threadIdx.x, ty = threadIdx.y;
#pragma unroll
    for (int i = 0; i < 32; i += 8)
        s[ty + i][tx] = x[(size_t)(b0 + ty + i) * NI + n0 + tx];
    __syncthreads();
#pragma unroll
    for (int i = 0; i < 32; i += 8) {
        float val = s[tx][ty + i];
        size_t idx = (size_t)(n0 + ty + i) * BB + b0 + tx;
        xt[idx] = val;
        xh[idx] = __float2bfloat16(val);
    }
}

// ---------------- fp32 -> bf16 weight conversion (both weights, one launch) --
// blocks [0, 4096): W_in (DM*NI elems); [4096, 8192): W_out (NI*DM elems)
__global__ void cvt2_kernel(const float* __restrict__ a, __nv_bfloat16* __restrict__ oa,
                            const float* __restrict__ b, __nv_bfloat16* __restrict__ ob) {
    int blk = blockIdx.x;
    const float* src;
    __nv_bfloat16* dst;
    size_t base;
    if (blk < 4096) { src = a; dst = oa; base = (size_t)blk * 2048; }
    else            { src = b; dst = ob; base = (size_t)(blk - 4096) * 2048; }
    size_t i = base + threadIdx.x * 8;
    float4 v0 = *(const float4*)(src + i);
    float4 v1 = *(const float4*)(src + i + 4);
    uint4 o;
    o.x = bf2u(__floats2bfloat162_rn(v0.x, v0.y));
    o.y = bf2u(__floats2bfloat162_rn(v0.z, v0.w));
    o.z = bf2u(__floats2bfloat162_rn(v1.x, v1.y));
    o.w = bf2u(__floats2bfloat162_rn(v1.z, v1.w));
    *(uint4*)(dst + i) = o;
}

// ---------------- gather: xth[r,:] = bf16(x0T[r,:] - tc[:]*sum val*x0Th[col,:]) --
__global__ void gather_kernel(const float* __restrict__ x0T,
                              const __nv_bfloat16* __restrict__ x0Th,
                              const int* __restrict__ off,
                              const int* __restrict__ ccol,
                              const float* __restrict__ cval,
                              const float* __restrict__ t,
                              __nv_bfloat16* __restrict__ xth) {
    int r = blockIdx.x;
    int tid = threadIdx.x;        // 0..127
    int b2 = tid * 2;
    int s = off[r], e = off[r + 1];
    float acc0 = 0.f, acc1 = 0.f;
    int j = s;
    for (; j + 3 < e; j += 4) {
        int   c0 = __ldg(&ccol[j]),     c1 = __ldg(&ccol[j + 1]);
        int   c2 = __ldg(&ccol[j + 2]), c3 = __ldg(&ccol[j + 3]);
        float v0 = __ldg(&cval[j]),     v1 = __ldg(&cval[j + 1]);
        float v2 = __ldg(&cval[j + 2]), v3 = __ldg(&cval[j + 3]);
        float2 f0 = __bfloat1622float2(*(const __nv_bfloat162*)(x0Th + (size_t)c0 * BB + b2));
        float2 f1 = __bfloat1622float2(*(const __nv_bfloat162*)(x0Th + (size_t)c1 * BB + b2));
        float2 f2 = __bfloat1622float2(*(const __nv_bfloat162*)(x0Th + (size_t)c2 * BB + b2));
        float2 f3 = __bfloat1622float2(*(const __nv_bfloat162*)(x0Th + (size_t)c3 * BB + b2));
        acc0 += v0 * f0.x + v1 * f1.x + v2 * f2.x + v3 * f3.x;
        acc1 += v0 * f0.y + v1 * f1.y + v2 * f2.y + v3 * f3.y;
    }
    for (; j < e; j++) {
        int   c0 = __ldg(&ccol[j]);
        float v0 = __ldg(&cval[j]);
        float2 f0 = __bfloat1622float2(*(const __nv_bfloat162*)(x0Th + (size_t)c0 * BB + b2));
        acc0 += v0 * f0.x;
        acc1 += v0 * f0.y;
    }
    float tc0 = 0.5f * t[b2];
    float tc1 = 0.5f * t[b2 + 1];
    float2 xv = *(const float2*)(x0T + (size_t)r * BB + b2);
    __nv_bfloat162 ov = __floats2bfloat162_rn(xv.x - tc0 * acc0, xv.y - tc1 * acc1);
    *(__nv_bfloat162*)(xth + (size_t)r * BB + b2) = ov;
}

// =================== bf16 GEMM1: 128x128 tile, BK=32, double-buffered =======
// A = xth [K=NI, M=BB] k-major bf16; W = Winh [DM, NI] row-major bf16.
// 256 threads, 8 warps (2m x 4n), warp tile 64x32.
__global__ __launch_bounds__(256) void gemm1_bf16_kernel(
    const __nv_bfloat16* __restrict__ A,
    const __nv_bfloat16* __restrict__ W,
    float* __restrict__ part, int Kper) {
    __shared__ __nv_bfloat16 As[2][32][136];   // [k][m], pitch 272B
    __shared__ __nv_bfloat16 Ws[2][128][40];   // [n][k], pitch 80B
    int m0 = blockIdx.x * 128;
    int n0 = blockIdx.y * 128;
    int k0 = blockIdx.z * Kper, kend = k0 + Kper;
    int tid = threadIdx.x;
    int w = tid >> 5, lane = tid & 31;
    int wm = (w >> 2) * 64, wn = (w & 3) * 32;
    int g = lane >> 2, tg = lane & 3;
    // ldmatrix per-lane source: k-row and m-col offsets within the tile
    int lm_k = (lane & 7) + ((lane >> 4) << 3);   // 0..15
    int lm_m = (lane & 8);                        // 0 or 8

    float acc[4][4][4];
#pragma unroll
    for (int i = 0; i < 4; i++)
#pragma unroll
        for (int j = 0; j < 4; j++)
#pragma unroll
            for (int q = 0; q < 4; q++) acc[i][j][q] = 0.f;

    // per-tile loads: A 32k x 128m (512 uint4), W 128n x 32k (512 uint4); 2 each
    uint4 ra[2], rw[2];
    int a_kk[2], a_mq[2], w_nn, w_kq;
#pragma unroll
    for (int r = 0; r < 2; r++) {
        int idx = tid + 256 * r;
        a_kk[r] = idx >> 4;
        a_mq[r] = (idx & 15) << 3;
    }
    w_nn = tid >> 1;
    w_kq = (tid & 1) << 4;   // 0 or 16 (two uint4 = 16 k)

#define G1_LDG(kt) do { \
    _Pragma("unroll") \
    for (int r = 0; r < 2; r++) \
        ra[r] = *(const uint4*)(A + (size_t)((kt) + a_kk[r]) * BB + m0 + a_mq[r]); \
    rw[0] = *(const uint4*)(W + (size_t)(n0 + w_nn) * NI + (kt) + w_kq); \
    rw[1] = *(const uint4*)(W + (size_t)(n0 + w_nn) * NI + (kt) + w_kq + 8); \
} while (0)

#define G1_STS(buf) do { \
    _Pragma("unroll") \
    for (int r = 0; r < 2; r++) \
        *(uint4*)&As[buf][a_kk[r]][a_mq[r]] = ra[r]; \
    *(uint4*)&Ws[buf][w_nn][w_kq] = rw[0]; \
    *(uint4*)&Ws[buf][w_nn][w_kq + 8] = rw[1]; \
} while (0)

    G1_LDG(k0);
    G1_STS(0);
    __syncthreads();

    int buf = 0;
    for (int kt = k0; kt < kend; kt += 32) {
        bool has_next = (kt + 32 < kend);
        if (has_next) G1_LDG(kt + 32);
#pragma unroll
        for (int kc = 0; kc < 32; kc += 16) {
            uint32_t af[4][4], bfr[4][2];
#pragma unroll
            for (int mi = 0; mi < 4; mi++) {
                uint32_t sa = (uint32_t)__cvta_generic_to_shared(
                    &As[buf][kc + lm_k][wm + mi * 16 + lm_m]);
                LDMATRIX_X4_TRANS(af[mi][0], af[mi][1], af[mi][2], af[mi][3], sa);
            }
#pragma unroll
            for (int ni = 0; ni < 4; ni++) {
                int rn = wn + ni * 8 + g;
                bfr[ni][0] = *(const uint32_t*)&Ws[buf][rn][kc + 2 * tg];
                bfr[ni][1] = *(const uint32_t*)&Ws[buf][rn][kc + 8 + 2 * tg];
            }
#pragma unroll
            for (int mi = 0; mi < 4; mi++)
#pragma unroll
                for (int ni = 0; ni < 4; ni++)
                    MMA_BF16(acc[mi][ni], af[mi], bfr[ni]);
        }
        if (has_next) G1_STS(buf ^ 1);
        __syncthreads();
        buf ^= 1;
    }
#undef G1_LDG
#undef G1_STS

    float* cp = part + (size_t)blockIdx.z * ((size_t)BB * DM);
#pragma unroll
    for (int mi = 0; mi < 4; mi++) {
        int r0 = m0 + wm + mi * 16 + g;
#pragma unroll
        for (int ni = 0; ni < 4; ni++) {
            int col = n0 + wn + ni * 8 + 2 * tg;
            *(float2*)&cp[(size_t)r0 * DM + col] =
                make_float2(acc[mi][ni][0], acc[mi][ni][1]);
            *(float2*)&cp[(size_t)(r0 + 8) * DM + col] =
                make_float2(acc[mi][ni][2], acc[mi][ni][3]);
        }
    }
}

// =========== bf16 loss GEMM: h2h[BB,DM] @ Wouth[NI,DM]^T + bias, MSE ========
__global__ __launch_bounds__(256) void gemm_loss_bf16_kernel(
    const __nv_bfloat16* __restrict__ A,     // [BB, DM] row-major
    const __nv_bfloat16* __restrict__ W,     // [NI, DM] row-major
    const float* __restrict__ bout,
    const float* __restrict__ x0,
    float* __restrict__ out) {
    __shared__ __nv_bfloat16 As[2][128][40];   // [m][k]
    __shared__ __nv_bfloat16 Ws[2][128][40];   // [n][k]
    __shared__ float sbuf[8];
    int m0 = blockIdx.x * 128;
    int n0 = blockIdx.y * 128;
    int tid = threadIdx.x;
    int w = tid >> 5, lane = tid & 31;
    int wm = (w >> 2) * 64, wn = (w & 3) * 32;
    int g = lane >> 2, tg = lane & 3;

    float acc[4][4][4];
#pragma unroll
    for (int i = 0; i < 4; i++)
#pragma unroll
        for (int j = 0; j < 4; j++)
#pragma unroll
            for (int q = 0; q < 4; q++) acc[i][j][q] = 0.f;

    int mm = tid >> 1;
    int kq = (tid & 1) << 4;
    uint4 ra[2], rw[2];

#define GL_LDG(kt) do { \
    ra[0] = *(const uint4*)(A + (size_t)(m0 + mm) * DM + (kt) + kq); \
    ra[1] = *(const uint4*)(A + (size_t)(m0 + mm) * DM + (kt) + kq + 8); \
    rw[0] = *(const uint4*)(W + (size_t)(n0 + mm) * DM + (kt) + kq); \
    rw[1] = *(const uint4*)(W + (size_t)(n0 + mm) * DM + (kt) + kq + 8); \
} while (0)

#define GL_STS(buf) do { \
    *(uint4*)&As[buf][mm][kq] = ra[0]; \
    *(uint4*)&As[buf][mm][kq + 8] = ra[1]; \
    *(uint4*)&Ws[buf][mm][kq] = rw[0]; \
    *(uint4*)&Ws[buf][mm][kq + 8] = rw[1]; \
} while (0)

    GL_LDG(0);
    GL_STS(0);
    __syncthreads();

    int buf = 0;
    for (int kt = 0; kt < DM; kt += 32) {
        bool has_next = (kt + 32 < DM);
        if (has_next) GL_LDG(kt + 32);
#pragma unroll
        for (int kc = 0; kc < 32; kc += 16) {
            uint32_t af[4][4], bfr[4][2];
#pragma unroll
            for (int mi = 0; mi < 4; mi++) {
                int r0 = wm + mi * 16 + g;
                af[mi][0] = *(const uint32_t*)&As[buf][r0    ][kc + 2 * tg];
                af[mi][1] = *(const uint32_t*)&As[buf][r0 + 8][kc + 2 * tg];
                af[mi][2] = *(const uint32_t*)&As[buf][r0    ][kc + 8 + 2 * tg];
                af[mi][3] = *(const uint32_t*)&As[buf][r0 + 8][kc + 8 + 2 * tg];
            }
#pragma unroll
            for (int ni = 0; ni < 4; ni++) {
                int rn = wn + ni * 8 + g;
                bfr[ni][0] = *(const uint32_t*)&Ws[buf][rn][kc + 2 * tg];
                bfr[ni][1] = *(const uint32_t*)&Ws[buf][rn][kc + 8 + 2 * tg];
            }
#pragma unroll
            for (int mi = 0; mi < 4; mi++)
#pragma unroll
                for (int ni = 0; ni < 4; ni++)
                    MMA_BF16(acc[mi][ni], af[mi], bfr[ni]);
        }
        if (has_next) GL_STS(buf ^ 1);
        __syncthreads();
        buf ^= 1;
    }
#undef GL_LDG
#undef GL_STS

    float local = 0.f;
#pragma unroll
    for (int ni = 0; ni < 4; ni++) {
        int col = n0 + wn + ni * 8 + 2 * tg;
        float bo0 = bout[col], bo1 = bout[col + 1];
#pragma unroll
        for (int mi = 0; mi < 4; mi++) {
            int r0 = m0 + wm + mi * 16 + g;
            float d00 = acc[mi][ni][0] + bo0 - x0[(size_t)r0 * NI + col];
            float d01 = acc[mi][ni][1] + bo1 - x0[(size_t)r0 * NI + col + 1];
            float d10 = acc[mi][ni][2] + bo0 - x0[(size_t)(r0 + 8) * NI + col];
            float d11 = acc[mi][ni][3] + bo1 - x0[(size_t)(r0 + 8) * NI + col + 1];
            local += d00 * d00 + d01 * d01 + d10 * d10 + d11 * d11;
        }
    }
#pragma unroll
    for (int o = 16; o > 0; o >>= 1) local += __shfl_xor_sync(0xffffffffu, local, o);
    if (lane == 0) sbuf[w] = local;
    __syncthreads();
    if (tid == 0) {
        float tot = 0.f;
#pragma unroll
        for (int i = 0; i < 8; i++) tot += sbuf[i];
        atomicAdd(out, tot * (1.f / ((float)BB * (float)NI)));
    }
}

// -------- small TF32 GEMM, no split-K, fused bias(+gelu) epilogue ----------
template<int ACT>
__global__ void gemm_small_kernel(const float* __restrict__ A,
                                  const float* __restrict__ W,
                                  const float* __restrict__ bias,
                                  float* __restrict__ out,
                                  int N2, int K) {
    __shared__ float As[64][20];
    __shared__ float Ws[64][20];
    int m0 = blockIdx.x * 64;
    int n0 = blockIdx.y * 64;
    int tid = threadIdx.x;
    int w = tid >> 5, lane = tid & 31;
    int wm = (w >> 1) * 32, wn = (w & 1) * 32;
    int g = lane >> 2, tg = lane & 3;

    float acc[2][4][4];
#pragma unroll
    for (int i = 0; i < 2; i++)
#pragma unroll
        for (int j = 0; j < 4; j++)
#pragma unroll
            for (int q = 0; q < 4; q++) acc[i][j][q] = 0.f;

    for (int kt = 0; kt < K; kt += 16) {
        {
            int mm = tid >> 1;
            int kk = (tid & 1) * 8;
            const float* src = A + (size_t)(m0 + mm) * K + kt + kk;
#pragma unroll
            for (int j = 0; j < 8; j++)
                As[mm][kk + j] = tf32r(src[j]);
        }
        {
            int nn = tid >> 1;
            int kk = (tid & 1) * 8;
            const float* src = W + (size_t)(n0 + nn) * K + kt + kk;
#pragma unroll
            for (int j = 0; j < 8; j++)
                Ws[nn][kk + j] = tf32r(src[j]);
        }
        __syncthreads();
#pragma unroll
        for (int ks = 0; ks < 16; ks += 8) {
            uint32_t af[2][4], bf[4][2];
#pragma unroll
            for (int mi = 0; mi < 2; mi++) {
                int r0 = wm + mi * 16 + g;
                af[mi][0] = __float_as_uint(As[r0    ][ks + tg]);
                af[mi][1] = __float_as_uint(As[r0 + 8][ks + tg]);
                af[mi][2] = __float_as_uint(As[r0    ][ks + tg + 4]);
                af[mi][3] = __float_as_uint(As[r0 + 8][ks + tg + 4]);
            }
#pragma unroll
            for (int ni = 0; ni < 4; ni++) {
                int rn = wn + ni * 8 + g;
                bf[ni][0] = __float_as_uint(Ws[rn][ks + tg]);
                bf[ni][1] = __float_as_uint(Ws[rn][ks + tg + 4]);
            }
#pragma unroll
            for (int mi = 0; mi < 2; mi++)
#pragma unroll
                for (int ni = 0; ni < 4; ni++)
                    MMA_TF32(acc[mi][ni], af[mi], bf[ni]);
        }
        __syncthreads();
    }
#pragma unroll
    for (int mi = 0; mi < 2; mi++) {
        int r0 = m0 + wm + mi * 16 + g;
#pragma unroll
        for (int ni = 0; ni < 4; ni++) {
            int col = n0 + wn + ni * 8 + 2 * tg;
            float b0v = bias[col], b1v = bias[col + 1];
            float v00 = acc[mi][ni][0] + b0v;
            float v01 = acc[mi][ni][1] + b1v;
            float v10 = acc[mi][ni][2] + b0v;
            float v11 = acc[mi][ni][3] + b1v;
            if (ACT == 1) {
                v00 = gelu_exact(v00); v01 = gelu_exact(v01);
                v10 = gelu_exact(v10); v11 = gelu_exact(v11);
            }
            *(float2*)&out[(size_t)r0 * N2 + col]       = make_float2(v00, v01);
            *(float2*)&out[(size_t)(r0 + 8) * N2 + col] = make_float2(v10, v11);
        }
    }
}

// small TF32 GEMM producing split-K partials (used for f2, K=2048)
__global__ void gemm_split_kernel(const float* __restrict__ A,
                                  const float* __restrict__ W,
                                  float* __restrict__ part,
                                  int N2, int K, int Kper) {
    __shared__ float As[64][20];
    __shared__ float Ws[64][20];
    int m0 = blockIdx.x * 64;
    int n0 = blockIdx.y * 64;
    int k0 = blockIdx.z * Kper;
    int tid = threadIdx.x;
    int w = tid >> 5, lane = tid & 31;
    int wm = (w >> 1) * 32, wn = (w & 1) * 32;
    int g = lane >> 2, tg = lane & 3;

    float acc[2][4][4];
#pragma unroll
    for (int i = 0; i < 2; i++)
#pragma unroll
        for (int j = 0; j < 4; j++)
#pragma unroll
            for (int q = 0; q < 4; q++) acc[i][j][q] = 0.f;

    for (int kt = k0; kt < k0 + Kper; kt += 16) {
        {
            int mm = tid >> 1;
            int kk = (tid & 1) * 8;
            const float* src = A + (size_t)(m0 + mm) * K + kt + kk;
#pragma unroll
            for (int j = 0; j < 8; j++)
                As[mm][kk + j] = tf32r(src[j]);
        }
        {
            int nn = tid >> 1;
            int kk = (tid & 1) * 8;
            const float* src = W + (size_t)(n0 + nn) * K + kt + kk;
#pragma unroll
            for (int j = 0; j < 8; j++)
                Ws[nn][kk + j] = tf32r(src[j]);
        }
        __syncthreads();
#pragma unroll
        for (int ks = 0; ks < 16; ks += 8) {
            uint32_t af[2][4], bf[4][2];
#pragma unroll
            for (int mi = 0; mi < 2; mi++) {
                int r0 = wm + mi * 16 + g;
                af[mi][0] = __float_as_uint(As[r0    ][ks + tg]);
                af[mi][1] = __float_as_uint(As[r0 + 8][ks + tg]);
                af[mi][2] = __float_as_uint(As[r0    ][ks + tg + 4]);
                af[mi][3] = __float_as_uint(As[r0 + 8][ks + tg + 4]);
            }
#pragma unroll
            for (int ni = 0; ni < 4; ni++) {
                int rn = wn + ni * 8 + g;
                bf[ni][0] = __float_as_uint(Ws[rn][ks + tg]);
                bf[ni][1] = __float_as_uint(Ws[rn][ks + tg + 4]);
            }
#pragma unroll
            for (int mi = 0; mi < 2; mi++)
#pragma unroll
                for (int ni = 0; ni < 4; ni++)
                    MMA_TF32(acc[mi][ni], af[mi], bf[ni]);
        }
        __syncthreads();
    }
    float* cp = part + (size_t)blockIdx.z * ((size_t)BB * N2);
#pragma unroll
    for (int mi = 0; mi < 2; mi++) {
        int r0 = m0 + wm + mi * 16 + g;
#pragma unroll
        for (int ni = 0; ni < 4; ni++) {
            int col = n0 + wn + ni * 8 + 2 * tg;
            *(float2*)&cp[(size_t)r0 * N2 + col] =
                make_float2(acc[mi][ni][0], acc[mi][ni][1]);
            *(float2*)&cp[(size_t)(r0 + 8) * N2 + col] =
                make_float2(acc[mi][ni][2], acc[mi][ni][3]);
        }
    }
}

// reduce split-K partials for gemm1 + bias + fused time embedding
__global__ void reduce1_te_kernel(const float* __restrict__ part, int ns,
                                  const float* __restrict__ bias,
                                  const float* __restrict__ t,
                                  const float* __restrict__ Wt1, const float* __restrict__ bt1,
                                  const float* __restrict__ Wt2, const float* __restrict__ bt2,
                                  float* __restrict__ out) {
    __shared__ float u[32];
    int i = blockIdx.x * 256 + threadIdx.x;
    int b = i >> 9;       // / DM
    int d = i & 511;
    if (threadIdx.x < 32) {
        float z = t[b] * Wt1[threadIdx.x] + bt1[threadIdx.x];
        u[threadIdx.x] = z / (1.f + expf(-z));     // silu
    }
    __syncthreads();
    float s = 0.f;
    for (int j = 0; j < ns; j++) s += part[(size_t)j * (BB * DM) + i];
    s += bias[d];
    float te = bt2[d];
    const float* wr = Wt2 + d * 32;
#pragma unroll
    for (int j = 0; j < 32; j++) te += u[j] * wr[j];
    out[i] = s + te;
}

// generic reduce (f2): partials + bias
__global__ void reduce_kernel(const float* __restrict__ part, int ns, int total,
                              int N2, const float* __restrict__ bias,
                              float* __restrict__ out) {
    int i = blockIdx.x * blockDim.x + threadIdx.x;
    if (i >= total) return;
    float s = 0.f;
    for (int j = 0; j < ns; j++) s += part[(size_t)j * total + i];
    s += bias[i % N2];
    out[i] = s;
}

// layernorm over D of (x+res); OBF=1 writes bf16, else fp32
template<int OBF>
__global__ void ln_kernel(const float* __restrict__ x, const float* __restrict__ res,
                          const float* __restrict__ g, const float* __restrict__ be,
                          float* __restrict__ outf, __nv_bfloat16* __restrict__ outh) {
    __shared__ float sbuf[8];
    int b = blockIdx.x, tid = threadIdx.x;     // 256 threads
    const float* xr = x + (size_t)b * DM;
    const float* rr = res + (size_t)b * DM;
    float y0 = xr[tid] + rr[tid];
    float y1 = xr[tid + 256] + rr[tid + 256];
    float s = y0 + y1;
#pragma unroll
    for (int o = 16; o > 0; o >>= 1) s += __shfl_xor_sync(0xffffffffu, s, o);
    if ((tid & 31) == 0) sbuf[tid >> 5] = s;
    __syncthreads();
    if (tid == 0) {
        float tot = 0.f;
        for (int i = 0; i < 8; i++) tot += sbuf[i];
        sbuf[0] = tot;
    }
    __syncthreads();
    float mu = sbuf[0] * (1.f / DM);
    __syncthreads();
    float d0 = y0 - mu, d1 = y1 - mu;
    float q = d0 * d0 + d1 * d1;
#pragma unroll
    for (int o = 16; o > 0; o >>= 1) q += __shfl_xor_sync(0xffffffffu, q, o);
    if ((tid & 31) == 0) sbuf[tid >> 5] = q;
    __syncthreads();
    if (tid == 0) {
        float tot = 0.f;
        for (int i = 0; i < 8; i++) tot += sbuf[i];
        sbuf[0] = tot;
    }
    __syncthreads();
    float inv = rsqrtf(sbuf[0] * (1.f / DM) + 1e-5f);
    float o0 = d0 * inv * g[tid] + be[tid];
    float o1 = d1 * inv * g[tid + 256] + be[tid + 256];
    if (OBF) {
        outh[(size_t)b * DM + tid]       = __float2bfloat16(o0);
        outh[(size_t)b * DM + tid + 256] = __float2bfloat16(o1);
    } else {
        outf[(size_t)b * DM + tid]       = o0;
        outf[(size_t)b * DM + tid + 256] = o1;
    }
}

// ---------------- launch ----------------
extern "C" void kernel_launch(void* const* d_in, const int* in_sizes, int n_in,
                              void* d_out, int out_size) {
    const float* x0    = (const float*)d_in[0];
    const float* t     = (const float*)d_in[1];
    const float* Lvals = (const float*)d_in[2];
    const float* W_in  = (const float*)d_in[3];
    const float* b_in  = (const float*)d_in[4];
    const float* W_out = (const float*)d_in[5];
    const float* b_out = (const float*)d_in[6];
    const float* W_qkv = (const float*)d_in[7];
    const float* b_qkv = (const float*)d_in[8];
    const float* W_o   = (const float*)d_in[9];
    const float* b_o   = (const float*)d_in[10];
    const float* g1    = (const float*)d_in[11];
    const float* be1   = (const float*)d_in[12];
    const float* g2    = (const float*)d_in[13];
    const float* be2   = (const float*)d_in[14];
    const float* W_f1  = (const float*)d_in[15];
    const float* b_f1  = (const float*)d_in[16];
    const float* W_f2  = (const float*)d_in[17];
    const float* b_f2  = (const float*)d_in[18];
    const float* W_t1  = (const float*)d_in[19];
    const float* b_t1  = (const float*)d_in[20];
    const float* W_t2  = (const float*)d_in[21];
    const float* b_t2  = (const float*)d_in[22];
    const int*   Lrows = (const int*)d_in[23];
    const int*   Lcols = (const int*)d_in[24];
    float* out = (float*)d_out;

    float *p_x0T, *p_part, *p_h, *p_h1, *p_v, *p_at, *p_f1, *p_f2;
    float *p_cval;
    __nv_bfloat16 *p_x0Th, *p_xth, *p_Winh, *p_Wouth, *p_h2h;
    int *p_cnt, *p_off, *p_wp, *p_ccol, *p_bsum;
    cudaGetSymbolAddress((void**)&p_x0T,  g_x0T);
    cudaGetSymbolAddress((void**)&p_x0Th, g_x0Th);
    cudaGetSymbolAddress((void**)&p_xth,  g_xth);
    cudaGetSymbolAddress((void**)&p_Winh, g_Winh);
    cudaGetSymbolAddress((void**)&p_Wouth,g_Wouth);
    cudaGetSymbolAddress((void**)&p_part, g_part);
    cudaGetSymbolAddress((void**)&p_h,    g_h);
    cudaGetSymbolAddress((void**)&p_h1,   g_h1);
    cudaGetSymbolAddress((void**)&p_v,    g_v);
    cudaGetSymbolAddress((void**)&p_at,   g_at);
    cudaGetSymbolAddress((void**)&p_f1,   g_f1);
    cudaGetSymbolAddress((void**)&p_f2,   g_f2);
    cudaGetSymbolAddress((void**)&p_h2h,  g_h2h);
    cudaGetSymbolAddress((void**)&p_cnt,  g_cnt);
    cudaGetSymbolAddress((void**)&p_off,  g_off);
    cudaGetSymbolAddress((void**)&p_wp,   g_wp);
    cudaGetSymbolAddress((void**)&p_ccol, g_ccol);
    cudaGetSymbolAddress((void**)&p_cval, g_cval);
    cudaGetSymbolAddress((void**)&p_bsum, g_bsum);

    // CSR build: hist -> scan1 (self-resets cnt) -> scan23 (also zeroes loss) -> fill
    hist_kernel<<<(NNZV + 255) / 256, 256>>>(Lrows, p_cnt);
    scan1_kernel<<<64, 256>>>(p_cnt, p_off, p_bsum);
    scan23_kernel<<<1, 1024>>>(p_bsum, p_off, p_wp, out);
    fill_kernel<<<(NNZV + 255) / 256, 256>>>(Lrows, Lcols, Lvals, p_wp, p_ccol, p_cval);

    // transpose (fp32 + bf16) and weight conversion
    transpose_kernel<<<dim3(NI / 32, BB / 32), dim3(32, 8)>>>(x0, p_x0T, p_x0Th);
    cvt2_kernel<<<8192, 256>>>(W_in, p_Winh, W_out, p_Wouth);

    // xt (bf16) = x0T - tc*Lx
    gather_kernel<<<NI, 128>>>(p_x0T, p_x0Th, p_off, p_ccol, p_cval, t, p_xth);

    // h = x_t @ W_in^T + b_in + te  (bf16 tensor cores; te fused into reduce)
    gemm1_bf16_kernel<<<dim3(2, 4, NSP1), 256>>>(p_xth, p_Winh, p_part, NI / NSP1);
    reduce1_te_kernel<<<(BB * DM) / 256, 256>>>(p_part, NSP1, b_in, t,
                                                W_t1, b_t1, W_t2, b_t2, p_h);

    // v = h @ Wv^T + bv
    gemm_small_kernel<0><<<dim3(4, 8), 128>>>(p_h, W_qkv + 2 * DM * DM,
                                              b_qkv + 2 * DM, p_v, DM, DM);
    // attn = v @ W_o^T + b_o
    gemm_small_kernel<0><<<dim3(4, 8), 128>>>(p_v, W_o, b_o, p_at, DM, DM);

    // h1 = LN(h + attn)
    ln_kernel<0><<<BB, 256>>>(p_h, p_at, g1, be1, p_h1, nullptr);

    // f1 = gelu(h1 @ W_f1^T + b_f1)
    gemm_small_kernel<1><<<dim3(4, DFF / 64), 128>>>(p_h1, W_f1, b_f1, p_f1, DFF, DM);

    // f2 = f1 @ W_f2^T + b_f2  (K=2048: split-4 + reduce)
    gemm_split_kernel<<<dim3(4, 8, 4), 128>>>(p_f1, W_f2, p_part, DM, DFF, DFF / 4);
    reduce_kernel<<<(BB * DM) / 256, 256>>>(p_part, 4, BB * DM, DM, b_f2, p_f2);

    // h2 = LN(h1 + f2) -> bf16
    ln_kernel<1><<<BB, 256>>>(p_h1, p_f2, g2, be2, nullptr, p_h2h);

    // loss = mean((h2 @ W_out^T + b_out - x0)^2)  (bf16 tensor cores)
    gemm_loss_bf16_kernel<<<dim3(2, NI / 128), 256>>>(p_h2h, p_Wouth, b_out, x0, out);
}

// round 10
// speedup vs baseline: 2.7746x; 1.2395x over previous
#include <cuda_runtime.h>
#include <cuda_bf16.h>
#include <math.h>
#include <stdint.h>

// Problem dims (fixed)
#define BB   256      // batch
#define NI   16384    // n_items
#define DM   512      // d_model
#define DFF  2048     // ff dim
#define NNZV (NI*33)  // 540672
#define NSP1 16       // K-splits for GEMM1
#define NCTA_MID 128  // CTAs in the fused middle kernel

// ---------------- scratch (device globals; no allocation allowed) ----------
__device__ float g_x0T[NI*BB];               // x0 transposed [N,B] fp32
__device__ __nv_bfloat16 g_x0Th[NI*BB];      // x0 transposed [N,B] bf16
__device__ __nv_bfloat16 g_xth[NI*BB];       // x_t [N,B] bf16 (k-major for GEMM1)
__device__ __nv_bfloat16 g_Winh[DM*NI];      // W_in bf16
__device__ __nv_bfloat16 g_Wouth[NI*DM];     // W_out bf16
__device__ float g_part[NSP1*BB*DM];         // split-K partials (reused)
__device__ float g_h  [BB*DM];
__device__ float g_h1 [BB*DM];
__device__ float g_v  [BB*DM];
__device__ float g_at [BB*DM];
__device__ float g_f1 [BB*DFF];
__device__ __nv_bfloat16 g_h2h[BB*DM];       // h2 bf16 (only loss GEMM reads it)
// CSR build scratch
__device__ int   g_cnt[NI];       // zero-initialized; scan1 re-zeros each replay
__device__ int   g_off[NI + 1];
__device__ int   g_wp [NI];
__device__ int2  g_cpack[NNZV];   // packed (col, val_bits)
__device__ int   g_bsum[64];
// grid barrier counters for the fused middle kernel (reset by last CTA)
__device__ int   g_bar[8];

// ---------------- helpers ----------------
__device__ __forceinline__ float tf32r(float x) {
    uint32_t r;
    asm("cvt.rna.tf32.f32 %0, %1;" : "=r"(r) : "f"(x));
    return __uint_as_float(r);
}

__device__ __forceinline__ uint32_t bf2u(__nv_bfloat162 h) {
    uint32_t u;
    memcpy(&u, &h, 4);
    return u;
}

#define MMA_TF32(c, a, b) \
    asm volatile("mma.sync.aligned.m16n8k8.row.col.f32.tf32.tf32.f32 " \
                 "{%0,%1,%2,%3}, {%4,%5,%6,%7}, {%8,%9}, {%0,%1,%2,%3};" \
                 : "+f"((c)[0]), "+f"((c)[1]), "+f"((c)[2]), "+f"((c)[3]) \
                 : "r"((a)[0]), "r"((a)[1]), "r"((a)[2]), "r"((a)[3]), \
                   "r"((b)[0]), "r"((b)[1]))

#define MMA_BF16(c, a, b) \
    asm volatile("mma.sync.aligned.m16n8k16.row.col.f32.bf16.bf16.f32 " \
                 "{%0,%1,%2,%3}, {%4,%5,%6,%7}, {%8,%9}, {%0,%1,%2,%3};" \
                 : "+f"((c)[0]), "+f"((c)[1]), "+f"((c)[2]), "+f"((c)[3]) \
                 : "r"((a)[0]), "r"((a)[1]), "r"((a)[2]), "r"((a)[3]), \
                   "r"((b)[0]), "r"((b)[1]))

#define LDMATRIX_X4_TRANS(r0, r1, r2, r3, addr) \
    asm volatile("ldmatrix.sync.aligned.m8n8.x4.trans.shared.b16 {%0,%1,%2,%3}, [%4];" \
                 : "=r"(r0), "=r"(r1), "=r"(r2), "=r"(r3) : "r"(addr))

__device__ __forceinline__ float gelu_exact(float s) {
    return 0.5f * s * (1.f + erff(s * 0.70710678118654752f));
}

// ---------------- CSR build ----------------
__global__ void hist_kernel(const int* __restrict__ rows, int* __restrict__ cnt) {
    int i = blockIdx.x * blockDim.x + threadIdx.x;
    if (i < NNZV) atomicAdd(&cnt[rows[i]], 1);
}

// per-block (256 bins) exclusive scan, write block totals; resets cnt to 0
__global__ void scan1_kernel(int* __restrict__ cnt, int* __restrict__ off,
                             int* __restrict__ bsum) {
    __shared__ int ws[8];
    int tid = threadIdx.x;
    int i = blockIdx.x * 256 + tid;
    int c = cnt[i];
    cnt[i] = 0;                       // reset for next replay
    int lane = tid & 31, w = tid >> 5;
    int inc = c;
#pragma unroll
    for (int o = 1; o < 32; o <<= 1) {
        int v = __shfl_up_sync(0xffffffffu, inc, o);
        if (lane >= o) inc += v;
    }
    if (lane == 31) ws[w] = inc;
    __syncthreads();
    if (tid < 8) {
        int v = ws[tid];
#pragma unroll
        for (int o = 1; o < 8; o <<= 1) {
            int u = __shfl_up_sync(0xffu, v, o);
            if (tid >= o) v += u;
        }
        ws[tid] = v;
    }
    __syncthreads();
    int base = (w > 0) ? ws[w - 1] : 0;
    off[i] = base + inc - c;
    if (tid == 255) bsum[blockIdx.x] = ws[7];
}

// merged scan2+scan3: scan 64 block sums, apply to off, copy to wp, zero loss
__global__ void scan23_kernel(const int* __restrict__ bsum,
                              int* __restrict__ off, int* __restrict__ wp,
                              float* __restrict__ loss) {
    __shared__ int sb[64];
    __shared__ int ws[2];
    int tid = threadIdx.x;   // 1024
    int lane = tid & 31;
    int v = 0, inc = 0;
    if (tid < 64) {
        v = bsum[tid];
        inc = v;
#pragma unroll
        for (int o = 1; o < 32; o <<= 1) {
            int u = __shfl_up_sync(0xffffffffu, inc, o);
            if (lane >= o) inc += u;
        }
        if (lane == 31) ws[tid >> 5] = inc;
    }
    __syncthreads();
    if (tid < 64) {
        int base = (tid >= 32) ? ws[0] : 0;
        sb[tid] = base + inc - v;
    }
    if (tid == 0) *loss = 0.f;
    __syncthreads();
    if (tid == 0) off[NI] = ws[0] + ws[1];
#pragma unroll
    for (int it = 0; it < 16; it++) {
        int i = it * 1024 + tid;
        int val = off[i] + sb[i >> 8];
        off[i] = val;
        wp[i] = val;
    }
}

__global__ void fill_kernel(const int* __restrict__ rows, const int* __restrict__ cols,
                            const float* __restrict__ vals,
                            int* __restrict__ wp, int2* __restrict__ cpack) {
    int i = blockIdx.x * blockDim.x + threadIdx.x;
    if (i >= NNZV) return;
    int r = rows[i];
    int p = atomicAdd(&wp[r], 1);
    cpack[p] = make_int2(cols[i], __float_as_int(vals[i]));
}

// ------- merged transpose (x0 -> x0T fp32+bf16) + weight fp32->bf16 cvt ----
__global__ void transcvt_kernel(const float* __restrict__ x,
                                float* __restrict__ xt,
                                __nv_bfloat16* __restrict__ xh,
                                const float* __restrict__ wa, __nv_bfloat16* __restrict__ oa,
                                const float* __restrict__ wb, __nv_bfloat16* __restrict__ ob) {
    __shared__ float s[32][33];
    int blk = blockIdx.x, tid = threadIdx.x;
    if (blk < 4096) {
        int n0 = (blk & 511) * 32, b0 = (blk >> 9) * 32;
        int tx = tid & 31, ty = tid >> 5;
#pragma unroll
        for (int i = 0; i < 32; i += 8)
            s[ty + i][tx] = x[(size_t)(b0 + ty + i) * NI + n0 + tx];
        __syncthreads();
#pragma unroll
        for (int i = 0; i < 32; i += 8) {
            float val = s[tx][ty + i];
            size_t idx = (size_t)(n0 + ty + i) * BB + b0 + tx;
            xt[idx] = val;
            xh[idx] = __float2bfloat16(val);
        }
    } else {
        int blk2 = blk - 4096;
        const float* src;
        __nv_bfloat16* dst;
        size_t base;
        if (blk2 < 4096) { src = wa; dst = oa; base = (size_t)blk2 * 2048; }
        else             { src = wb; dst = ob; base = (size_t)(blk2 - 4096) * 2048; }
        size_t i = base + tid * 8;
        float4 v0 = *(const float4*)(src + i);
        float4 v1 = *(const float4*)(src + i + 4);
        uint4 o;
        o.x = bf2u(__floats2bfloat162_rn(v0.x, v0.y));
        o.y = bf2u(__floats2bfloat162_rn(v0.z, v0.w));
        o.z = bf2u(__floats2bfloat162_rn(v1.x, v1.y));
        o.w = bf2u(__floats2bfloat162_rn(v1.z, v1.w));
        *(uint4*)(dst + i) = o;
    }
}

// ---------------- gather: xth[r,:] = bf16(x0T[r,:] - tc[:]*sum val*x0Th[col,:]) --
__global__ void gather_kernel(const float* __restrict__ x0T,
                              const __nv_bfloat16* __restrict__ x0Th,
                              const int* __restrict__ off,
                              const int2* __restrict__ cpack,
                              const float* __restrict__ t,
                              __nv_bfloat16* __restrict__ xth) {
    int r = blockIdx.x;
    int tid = threadIdx.x;        // 0..127
    int b2 = tid * 2;
    int s = off[r], e = off[r + 1];
    float acc0 = 0.f, acc1 = 0.f;
    int j = s;
    for (; j + 3 < e; j += 4) {
        int2 cv0 = __ldg(&cpack[j]),     cv1 = __ldg(&cpack[j + 1]);
        int2 cv2 = __ldg(&cpack[j + 2]), cv3 = __ldg(&cpack[j + 3]);
        float v0 = __int_as_float(cv0.y), v1 = __int_as_float(cv1.y);
        float v2 = __int_as_float(cv2.y), v3 = __int_as_float(cv3.y);
        float2 f0 = __bfloat1622float2(*(const __nv_bfloat162*)(x0Th + (size_t)cv0.x * BB + b2));
        float2 f1 = __bfloat1622float2(*(const __nv_bfloat162*)(x0Th + (size_t)cv1.x * BB + b2));
        float2 f2 = __bfloat1622float2(*(const __nv_bfloat162*)(x0Th + (size_t)cv2.x * BB + b2));
        float2 f3 = __bfloat1622float2(*(const __nv_bfloat162*)(x0Th + (size_t)cv3.x * BB + b2));
        acc0 += v0 * f0.x + v1 * f1.x + v2 * f2.x + v3 * f3.x;
        acc1 += v0 * f0.y + v1 * f1.y + v2 * f2.y + v3 * f3.y;
    }
    for (; j < e; j++) {
        int2 cv0 = __ldg(&cpack[j]);
        float v0 = __int_as_float(cv0.y);
        float2 f0 = __bfloat1622float2(*(const __nv_bfloat162*)(x0Th + (size_t)cv0.x * BB + b2));
        acc0 += v0 * f0.x;
        acc1 += v0 * f0.y;
    }
    float tc0 = 0.5f * t[b2];
    float tc1 = 0.5f * t[b2 + 1];
    float2 xv = *(const float2*)(x0T + (size_t)r * BB + b2);
    __nv_bfloat162 ov = __floats2bfloat162_rn(xv.x - tc0 * acc0, xv.y - tc1 * acc1);
    *(__nv_bfloat162*)(xth + (size_t)r * BB + b2) = ov;
}

// =================== bf16 GEMM1: 128x128 tile, BK=32, double-buffered =======
__global__ __launch_bounds__(256) void gemm1_bf16_kernel(
    const __nv_bfloat16* __restrict__ A,
    const __nv_bfloat16* __restrict__ W,
    float* __restrict__ part, int Kper) {
    __shared__ __nv_bfloat16 As[2][32][136];   // [k][m]
    __shared__ __nv_bfloat16 Ws[2][128][40];   // [n][k]
    int m0 = blockIdx.x * 128;
    int n0 = blockIdx.y * 128;
    int k0 = blockIdx.z * Kper, kend = k0 + Kper;
    int tid = threadIdx.x;
    int w = tid >> 5, lane = tid & 31;
    int wm = (w >> 2) * 64, wn = (w & 3) * 32;
    int g = lane >> 2, tg = lane & 3;
    int lm_k = (lane & 7) + ((lane >> 4) << 3);   // 0..15
    int lm_m = (lane & 8);                        // 0 or 8

    float acc[4][4][4];
#pragma unroll
    for (int i = 0; i < 4; i++)
#pragma unroll
        for (int j = 0; j < 4; j++)
#pragma unroll
            for (int q = 0; q < 4; q++) acc[i][j][q] = 0.f;

    uint4 ra[2], rw[2];
    int a_kk[2], a_mq[2], w_nn, w_kq;
#pragma unroll
    for (int r = 0; r < 2; r++) {
        int idx = tid + 256 * r;
        a_kk[r] = idx >> 4;
        a_mq[r] = (idx & 15) << 3;
    }
    w_nn = tid >> 1;
    w_kq = (tid & 1) << 4;

#define G1_LDG(kt) do { \
    _Pragma("unroll") \
    for (int r = 0; r < 2; r++) \
        ra[r] = *(const uint4*)(A + (size_t)((kt) + a_kk[r]) * BB + m0 + a_mq[r]); \
    rw[0] = *(const uint4*)(W + (size_t)(n0 + w_nn) * NI + (kt) + w_kq); \
    rw[1] = *(const uint4*)(W + (size_t)(n0 + w_nn) * NI + (kt) + w_kq + 8); \
} while (0)

#define G1_STS(buf) do { \
    _Pragma("unroll") \
    for (int r = 0; r < 2; r++) \
        *(uint4*)&As[buf][a_kk[r]][a_mq[r]] = ra[r]; \
    *(uint4*)&Ws[buf][w_nn][w_kq] = rw[0]; \
    *(uint4*)&Ws[buf][w_nn][w_kq + 8] = rw[1]; \
} while (0)

    G1_LDG(k0);
    G1_STS(0);
    __syncthreads();

    int buf = 0;
    for (int kt = k0; kt < kend; kt += 32) {
        bool has_next = (kt + 32 < kend);
        if (has_next) G1_LDG(kt + 32);
#pragma unroll
        for (int kc = 0; kc < 32; kc += 16) {
            uint32_t af[4][4], bfr[4][2];
#pragma unroll
            for (int mi = 0; mi < 4; mi++) {
                uint32_t sa = (uint32_t)__cvta_generic_to_shared(
                    &As[buf][kc + lm_k][wm + mi * 16 + lm_m]);
                LDMATRIX_X4_TRANS(af[mi][0], af[mi][1], af[mi][2], af[mi][3], sa);
            }
#pragma unroll
            for (int ni = 0; ni < 4; ni++) {
                int rn = wn + ni * 8 + g;
                bfr[ni][0] = *(const uint32_t*)&Ws[buf][rn][kc + 2 * tg];
                bfr[ni][1] = *(const uint32_t*)&Ws[buf][rn][kc + 8 + 2 * tg];
            }
#pragma unroll
            for (int mi = 0; mi < 4; mi++)
#pragma unroll
                for (int ni = 0; ni < 4; ni++)
                    MMA_BF16(acc[mi][ni], af[mi], bfr[ni]);
        }
        if (has_next) G1_STS(buf ^ 1);
        __syncthreads();
        buf ^= 1;
    }
#undef G1_LDG
#undef G1_STS

    float* cp = part + (size_t)blockIdx.z * ((size_t)BB * DM);
#pragma unroll
    for (int mi = 0; mi < 4; mi++) {
        int r0 = m0 + wm + mi * 16 + g;
#pragma unroll
        for (int ni = 0; ni < 4; ni++) {
            int col = n0 + wn + ni * 8 + 2 * tg;
            *(float2*)&cp[(size_t)r0 * DM + col] =
                make_float2(acc[mi][ni][0], acc[mi][ni][1]);
            *(float2*)&cp[(size_t)(r0 + 8) * DM + col] =
                make_float2(acc[mi][ni][2], acc[mi][ni][3]);
        }
    }
}

// =========== bf16 loss GEMM: h2h[BB,DM] @ Wouth[NI,DM]^T + bias, MSE ========
__global__ __launch_bounds__(256) void gemm_loss_bf16_kernel(
    const __nv_bfloat16* __restrict__ A,
    const __nv_bfloat16* __restrict__ W,
    const float* __restrict__ bout,
    const float* __restrict__ x0,
    float* __restrict__ out) {
    __shared__ __nv_bfloat16 As[2][128][40];
    __shared__ __nv_bfloat16 Ws[2][128][40];
    __shared__ float sbuf[8];
    int m0 = blockIdx.x * 128;
    int n0 = blockIdx.y * 128;
    int tid = threadIdx.x;
    int w = tid >> 5, lane = tid & 31;
    int wm = (w >> 2) * 64, wn = (w & 3) * 32;
    int g = lane >> 2, tg = lane & 3;

    float acc[4][4][4];
#pragma unroll
    for (int i = 0; i < 4; i++)
#pragma unroll
        for (int j = 0; j < 4; j++)
#pragma unroll
            for (int q = 0; q < 4; q++) acc[i][j][q] = 0.f;

    int mm = tid >> 1;
    int kq = (tid & 1) << 4;
    uint4 ra[2], rw[2];

#define GL_LDG(kt) do { \
    ra[0] = *(const uint4*)(A + (size_t)(m0 + mm) * DM + (kt) + kq); \
    ra[1] = *(const uint4*)(A + (size_t)(m0 + mm) * DM + (kt) + kq + 8); \
    rw[0] = *(const uint4*)(W + (size_t)(n0 + mm) * DM + (kt) + kq); \
    rw[1] = *(const uint4*)(W + (size_t)(n0 + mm) * DM + (kt) + kq + 8); \
} while (0)

#define GL_STS(buf) do { \
    *(uint4*)&As[buf][mm][kq] = ra[0]; \
    *(uint4*)&As[buf][mm][kq + 8] = ra[1]; \
    *(uint4*)&Ws[buf][mm][kq] = rw[0]; \
    *(uint4*)&Ws[buf][mm][kq + 8] = rw[1]; \
} while (0)

    GL_LDG(0);
    GL_STS(0);
    __syncthreads();

    int buf = 0;
    for (int kt = 0; kt < DM; kt += 32) {
        bool has_next = (kt + 32 < DM);
        if (has_next) GL_LDG(kt + 32);
#pragma unroll
        for (int kc = 0; kc < 32; kc += 16) {
            uint32_t af[4][4], bfr[4][2];
#pragma unroll
            for (int mi = 0; mi < 4; mi++) {
                int r0 = wm + mi * 16 + g;
                af[mi][0] = *(const uint32_t*)&As[buf][r0    ][kc + 2 * tg];
                af[mi][1] = *(const uint32_t*)&As[buf][r0 + 8][kc + 2 * tg];
                af[mi][2] = *(const uint32_t*)&As[buf][r0    ][kc + 8 + 2 * tg];
                af[mi][3] = *(const uint32_t*)&As[buf][r0 + 8][kc + 8 + 2 * tg];
            }
#pragma unroll
            for (int ni = 0; ni < 4; ni++) {
                int rn = wn + ni * 8 + g;
                bfr[ni][0] = *(const uint32_t*)&Ws[buf][rn][kc + 2 * tg];
                bfr[ni][1] = *(const uint32_t*)&Ws[buf][rn][kc + 8 + 2 * tg];
            }
#pragma unroll
            for (int mi = 0; mi < 4; mi++)
#pragma unroll
                for (int ni = 0; ni < 4; ni++)
                    MMA_BF16(acc[mi][ni], af[mi], bfr[ni]);
        }
        if (has_next) GL_STS(buf ^ 1);
        __syncthreads();
        buf ^= 1;
    }
#undef GL_LDG
#undef GL_STS

    float local = 0.f;
#pragma unroll
    for (int ni = 0; ni < 4; ni++) {
        int col = n0 + wn + ni * 8 + 2 * tg;
        float bo0 = bout[col], bo1 = bout[col + 1];
#pragma unroll
        for (int mi = 0; mi < 4; mi++) {
            int r0 = m0 + wm + mi * 16 + g;
            float d00 = acc[mi][ni][0] + bo0 - x0[(size_t)r0 * NI + col];
            float d01 = acc[mi][ni][1] + bo1 - x0[(size_t)r0 * NI + col + 1];
            float d10 = acc[mi][ni][2] + bo0 - x0[(size_t)(r0 + 8) * NI + col];
            float d11 = acc[mi][ni][3] + bo1 - x0[(size_t)(r0 + 8) * NI + col + 1];
            local += d00 * d00 + d01 * d01 + d10 * d10 + d11 * d11;
        }
    }
#pragma unroll
    for (int o = 16; o > 0; o >>= 1) local += __shfl_xor_sync(0xffffffffu, local, o);
    if (lane == 0) sbuf[w] = local;
    __syncthreads();
    if (tid == 0) {
        float tot = 0.f;
#pragma unroll
        for (int i = 0; i < 8; i++) tot += sbuf[i];
        atomicAdd(out, tot * (1.f / ((float)BB * (float)NI)));
    }
}

// ================= fused middle section (persistent, grid-barrier) =========
__device__ __forceinline__ void gridbar(int i) {
    __syncthreads();
    if (threadIdx.x == 0) {
        __threadfence();
        atomicAdd(&g_bar[i], 1);
        while (atomicAdd(&g_bar[i], 0) < NCTA_MID) { }
    }
    __syncthreads();
}

// 64x64 TF32 tile GEMM with 256 threads (8 warps, 2m x 4n, warp 32x16).
// act: 0 = +bias, 1 = +bias+gelu, 2 = raw store (partials)
__device__ __noinline__ void tile_gemm64(const float* __restrict__ A,
                                         const float* __restrict__ W,
                                         const float* __restrict__ bias,
                                         float* __restrict__ out,
                                         int N2, int lda, int m0, int n0,
                                         int k0, int kend, int act,
                                         float As[64][20], float Ws[64][20]) {
    int tid = threadIdx.x;
    int w = tid >> 5, lane = tid & 31;
    int wm = (w >> 2) * 32, wn = (w & 3) * 16;
    int g = lane >> 2, tg = lane & 3;
    int mm = tid >> 2, kk = (tid & 3) * 4;

    float acc[2][2][4];
#pragma unroll
    for (int i = 0; i < 2; i++)
#pragma unroll
        for (int j = 0; j < 2; j++)
#pragma unroll
            for (int q = 0; q < 4; q++) acc[i][j][q] = 0.f;

    for (int kt = k0; kt < kend; kt += 16) {
        float4 av = *(const float4*)(A + (size_t)(m0 + mm) * lda + kt + kk);
        As[mm][kk + 0] = tf32r(av.x);
        As[mm][kk + 1] = tf32r(av.y);
        As[mm][kk + 2] = tf32r(av.z);
        As[mm][kk + 3] = tf32r(av.w);
        float4 wv = *(const float4*)(W + (size_t)(n0 + mm) * lda + kt + kk);
        Ws[mm][kk + 0] = tf32r(wv.x);
        Ws[mm][kk + 1] = tf32r(wv.y);
        Ws[mm][kk + 2] = tf32r(wv.z);
        Ws[mm][kk + 3] = tf32r(wv.w);
        __syncthreads();
#pragma unroll
        for (int ks = 0; ks < 16; ks += 8) {
            uint32_t af[2][4], bf[2][2];
#pragma unroll
            for (int mi = 0; mi < 2; mi++) {
                int r0 = wm + mi * 16 + g;
                af[mi][0] = __float_as_uint(As[r0    ][ks + tg]);
                af[mi][1] = __float_as_uint(As[r0 + 8][ks + tg]);
                af[mi][2] = __float_as_uint(As[r0    ][ks + tg + 4]);
                af[mi][3] = __float_as_uint(As[r0 + 8][ks + tg + 4]);
            }
#pragma unroll
            for (int ni = 0; ni < 2; ni++) {
                int rn = wn + ni * 8 + g;
                bf[ni][0] = __float_as_uint(Ws[rn][ks + tg]);
                bf[ni][1] = __float_as_uint(Ws[rn][ks + tg + 4]);
            }
#pragma unroll
            for (int mi = 0; mi < 2; mi++)
#pragma unroll
                for (int ni = 0; ni < 2; ni++)
                    MMA_TF32(acc[mi][ni], af[mi], bf[ni]);
        }
        __syncthreads();
    }
#pragma unroll
    for (int mi = 0; mi < 2; mi++) {
        int r0 = m0 + wm + mi * 16 + g;
#pragma unroll
        for (int ni = 0; ni < 2; ni++) {
            int col = n0 + wn + ni * 8 + 2 * tg;
            float c0 = acc[mi][ni][0], c1 = acc[mi][ni][1];
            float c2 = acc[mi][ni][2], c3 = acc[mi][ni][3];
            if (act < 2) {
                float b0v = bias[col], b1v = bias[col + 1];
                c0 += b0v; c1 += b1v; c2 += b0v; c3 += b1v;
                if (act == 1) {
                    c0 = gelu_exact(c0); c1 = gelu_exact(c1);
                    c2 = gelu_exact(c2); c3 = gelu_exact(c3);
                }
            }
            *(float2*)&out[(size_t)r0 * N2 + col]       = make_float2(c0, c1);
            *(float2*)&out[(size_t)(r0 + 8) * N2 + col] = make_float2(c2, c3);
        }
    }
}

// row layernorm helper: y0/y1 are this thread's 2 elems of a 512-row
__device__ __forceinline__ void ln_row(float y0, float y1,
                                       const float* __restrict__ g,
                                       const float* __restrict__ be,
                                       size_t base, float* sbuf,
                                       float* outf, __nv_bfloat16* outh) {
    int tid = threadIdx.x;
    __syncthreads();
    float s = y0 + y1;
#pragma unroll
    for (int o = 16; o > 0; o >>= 1) s += __shfl_xor_sync(0xffffffffu, s, o);
    if ((tid & 31) == 0) sbuf[tid >> 5] = s;
    __syncthreads();
    if (tid == 0) {
        float tot = 0.f;
        for (int i = 0; i < 8; i++) tot += sbuf[i];
        sbuf[0] = tot;
    }
    __syncthreads();
    float mu = sbuf[0] * (1.f / DM);
    __syncthreads();
    float d0 = y0 - mu, d1 = y1 - mu;
    float q = d0 * d0 + d1 * d1;
#pragma unroll
    for (int o = 16; o > 0; o >>= 1) q += __shfl_xor_sync(0xffffffffu, q, o);
    if ((tid & 31) == 0) sbuf[tid >> 5] = q;
    __syncthreads();
    if (tid == 0) {
        float tot = 0.f;
        for (int i = 0; i < 8; i++) tot += sbuf[i];
        sbuf[0] = tot;
    }
    __syncthreads();
    float inv = rsqrtf(sbuf[0] * (1.f / DM) + 1e-5f);
    float o0 = d0 * inv * g[tid] + be[tid];
    float o1 = d1 * inv * g[tid + 256] + be[tid + 256];
    if (outf) {
        outf[base + tid]       = o0;
        outf[base + tid + 256] = o1;
    } else {
        outh[base + tid]       = __float2bfloat16(o0);
        outh[base + tid + 256] = __float2bfloat16(o1);
    }
}

__global__ __launch_bounds__(256) void middle_kernel(
    const float* __restrict__ t,
    const float* __restrict__ Wt1, const float* __restrict__ bt1,
    const float* __restrict__ Wt2, const float* __restrict__ bt2,
    const float* __restrict__ b_in,
    const float* __restrict__ Wv,  const float* __restrict__ bv,
    const float* __restrict__ Wo,  const float* __restrict__ bo,
    const float* __restrict__ g1,  const float* __restrict__ be1,
    const float* __restrict__ Wf1, const float* __restrict__ bf1,
    const float* __restrict__ Wf2, const float* __restrict__ bf2,
    const float* __restrict__ g2,  const float* __restrict__ be2) {
    __shared__ float As[64][20];
    __shared__ float Ws[64][20];
    __shared__ float sh_u[64];
    __shared__ float sbuf[8];
    int cta = blockIdx.x, tid = threadIdx.x;

    // ---- P0: h = reduce16(part) + b_in + time embedding ----
    {
        int base = cta * 1024;            // 1024 elems per CTA (2 batch rows)
        if (tid < 64) {
            int bb = tid >> 5, j = tid & 31;
            float z = t[cta * 2 + bb] * Wt1[j] + bt1[j];
            sh_u[tid] = z / (1.f + expf(-z));   // silu
        }
        __syncthreads();
#pragma unroll
        for (int k = 0; k < 4; k++) {
            int i = base + k * 256 + tid;
            int d = i & 511;
            int bb = (i >> 9) & 1;
            float s = 0.f;
#pragma unroll
            for (int j = 0; j < NSP1; j++) s += g_part[(size_t)j * (BB * DM) + i];
            s += b_in[d];
            float te = bt2[d];
            const float* wr = Wt2 + d * 32;
#pragma unroll
            for (int j = 0; j < 32; j++) te += sh_u[bb * 32 + j] * wr[j];
            g_h[i] = s + te;
        }
    }
    gridbar(0);

    // ---- PA: v = h @ Wv^T + bv  (32 tiles) ----
    if (cta < 32)
        tile_gemm64(g_h, Wv, bv, g_v, DM, DM,
                    (cta & 3) * 64, (cta >> 2) * 64, 0, DM, 0, As, Ws);
    gridbar(1);

    // ---- PB: at = v @ Wo^T + bo ----
    if (cta < 32)
        tile_gemm64(g_v, Wo, bo, g_at, DM, DM,
                    (cta & 3) * 64, (cta >> 2) * 64, 0, DM, 0, As, Ws);
    gridbar(2);

    // ---- PC: h1 = LN(h + at)  (2 rows per CTA) ----
#pragma unroll
    for (int e = 0; e < 2; e++) {
        int r = cta * 2 + e;
        size_t base = (size_t)r * DM;
        float y0 = g_h[base + tid] + g_at[base + tid];
        float y1 = g_h[base + tid + 256] + g_at[base + tid + 256];
        ln_row(y0, y1, g1, be1, base, sbuf, g_h1, nullptr);
    }
    gridbar(3);

    // ---- PD: f1 = gelu(h1 @ Wf1^T + bf1)  (128 tiles, 1 per CTA) ----
    tile_gemm64(g_h1, Wf1, bf1, g_f1, DFF, DM,
                (cta & 3) * 64, (cta >> 2) * 64, 0, DM, 1, As, Ws);
    gridbar(4);

    // ---- PE: f2 partials = f1 @ Wf2^T (split-4, 128 tiles, 1 per CTA) ----
    {
        int sp = cta >> 5;
        int tile = cta & 31;
        tile_gemm64(g_f1, Wf2, nullptr, g_part + (size_t)sp * (BB * DM), DM, DFF,
                    (tile & 3) * 64, (tile >> 2) * 64, sp * 512, sp * 512 + 512, 2,
                    As, Ws);
    }
    gridbar(5);

    // ---- PF: h2 = LN(h1 + reduce4(part) + bf2) -> bf16  (2 rows per CTA) ----
#pragma unroll
    for (int e = 0; e < 2; e++) {
        int r = cta * 2 + e;
        size_t base = (size_t)r * DM;
        size_t i0 = base + tid, i1 = base + tid + 256;
        float s0 = 0.f, s1 = 0.f;
#pragma unroll
        for (int j = 0; j < 4; j++) {
            s0 += __ldcg(&g_part[(size_t)j * (BB * DM) + i0]);   // stale-L1 safe
            s1 += __ldcg(&g_part[(size_t)j * (BB * DM) + i1]);
        }
        float y0 = __ldcg(&g_h1[i0]) + s0 + bf2[tid];
        float y1 = __ldcg(&g_h1[i1]) + s1 + bf2[tid + 256];
        ln_row(y0, y1, g2, be2, base, sbuf, nullptr, g_h2h);
    }

    // ---- ticket: last CTA resets barrier counters for next graph replay ----
    __syncthreads();
    if (tid == 0) {
        int old = atomicAdd(&g_bar[7], 1);
        if (old == NCTA_MID - 1) {
#pragma unroll
            for (int i = 0; i < 8; i++) atomicExch(&g_bar[i], 0);
        }
    }
}

// ---------------- launch ----------------
extern "C" void kernel_launch(void* const* d_in, const int* in_sizes, int n_in,
                              void* d_out, int out_size) {
    const float* x0    = (const float*)d_in[0];
    const float* t     = (const float*)d_in[1];
    const float* Lvals = (const float*)d_in[2];
    const float* W_in  = (const float*)d_in[3];
    const float* b_in  = (const float*)d_in[4];
    const float* W_out = (const float*)d_in[5];
    const float* b_out = (const float*)d_in[6];
    const float* W_qkv = (const float*)d_in[7];
    const float* b_qkv = (const float*)d_in[8];
    const float* W_o   = (const float*)d_in[9];
    const float* b_o   = (const float*)d_in[10];
    const float* g1    = (const float*)d_in[11];
    const float* be1   = (const float*)d_in[12];
    const float* g2    = (const float*)d_in[13];
    const float* be2   = (const float*)d_in[14];
    const float* W_f1  = (const float*)d_in[15];
    const float* b_f1  = (const float*)d_in[16];
    const float* W_f2  = (const float*)d_in[17];
    const float* b_f2  = (const float*)d_in[18];
    const float* W_t1  = (const float*)d_in[19];
    const float* b_t1  = (const float*)d_in[20];
    const float* W_t2  = (const float*)d_in[21];
    const float* b_t2  = (const float*)d_in[22];
    const int*   Lrows = (const int*)d_in[23];
    const int*   Lcols = (const int*)d_in[24];
    float* out = (float*)d_out;

    float *p_x0T, *p_part;
    __nv_bfloat16 *p_x0Th, *p_xth, *p_Winh, *p_Wouth, *p_h2h;
    int *p_cnt, *p_off, *p_wp, *p_bsum;
    int2* p_cpack;
    cudaGetSymbolAddress((void**)&p_x0T,  g_x0T);
    cudaGetSymbolAddress((void**)&p_x0Th, g_x0Th);
    cudaGetSymbolAddress((void**)&p_xth,  g_xth);
    cudaGetSymbolAddress((void**)&p_Winh, g_Winh);
    cudaGetSymbolAddress((void**)&p_Wouth,g_Wouth);
    cudaGetSymbolAddress((void**)&p_part, g_part);
    cudaGetSymbolAddress((void**)&p_h2h,  g_h2h);
    cudaGetSymbolAddress((void**)&p_cnt,  g_cnt);
    cudaGetSymbolAddress((void**)&p_off,  g_off);
    cudaGetSymbolAddress((void**)&p_wp,   g_wp);
    cudaGetSymbolAddress((void**)&p_cpack,g_cpack);
    cudaGetSymbolAddress((void**)&p_bsum, g_bsum);

    // CSR build: hist -> scan1 (self-resets cnt) -> scan23 (zeroes loss) -> fill
    hist_kernel<<<(NNZV + 255) / 256, 256>>>(Lrows, p_cnt);
    scan1_kernel<<<64, 256>>>(p_cnt, p_off, p_bsum);
    scan23_kernel<<<1, 1024>>>(p_bsum, p_off, p_wp, out);
    fill_kernel<<<(NNZV + 255) / 256, 256>>>(Lrows, Lcols, Lvals, p_wp, p_cpack);

    // transpose + weight cvt (one launch)
    transcvt_kernel<<<12288, 256>>>(x0, p_x0T, p_x0Th, W_in, p_Winh, W_out, p_Wouth);

    // xt (bf16) = x0T - tc*Lx
    gather_kernel<<<NI, 128>>>(p_x0T, p_x0Th, p_off, p_cpack, t, p_xth);

    // GEMM1 partials (bf16 tensor cores)
    gemm1_bf16_kernel<<<dim3(2, 4, NSP1), 256>>>(p_xth, p_Winh, p_part, NI / NSP1);

    // entire middle section in one persistent kernel
    middle_kernel<<<NCTA_MID, 256>>>(t, W_t1, b_t1, W_t2, b_t2, b_in,
                                     W_qkv + 2 * DM * DM, b_qkv + 2 * DM,
                                     W_o, b_o, g1, be1, W_f1, b_f1,
                                     W_f2, b_f2, g2, be2);

    // loss = mean((h2 @ W_out^T + b_out - x0)^2)
    gemm_loss_bf16_kernel<<<dim3(2, NI / 128), 256>>>(p_h2h, p_Wouth, b_out, x0, out);
}